// round 11
// baseline (speedup 1.0000x reference)
#include <cuda_runtime.h>
#include <cuda_bf16.h>
#include <math.h>

#define BSZ 16
#define TT 32
#define EDIM 768
#define HH 256
#define HH2 512
#define G3 768
#define SBN 64
#define NTOK 64
#define DEDIM 2048

// ---- scratch (device globals, no allocation) ----
__device__ float g_X0[SBN*TT*EDIM];
__device__ float g_XI[2*TT*SBN*G3];
__device__ float g_HA[SBN*TT*HH2];
__device__ float g_HB[SBN*TT*HH2];
__device__ float g_HS0[2*SBN*HH];
__device__ float g_HS1[2*SBN*HH];
__device__ float g_SP[BSZ*NTOK*NTOK];
__device__ float g_WL[BSZ*NTOK*NTOK];
__device__ float g_WR[BSZ*NTOK*NTOK];
__device__ float g_LC[BSZ*NTOK*HH2];
__device__ float g_RC[BSZ*NTOK*HH2];
__device__ float g_MTL[BSZ*NTOK];
__device__ float g_MTR[BSZ*NTOK];
__device__ float g_ATTS[4*BSZ*TT];
__device__ float g_ATTW[4*BSZ*TT];
__device__ float g_CAT[BSZ*DEDIM];
__device__ float g_HW[BSZ*DEDIM];
// split weights: tile 0 = Wn-hi, 1 = Wn-lo, 2 = Wg-hi, 3 = Wg-lo; each [512 gates][512 k] bf16
__device__ __nv_bfloat16 g_WS[4*512*512];

__device__ __forceinline__ unsigned smem_u32(const void* p){
    unsigned a;
    asm("{ .reg .u64 t; cvta.to.shared.u64 t, %1; cvt.u32.u64 %0, t; }" : "=r"(a) : "l"(p));
    return a;
}
__device__ __forceinline__ void ldsm4(unsigned* r, unsigned addr){
    asm volatile("ldmatrix.sync.aligned.m8n8.x4.shared.b16 {%0,%1,%2,%3}, [%4];"
        : "=r"(r[0]), "=r"(r[1]), "=r"(r[2]), "=r"(r[3]) : "r"(addr));
}
__device__ __forceinline__ void ldsm2(unsigned* r, unsigned addr){
    asm volatile("ldmatrix.sync.aligned.m8n8.x2.shared.b16 {%0,%1}, [%2];"
        : "=r"(r[0]), "=r"(r[1]) : "r"(addr));
}
__device__ __forceinline__ void mma_bf16(float* c, const unsigned* a, const unsigned* b){
    asm volatile("mma.sync.aligned.m16n8k16.row.col.f32.bf16.bf16.f32 "
        "{%0,%1,%2,%3}, {%4,%5,%6,%7}, {%8,%9}, {%0,%1,%2,%3};"
        : "+f"(c[0]), "+f"(c[1]), "+f"(c[2]), "+f"(c[3])
        : "r"(a[0]), "r"(a[1]), "r"(a[2]), "r"(a[3]), "r"(b[0]), "r"(b[1]));
}

// ---------------- small kernels ----------------
__global__ void k_zero(float* p, int n){
    int i = blockIdx.x*256 + threadIdx.x;
    if (i < n) p[i] = 0.f;
}

__global__ void k_gather(const float* __restrict__ f0, const float* __restrict__ f1,
                         const float* __restrict__ f2, const float* __restrict__ f3){
    int i = blockIdx.x*256 + threadIdx.x;
    const int per = (BSZ*TT*EDIM)/4;
    int f = i / per, r = i - f*per;
    const float4* src = (f==0)?(const float4*)f0:(f==1)?(const float4*)f1
                      :(f==2)?(const float4*)f2:(const float4*)f3;
    ((float4*)g_X0)[i] = src[r];
}

__global__ void k_masks(const float* __restrict__ f0, const float* __restrict__ f1,
                        const float* __restrict__ f2, const float* __restrict__ f3){
    int warp = (blockIdx.x*256 + threadIdx.x) >> 5;
    int lane = threadIdx.x & 31;
    int f = warp / (BSZ*TT), r = warp % (BSZ*TT);
    const float* src = (f==0)?f0:(f==1)?f1:(f==2)?f2:f3;
    const float* row = src + (size_t)r*EDIM;
    bool nz = false;
    for (int k = lane; k < EDIM; k += 32) nz |= (row[k] != 0.f);
    unsigned any = __ballot_sync(0xffffffffu, nz);
    if (lane == 0){
        int b = r / TT, t = r % TT;
        float v = any ? 1.f : 0.f;
        if (f < 2) g_MTL[b*NTOK + f*32 + t] = v;
        else       g_MTR[b*NTOK + (f-2)*32 + t] = v;
    }
}

__global__ void k_wsplit(const float* __restrict__ Wn, const float* __restrict__ Wg){
    int i = blockIdx.x*256 + threadIdx.x;
    if (i < 512*512){
        float wn = Wn[i], wg = Wg[i];
        __nv_bfloat16 h;
        h = __float2bfloat16(wn);
        g_WS[0*262144 + i] = h;
        g_WS[1*262144 + i] = __float2bfloat16(wn - __bfloat162float(h));
        h = __float2bfloat16(wg);
        g_WS[2*262144 + i] = h;
        g_WS[3*262144 + i] = __float2bfloat16(wg - __bfloat162float(h));
    }
}

// XI = A(2048,K) @ W(1536,K)^T + bias ; 128x64 block tile, 8x4 per thread
__global__ void __launch_bounds__(256) k_sgemm_xi(const float* __restrict__ A, int K,
        const float* __restrict__ W, const float* __restrict__ bias){
    __shared__ float As[16][136];
    __shared__ float Ws[16][72];
    int tid = threadIdx.x, tx = tid & 15, ty = tid >> 4;
    int n0 = blockIdx.x*64, m0 = blockIdx.y*128;
    float acc[8][4];
    #pragma unroll
    for (int u=0;u<8;u++){acc[u][0]=0.f;acc[u][1]=0.f;acc[u][2]=0.f;acc[u][3]=0.f;}
    for (int k0 = 0; k0 < K; k0 += 16){
        __syncthreads();
        #pragma unroll
        for (int i = 0; i < 8; i++){
            int l = tid + i*256, mm = l >> 4, kk = l & 15;
            As[kk][mm] = A[(size_t)(m0+mm)*K + k0 + kk];
        }
        #pragma unroll
        for (int i = 0; i < 4; i++){
            int l = tid + i*256, mm = l >> 4, kk = l & 15;
            Ws[kk][mm] = W[(size_t)(n0+mm)*K + k0 + kk];
        }
        __syncthreads();
        #pragma unroll
        for (int kk = 0; kk < 16; kk++){
            float4 a0 = *(const float4*)&As[kk][ty*8];
            float4 a1 = *(const float4*)&As[kk][ty*8+4];
            float4 b0 = *(const float4*)&Ws[kk][tx*4];
            float av[8] = {a0.x,a0.y,a0.z,a0.w,a1.x,a1.y,a1.z,a1.w};
            float bv[4] = {b0.x,b0.y,b0.z,b0.w};
            #pragma unroll
            for (int u=0;u<8;u++)
                #pragma unroll
                for (int v=0;v<4;v++) acc[u][v] += av[u]*bv[v];
        }
    }
    #pragma unroll
    for (int u=0;u<8;u++){
        int m = m0 + ty*8 + u, sb = m >> 5, t = m & 31;
        #pragma unroll
        for (int v=0;v<4;v++){
            int n = n0 + tx*4 + v, dir = (n >= G3) ? 1 : 0, g = n - dir*G3;
            g_XI[(size_t)((dir*TT + t)*SBN + sb)*G3 + g] = acc[u][v] + bias[n];
        }
    }
}

// one GRU time step
__global__ void __launch_bounds__(256) k_gru_step(const float* __restrict__ hprev,
        float* __restrict__ hnext, const float* __restrict__ Whh,
        const float* __restrict__ bhh, float* __restrict__ Y, int t){
    __shared__ float hs[16][260];
    int dir = blockIdx.z;
    int tt = dir ? (31 - t) : t;
    int tid = threadIdx.x, u_loc = tid & 15, bb = tid >> 4;
    int u = blockIdx.x*16 + u_loc;
    int sb0 = blockIdx.y*16, sb = sb0 + bb;
    const float* hp = hprev + dir*SBN*HH + sb0*HH;
    #pragma unroll
    for (int i = 0; i < 4; i++){
        int l4 = tid + i*256, row = l4 >> 6, c4 = l4 & 63;
        *(float4*)&hs[row][c4*4] = *(const float4*)&hp[row*HH + c4*4];
    }
    __syncthreads();
    const float4* wr4 = (const float4*)(Whh + (size_t)dir*G3*HH + (size_t)u*HH);
    const float4* wz4 = (const float4*)(Whh + (size_t)dir*G3*HH + (size_t)(HH+u)*HH);
    const float4* wn4 = (const float4*)(Whh + (size_t)dir*G3*HH + (size_t)(2*HH+u)*HH);
    const float4* h4 = (const float4*)&hs[bb][0];
    float ar=0.f, az=0.f, an=0.f;
    #pragma unroll 8
    for (int k4 = 0; k4 < 64; k4++){
        float4 h = h4[k4];
        float4 a = wr4[k4], c = wz4[k4], d = wn4[k4];
        ar += h.x*a.x + h.y*a.y + h.z*a.z + h.w*a.w;
        az += h.x*c.x + h.y*c.y + h.z*c.z + h.w*c.w;
        an += h.x*d.x + h.y*d.y + h.z*d.z + h.w*d.w;
    }
    const float* xi = g_XI + (size_t)((dir*TT + tt)*SBN + sb)*G3 + u;
    float br = bhh[dir*G3 + u], bz = bhh[dir*G3 + HH + u], bn = bhh[dir*G3 + 2*HH + u];
    float r = 1.f/(1.f + expf(-(xi[0]   + ar + br)));
    float z = 1.f/(1.f + expf(-(xi[HH]  + az + bz)));
    float n = tanhf(xi[2*HH] + r*(an + bn));
    float hv = (1.f - z)*n + z*hs[bb][u];
    hnext[dir*SBN*HH + sb*HH + u] = hv;
    Y[(size_t)(sb*TT + tt)*HH2 + dir*HH + u] = hv;
}

// ---------------- mma.sync pairwise highway scores v2 ----------------
// grid (64,16): bx = i_tile(8)*8 + j_tile(8); by = b. 256 threads = 8 warps.
// M = 64 pairs (8i x 8j); A tile (hi+lo, 64x512 bf16) built ONCE and kept in smem.
// Warp w: mw=w>>1 (16 pair-rows), nw=w&1 (32 gates per 64-gate chunk).
#define LSTR 516
#define ASTR 1040
#define LS_OFF 0
#define RS_OFF (8*LSTR*4)
#define AHI_OFF (RS_OFF + 8*LSTR*4)
#define ALO_OFF (AHI_OFF + 64*ASTR)
#define WT_OFF  (ALO_OFF + 64*ASTR)
#define BIAS_OFF (WT_OFF + 4*64*144)
#define SRED_OFF (BIAS_OFF + 192*4)
#define SMEM_SC  (SRED_OFF + 128*4)

__global__ void __launch_bounds__(256) k_scores_mma(const float* __restrict__ emb,
        const float* __restrict__ bnp, const float* __restrict__ bgp,
        const float* __restrict__ lwp){
    extern __shared__ char smc[];
    float* Ls = (float*)(smc + LS_OFF);
    float* Rs = (float*)(smc + RS_OFF);
    float* bias = (float*)(smc + BIAS_OFF);
    float* sred = (float*)(smc + SRED_OFF);
    const unsigned sbase = smem_u32(smc);
    int tid = threadIdx.x, w = tid >> 5, l = tid & 31;
    int b = blockIdx.y;
    int i0 = (blockIdx.x >> 3)*8, j0 = (blockIdx.x & 7)*8;
    int mw = w >> 1, nw = w & 1;

    for (int idx = tid; idx < 8*128; idx += 256){
        int row = idx >> 7, c4 = idx & 127;
        int itok = i0 + row, fi = itok >> 5, ti = itok & 31;
        *(float4*)&Ls[row*LSTR + c4*4] = *(const float4*)&emb[(size_t)((fi*BSZ + b)*TT + ti)*HH2 + c4*4];
        int jtok = j0 + row, fj = (jtok >> 5) + 2, tj = jtok & 31;
        *(float4*)&Rs[row*LSTR + c4*4] = *(const float4*)&emb[(size_t)((fj*BSZ + b)*TT + tj)*HH2 + c4*4];
    }
    __syncthreads();

    // build |L-R| hi/lo bf16 A-tile ONCE: thread -> pair (tid>>2), k-quarter (tid&3)*128
    {
        int pb = tid >> 2, q = tid & 3;
        const float* lr = &Ls[(pb >> 3)*LSTR + q*128];
        const float* rr = &Rs[(pb & 7)*LSTR + q*128];
        char* ahi = smc + AHI_OFF + pb*ASTR + q*256;
        char* alo = smc + ALO_OFF + pb*ASTR + q*256;
        #pragma unroll
        for (int kk = 0; kk < 128; kk += 2){
            float d0 = fabsf(lr[kk]   - rr[kk]);
            float d1 = fabsf(lr[kk+1] - rr[kk+1]);
            __nv_bfloat16 h0 = __float2bfloat16(d0), h1 = __float2bfloat16(d1);
            __nv_bfloat16 e0 = __float2bfloat16(d0 - __bfloat162float(h0));
            __nv_bfloat16 e1 = __float2bfloat16(d1 - __bfloat162float(h1));
            unsigned hp = ((unsigned)*(unsigned short*)&h0) | (((unsigned)*(unsigned short*)&h1) << 16);
            unsigned lp = ((unsigned)*(unsigned short*)&e0) | (((unsigned)*(unsigned short*)&e1) << 16);
            *(unsigned*)(ahi + kk*2) = hp;
            *(unsigned*)(alo + kk*2) = lp;
        }
    }

    float sl[2] = {0.f, 0.f};

    for (int nc = 0; nc < 8; nc++){
        float acc[8][4];
        #pragma unroll
        for (int nt=0;nt<8;nt++){acc[nt][0]=0.f;acc[nt][1]=0.f;acc[nt][2]=0.f;acc[nt][3]=0.f;}
        __syncthreads();
        if (tid < 192){
            int t3 = tid >> 6, g = tid & 63;
            const float* src = (t3==0) ? bnp : (t3==1) ? bgp : lwp;
            bias[t3*64 + g] = src[nc*64 + g];
        }
        for (int kc = 0; kc < 8; kc++){
            __syncthreads();
            // stream W tiles (4 matrices x 64 gates x 64 k, bf16)
            #pragma unroll
            for (int it = 0; it < 8; it++){
                int u = tid + it*256;
                int t4 = u >> 9, rem = u & 511, row = rem >> 3, c8 = rem & 7;
                const uint4* src = (const uint4*)&g_WS[((size_t)t4*512 + nc*64 + row)*512 + kc*64 + c8*8];
                *(uint4*)(smc + WT_OFF + t4*9216 + row*144 + c8*16) = *src;
            }
            __syncthreads();
            #pragma unroll
            for (int ks = 0; ks < 4; ks++){
                unsigned ah[4], al[4];
                unsigned arow = 16*mw + (l & 15);
                unsigned aoff = AHI_OFF + arow*ASTR + (unsigned)((kc*64 + ks*16 + (l>>4)*8)*2);
                ldsm4(ah, sbase + aoff);
                ldsm4(al, sbase + aoff + (ALO_OFF - AHI_OFF));
                #pragma unroll
                for (int nt = 0; nt < 8; nt++){
                    int thi = (nt < 4) ? 0 : 2;
                    unsigned grow = nw*32 + (nt & 3)*8 + (l & 7);
                    unsigned boff = WT_OFF + thi*9216 + grow*144 + (unsigned)((ks*16 + ((l>>3)&1)*8)*2);
                    unsigned bh[2], bl[2];
                    ldsm2(bh, sbase + boff);
                    ldsm2(bl, sbase + boff + 9216);
                    mma_bf16(acc[nt], ah, bh);
                    mma_bf16(acc[nt], al, bh);
                    mma_bf16(acc[nt], ah, bl);
                }
            }
        }
        // fused highway epilogue for this 64-gate chunk
        #pragma unroll
        for (int nt = 0; nt < 4; nt++)
        #pragma unroll
        for (int rh = 0; rh < 2; rh++)
        #pragma unroll
        for (int cc = 0; cc < 2; cc++){
            float an = acc[nt][rh*2 + cc];
            float ag = acc[nt+4][rh*2 + cc];
            int kgl = nw*32 + nt*8 + (l & 3)*2 + cc;
            int kg = nc*64 + kgl;
            int r = 16*mw + 8*rh + (l >> 2);
            float d = fabsf(Ls[(r>>3)*LSTR + kg] - Rs[(r&7)*LSTR + kg]);
            float nn = fmaxf(an + bias[kgl], 0.f);
            float gv = 1.f/(1.f + __expf(-(ag + bias[64 + kgl])));
            sl[rh] += bias[128 + kgl]*(nn*gv + (1.f - gv)*d);
        }
    }
    // reduce cols within quads, combine the two n-warps via smem
    #pragma unroll
    for (int rh = 0; rh < 2; rh++){
        float s = sl[rh];
        s += __shfl_xor_sync(0xffffffffu, s, 1);
        s += __shfl_xor_sync(0xffffffffu, s, 2);
        if ((l & 3) == 0){
            int r = 16*mw + 8*rh + (l >> 2);
            sred[r*2 + nw] = s;
        }
    }
    __syncthreads();
    if (tid < 64){
        float s = sred[tid*2] + sred[tid*2 + 1];
        int il = tid >> 3, jl = tid & 7;
        g_SP[(b*NTOK + i0 + il)*NTOK + j0 + jl] = s;
    }
}

// masked softmax; transposed=1 -> softmax over i for fixed j
__global__ void k_soft(const float* __restrict__ mask, float* __restrict__ Wout,
                       const float* __restrict__ lintb, int transposed){
    int b = blockIdx.y, r = blockIdx.x, j = threadIdx.x;  // 64 threads
    float v = lintb[0] + (transposed ? g_SP[(b*NTOK + j)*NTOK + r]
                                     : g_SP[(b*NTOK + r)*NTOK + j]);
    v += (mask[b*NTOK + j] > 0.5f) ? 0.f : -1e10f;
    __shared__ float red[2];
    float m = v;
    #pragma unroll
    for (int off = 16; off; off >>= 1) m = fmaxf(m, __shfl_xor_sync(0xffffffffu, m, off));
    if ((j & 31) == 0) red[j >> 5] = m;
    __syncthreads();
    m = fmaxf(red[0], red[1]);
    __syncthreads();
    float e = expf(v - m), s = e;
    #pragma unroll
    for (int off = 16; off; off >>= 1) s += __shfl_xor_sync(0xffffffffu, s, off);
    if ((j & 31) == 0) red[j >> 5] = s;
    __syncthreads();
    Wout[(b*NTOK + r)*NTOK + j] = e / (red[0] + red[1]);
}

__global__ void __launch_bounds__(256) k_cmp(const float* __restrict__ emb,
        const float* __restrict__ W, float* __restrict__ OUT, int rside){
    int b = blockIdx.y, r = blockIdx.x, tid = threadIdx.x;
    __shared__ float w[64];
    __shared__ float a[512];
    if (tid < 64) w[tid] = W[(b*NTOK + r)*NTOK + tid];
    int f_own = (r >> 5) + (rside ? 2 : 0), t_own = r & 31;
    for (int k = tid; k < 512; k += 256)
        a[k] = emb[(size_t)((f_own*BSZ + b)*TT + t_own)*HH2 + k];
    __syncthreads();
    int k0 = tid, k1 = tid + 256;
    float acc0 = 0.f, acc1 = 0.f;
    for (int o = 0; o < 64; o++){
        int f_o = (o >> 5) + (rside ? 0 : 2), t_o = o & 31;
        const float* row = emb + (size_t)((f_o*BSZ + b)*TT + t_o)*HH2;
        float wv = w[o];
        acc0 += wv*fabsf(a[k0] - row[k0]);
        acc1 += wv*fabsf(a[k1] - row[k1]);
    }
    OUT[(size_t)(b*NTOK + r)*HH2 + k0] = acc0;
    OUT[(size_t)(b*NTOK + r)*HH2 + k1] = acc1;
}

__global__ void k_attw(const float* __restrict__ emb, const float* __restrict__ attrL,
                       const float* __restrict__ attrR){
    int t = blockIdx.x*4 + (threadIdx.x >> 5), lane = threadIdx.x & 31;
    int sf = blockIdx.y, b = blockIdx.z;
    const float* av = (sf < 2 ? attrL + sf*HH2 : attrR + (sf-2)*HH2);
    const float* row = emb + (size_t)((sf*BSZ + b)*TT + t)*HH2;
    float s = 0.f;
    for (int k = lane; k < HH2; k += 32) s += row[k]*av[k];
    #pragma unroll
    for (int off = 16; off; off >>= 1) s += __shfl_xor_sync(0xffffffffu, s, off);
    if (lane == 0) g_ATTS[(sf*BSZ + b)*TT + t] = s;
}

__global__ void k_attsoft(){
    int sf = blockIdx.x, b = blockIdx.y, t = threadIdx.x;
    float mk = (sf < 2) ? g_MTL[b*NTOK + sf*32 + t] : g_MTR[b*NTOK + (sf-2)*32 + t];
    float v = g_ATTS[(sf*BSZ + b)*TT + t] + (mk > 0.5f ? 0.f : -1e10f);
    float m = v;
    #pragma unroll
    for (int off = 16; off; off >>= 1) m = fmaxf(m, __shfl_xor_sync(0xffffffffu, m, off));
    float e = expf(v - m), s = e;
    #pragma unroll
    for (int off = 16; off; off >>= 1) s += __shfl_xor_sync(0xffffffffu, s, off);
    g_ATTW[(sf*BSZ + b)*TT + t] = e / s;
}

__global__ void __launch_bounds__(256) k_rep(const float* __restrict__ empty_attr){
    int sf = blockIdx.x, b = blockIdx.y, tid = threadIdx.x;
    const float* MT = (sf < 2) ? g_MTL + b*NTOK + sf*32 : g_MTR + b*NTOK + (sf-2)*32;
    float am = 0.f;
    for (int t = 0; t < 32; t++) am = fmaxf(am, MT[t]);
    const float* cmp = (sf < 2) ? g_LC : g_RC;
    int tok0 = (sf & 1)*32;
    for (int k = tid; k < HH2; k += 256){
        float acc = 0.f;
        for (int t = 0; t < 32; t++)
            acc += cmp[(size_t)(b*NTOK + tok0 + t)*HH2 + k]*g_ATTW[(sf*BSZ + b)*TT + t];
        g_CAT[b*DEDIM + sf*HH2 + k] = (am > 0.5f) ? acc : empty_attr[k];
    }
}

__global__ void __launch_bounds__(256) k_hwe(const float* __restrict__ Wn,
        const float* __restrict__ bn, const float* __restrict__ Wg,
        const float* __restrict__ bg){
    int n = blockIdx.x*8 + (threadIdx.x >> 5), lane = threadIdx.x & 31;
    int b = blockIdx.y;
    const float* c = g_CAT + b*DEDIM;
    float sn = 0.f, sg = 0.f;
    for (int k = lane; k < DEDIM; k += 32){
        float cv = c[k];
        sn += Wn[(size_t)n*DEDIM + k]*cv;
        sg += Wg[(size_t)n*DEDIM + k]*cv;
    }
    #pragma unroll
    for (int off = 16; off; off >>= 1){
        sn += __shfl_xor_sync(0xffffffffu, sn, off);
        sg += __shfl_xor_sync(0xffffffffu, sg, off);
    }
    if (lane == 0){
        float nn = fmaxf(sn + bn[n], 0.f);
        float gv = 1.f/(1.f + expf(-(sg + bg[n])));
        g_HW[b*DEDIM + n] = nn*gv + (1.f - gv)*c[n];
    }
}

__global__ void __launch_bounds__(256) k_logits(const float* __restrict__ lW,
        const float* __restrict__ lb, float* __restrict__ out){
    int b = blockIdx.x, tid = threadIdx.x;
    const float* h = g_HW + b*DEDIM;
    float a0 = 0.f, a1 = 0.f;
    for (int k = tid; k < DEDIM; k += 256){
        float hv = h[k];
        a0 += hv*lW[k];
        a1 += hv*lW[DEDIM + k];
    }
    #pragma unroll
    for (int off = 16; off; off >>= 1){
        a0 += __shfl_xor_sync(0xffffffffu, a0, off);
        a1 += __shfl_xor_sync(0xffffffffu, a1, off);
    }
    __shared__ float r0[8], r1[8];
    if ((tid & 31) == 0){ r0[tid >> 5] = a0; r1[tid >> 5] = a1; }
    __syncthreads();
    if (tid == 0){
        float s0 = 0.f, s1 = 0.f;
        for (int w = 0; w < 8; w++){ s0 += r0[w]; s1 += r1[w]; }
        s0 += lb[0]; s1 += lb[1];
        float m = fmaxf(s0, s1);
        float lse = m + logf(expf(s0 - m) + expf(s1 - m));
        out[b*2 + 0] = s0 - lse;
        out[b*2 + 1] = s1 - lse;
    }
}

extern "C" void kernel_launch(void* const* d_in, const int* in_sizes, int n_in,
                              void* d_out, int out_size) {
    const float* lf0 = (const float*)d_in[0];
    const float* lf1 = (const float*)d_in[1];
    const float* rf0 = (const float*)d_in[2];
    const float* rf1 = (const float*)d_in[3];
    const float* Wih0 = (const float*)d_in[4];
    const float* Whh0 = (const float*)d_in[5];
    const float* bih0 = (const float*)d_in[6];
    const float* bhh0 = (const float*)d_in[7];
    const float* Wih12 = (const float*)d_in[8];
    const float* Whh12 = (const float*)d_in[9];
    const float* bih12 = (const float*)d_in[10];
    const float* bhh12 = (const float*)d_in[11];
    const float* hwt_Wn = (const float*)d_in[12];
    const float* hwt_bn = (const float*)d_in[13];
    const float* hwt_Wg = (const float*)d_in[14];
    const float* hwt_bg = (const float*)d_in[15];
    const float* lint_W = (const float*)d_in[16];
    const float* lint_b = (const float*)d_in[17];
    const float* attrL = (const float*)d_in[18];
    const float* attrR = (const float*)d_in[19];
    const float* empty_attr = (const float*)d_in[20];
    const float* hwe_Wn = (const float*)d_in[21];
    const float* hwe_bn = (const float*)d_in[22];
    const float* hwe_Wg = (const float*)d_in[23];
    const float* hwe_bg = (const float*)d_in[24];
    const float* line_W = (const float*)d_in[25];
    const float* line_b = (const float*)d_in[26];
    float* out = (float*)d_out;

    float *X0, *HA, *HB, *HS0, *HS1, *WL, *WR, *LC, *RC, *MTL, *MTR;
    cudaGetSymbolAddress((void**)&X0, g_X0);
    cudaGetSymbolAddress((void**)&HA, g_HA);
    cudaGetSymbolAddress((void**)&HB, g_HB);
    cudaGetSymbolAddress((void**)&HS0, g_HS0);
    cudaGetSymbolAddress((void**)&HS1, g_HS1);
    cudaGetSymbolAddress((void**)&WL, g_WL);
    cudaGetSymbolAddress((void**)&WR, g_WR);
    cudaGetSymbolAddress((void**)&LC, g_LC);
    cudaGetSymbolAddress((void**)&RC, g_RC);
    cudaGetSymbolAddress((void**)&MTL, g_MTL);
    cudaGetSymbolAddress((void**)&MTR, g_MTR);

    cudaFuncSetAttribute(k_scores_mma, cudaFuncAttributeMaxDynamicSharedMemorySize, SMEM_SC);

    k_gather<<<1536, 256>>>(lf0, lf1, rf0, rf1);
    k_masks<<<256, 256>>>(lf0, lf1, rf0, rf1);
    k_wsplit<<<1024, 256>>>(hwt_Wn, hwt_Wg);

    for (int l = 0; l < 3; l++){
        const float* A = (l == 0) ? X0 : ((l == 1) ? HA : HB);
        int K = (l == 0) ? EDIM : HH2;
        const float* Wih = (l == 0) ? Wih0 : Wih12 + (size_t)(l-1)*2*G3*HH2;
        const float* bih = (l == 0) ? bih0 : bih12 + (size_t)(l-1)*2*G3;
        const float* Whh = (l == 0) ? Whh0 : Whh12 + (size_t)(l-1)*2*G3*HH;
        const float* bhh = (l == 0) ? bhh0 : bhh12 + (size_t)(l-1)*2*G3;
        float* Y = (l == 1) ? HB : HA;
        k_sgemm_xi<<<dim3(24, 16), 256>>>(A, K, Wih, bih);
        k_zero<<<128, 256>>>(HS0, 2*SBN*HH);
        for (int t = 0; t < 32; t++){
            const float* hp = (t & 1) ? HS1 : HS0;
            float* hn = (t & 1) ? HS0 : HS1;
            k_gru_step<<<dim3(16, 4, 2), 256>>>(hp, hn, Whh, bhh, Y, t);
        }
    }

    k_scores_mma<<<dim3(64, 16), 256, SMEM_SC>>>(HA, hwt_bn, hwt_bg, lint_W);
    k_soft<<<dim3(64, 16), 64>>>(MTR, WL, lint_b, 0);
    k_soft<<<dim3(64, 16), 64>>>(MTL, WR, lint_b, 1);
    k_cmp<<<dim3(64, 16), 256>>>(HA, WL, LC, 0);
    k_cmp<<<dim3(64, 16), 256>>>(HA, WR, RC, 1);
    k_attw<<<dim3(8, 4, 16), 128>>>(HA, attrL, attrR);
    k_attsoft<<<dim3(4, 16), 32>>>();
    k_rep<<<dim3(4, 16), 256>>>(empty_attr);
    k_hwe<<<dim3(256, 16), 256>>>(hwe_Wn, hwe_bn, hwe_Wg, hwe_bg);
    k_logits<<<16, 256>>>(line_W, line_b, out);
}

// round 12
// speedup vs baseline: 1.9913x; 1.9913x over previous
#include <cuda_runtime.h>
#include <cuda_bf16.h>
#include <math.h>

#define BSZ 16
#define TT 32
#define EDIM 768
#define HH 256
#define HH2 512
#define G3 768
#define SBN 64
#define NTOK 64
#define DEDIM 2048
#define HT_DIR 16384   // 256*64

// ---- scratch (device globals, no allocation) ----
__device__ float g_X0[SBN*TT*EDIM];
__device__ float g_XI[2*TT*SBN*G3];
__device__ float g_HA[SBN*TT*HH2];
__device__ float g_HB[SBN*TT*HH2];
__device__ float g_HT0[2*HT_DIR];
__device__ float g_HT1[2*HT_DIR];
__device__ float g_WHT[3*2*HH*G3];      // [layer][dir][k=256][row=768]
__device__ float g_SP[BSZ*NTOK*NTOK];
__device__ float g_WL[BSZ*NTOK*NTOK];
__device__ float g_WR[BSZ*NTOK*NTOK];
__device__ float g_LC[BSZ*NTOK*HH2];
__device__ float g_RC[BSZ*NTOK*HH2];
__device__ float g_MTL[BSZ*NTOK];
__device__ float g_MTR[BSZ*NTOK];
__device__ float g_ATTS[4*BSZ*TT];
__device__ float g_ATTW[4*BSZ*TT];
__device__ float g_CAT[BSZ*DEDIM];
__device__ float g_HW[BSZ*DEDIM];
// split weights: tile 0 = Wn-hi, 1 = Wn-lo, 2 = Wg-hi, 3 = Wg-lo; each [512 gates][512 k] bf16
__device__ __nv_bfloat16 g_WS[4*512*512];

__device__ __forceinline__ unsigned smem_u32(const void* p){
    unsigned a;
    asm("{ .reg .u64 t; cvta.to.shared.u64 t, %1; cvt.u32.u64 %0, t; }" : "=r"(a) : "l"(p));
    return a;
}
__device__ __forceinline__ void ldsm4(unsigned* r, unsigned addr){
    asm volatile("ldmatrix.sync.aligned.m8n8.x4.shared.b16 {%0,%1,%2,%3}, [%4];"
        : "=r"(r[0]), "=r"(r[1]), "=r"(r[2]), "=r"(r[3]) : "r"(addr));
}
__device__ __forceinline__ void ldsm2(unsigned* r, unsigned addr){
    asm volatile("ldmatrix.sync.aligned.m8n8.x2.shared.b16 {%0,%1}, [%2];"
        : "=r"(r[0]), "=r"(r[1]) : "r"(addr));
}
__device__ __forceinline__ void mma_bf16(float* c, const unsigned* a, const unsigned* b){
    asm volatile("mma.sync.aligned.m16n8k16.row.col.f32.bf16.bf16.f32 "
        "{%0,%1,%2,%3}, {%4,%5,%6,%7}, {%8,%9}, {%0,%1,%2,%3};"
        : "+f"(c[0]), "+f"(c[1]), "+f"(c[2]), "+f"(c[3])
        : "r"(a[0]), "r"(a[1]), "r"(a[2]), "r"(a[3]), "r"(b[0]), "r"(b[1]));
}

// ---------------- small kernels ----------------
__global__ void k_zero(float* p, int n){
    int i = blockIdx.x*256 + threadIdx.x;
    if (i < n) p[i] = 0.f;
}

__global__ void k_gather(const float* __restrict__ f0, const float* __restrict__ f1,
                         const float* __restrict__ f2, const float* __restrict__ f3){
    int i = blockIdx.x*256 + threadIdx.x;
    const int per = (BSZ*TT*EDIM)/4;
    int f = i / per, r = i - f*per;
    const float4* src = (f==0)?(const float4*)f0:(f==1)?(const float4*)f1
                      :(f==2)?(const float4*)f2:(const float4*)f3;
    ((float4*)g_X0)[i] = src[r];
}

__global__ void k_masks(const float* __restrict__ f0, const float* __restrict__ f1,
                        const float* __restrict__ f2, const float* __restrict__ f3){
    int warp = (blockIdx.x*256 + threadIdx.x) >> 5;
    int lane = threadIdx.x & 31;
    int f = warp / (BSZ*TT), r = warp % (BSZ*TT);
    const float* src = (f==0)?f0:(f==1)?f1:(f==2)?f2:f3;
    const float* row = src + (size_t)r*EDIM;
    bool nz = false;
    for (int k = lane; k < EDIM; k += 32) nz |= (row[k] != 0.f);
    unsigned any = __ballot_sync(0xffffffffu, nz);
    if (lane == 0){
        int b = r / TT, t = r % TT;
        float v = any ? 1.f : 0.f;
        if (f < 2) g_MTL[b*NTOK + f*32 + t] = v;
        else       g_MTR[b*NTOK + (f-2)*32 + t] = v;
    }
}

__global__ void k_wsplit(const float* __restrict__ Wn, const float* __restrict__ Wg){
    int i = blockIdx.x*256 + threadIdx.x;
    if (i < 512*512){
        float wn = Wn[i], wg = Wg[i];
        __nv_bfloat16 h;
        h = __float2bfloat16(wn);
        g_WS[0*262144 + i] = h;
        g_WS[1*262144 + i] = __float2bfloat16(wn - __bfloat162float(h));
        h = __float2bfloat16(wg);
        g_WS[2*262144 + i] = h;
        g_WS[3*262144 + i] = __float2bfloat16(wg - __bfloat162float(h));
    }
}

// transpose Whh into [ld = layer*2+dir][k][row] layout
__global__ void k_wtrans(const float* __restrict__ Whh0, const float* __restrict__ Whh12){
    int idx = blockIdx.x*256 + threadIdx.x;     // over 3*2*768*256
    if (idx >= 3*2*768*256) return;
    int k = idx & 255, rest = idx >> 8;
    int row = rest % 768, ld = rest / 768;
    const float* src = (ld < 2) ? &Whh0[(size_t)ld*768*256]
                                : &Whh12[(size_t)(ld-2)*768*256];
    g_WHT[((size_t)ld*256 + k)*768 + row] = src[row*256 + k];
}

// XI = A(2048,K) @ W(1536,K)^T + bias ; 128x64 block tile, 8x4 per thread
__global__ void __launch_bounds__(256) k_sgemm_xi(const float* __restrict__ A, int K,
        const float* __restrict__ W, const float* __restrict__ bias){
    __shared__ float As[16][136];
    __shared__ float Ws[16][72];
    int tid = threadIdx.x, tx = tid & 15, ty = tid >> 4;
    int n0 = blockIdx.x*64, m0 = blockIdx.y*128;
    float acc[8][4];
    #pragma unroll
    for (int u=0;u<8;u++){acc[u][0]=0.f;acc[u][1]=0.f;acc[u][2]=0.f;acc[u][3]=0.f;}
    for (int k0 = 0; k0 < K; k0 += 16){
        __syncthreads();
        #pragma unroll
        for (int i = 0; i < 8; i++){
            int l = tid + i*256, mm = l >> 4, kk = l & 15;
            As[kk][mm] = A[(size_t)(m0+mm)*K + k0 + kk];
        }
        #pragma unroll
        for (int i = 0; i < 4; i++){
            int l = tid + i*256, mm = l >> 4, kk = l & 15;
            Ws[kk][mm] = W[(size_t)(n0+mm)*K + k0 + kk];
        }
        __syncthreads();
        #pragma unroll
        for (int kk = 0; kk < 16; kk++){
            float4 a0 = *(const float4*)&As[kk][ty*8];
            float4 a1 = *(const float4*)&As[kk][ty*8+4];
            float4 b0 = *(const float4*)&Ws[kk][tx*4];
            float av[8] = {a0.x,a0.y,a0.z,a0.w,a1.x,a1.y,a1.z,a1.w};
            float bv[4] = {b0.x,b0.y,b0.z,b0.w};
            #pragma unroll
            for (int u=0;u<8;u++)
                #pragma unroll
                for (int v=0;v<4;v++) acc[u][v] += av[u]*bv[v];
        }
    }
    #pragma unroll
    for (int u=0;u<8;u++){
        int m = m0 + ty*8 + u, sb = m >> 5, t = m & 31;
        #pragma unroll
        for (int v=0;v<4;v++){
            int n = n0 + tx*4 + v, dir = (n >= G3) ? 1 : 0, g = n - dir*G3;
            g_XI[(size_t)((dir*TT + t)*SBN + sb)*G3 + g] = acc[u][v] + bias[n];
        }
    }
}

// ---------------- GRU step v3: smem-tiled, transposed layouts ----------------
// grid (64, 1, 2): bx = unit-tile of 4 (256/4=64); bz = dir. 256 threads.
// thread: u_l = tid&3, sbg = (tid>>2)&15 (4 sb each), ks = tid>>6 (k-split of 64).
// smem: hs[256][68] (h transposed), ws[3*256][5] (w transposed), red[256][12].
#define GRU_HS_F 17408
#define GRU_WS_F 3840
#define GRU_RED_F 3072
#define SMEM_GRU ((GRU_HS_F + GRU_WS_F + GRU_RED_F)*4)

__global__ void __launch_bounds__(256) k_gru_step(const float* __restrict__ hTp,
        float* __restrict__ hTn, const float* __restrict__ WhT,
        const float* __restrict__ bhh, float* __restrict__ Y, int t){
    extern __shared__ float sm[];
    float* hs  = sm;
    float* ws  = sm + GRU_HS_F;
    float* red = sm + GRU_HS_F + GRU_WS_F;
    int dir = blockIdx.z;
    int tt = dir ? (31 - t) : t;
    int tid = threadIdx.x;
    int u_l = tid & 3, sbg = (tid >> 2) & 15, ks = tid >> 6;
    int u0 = blockIdx.x * 4;
    const float* hp = hTp + dir*HT_DIR;
    // load h^T [k][sb] coalesced
    #pragma unroll
    for (int i = 0; i < 16; i++){
        int id = tid + i*256;
        int k = id >> 4, s4 = id & 15;
        *(float4*)&hs[k*68 + s4*4] = *(const float4*)&hp[k*64 + s4*4];
    }
    // load w^T for this unit tile: 3 gates x 256 k x 4 units
    const float* wt = WhT + (size_t)dir*HH*G3;
    #pragma unroll
    for (int i = 0; i < 3; i++){
        int id = tid + i*256;          // 0..767 = (g,k)
        int g = id >> 8, k = id & 255;
        float4 v = *(const float4*)&wt[(size_t)k*G3 + g*HH + u0];
        float* d = &ws[(g*256 + k)*5];
        d[0] = v.x; d[1] = v.y; d[2] = v.z; d[3] = v.w;
    }
    __syncthreads();
    float4 ar = make_float4(0.f,0.f,0.f,0.f), az = ar, an = ar;
    int kbase = ks*64;
    #pragma unroll 8
    for (int kk = 0; kk < 64; kk++){
        int k = kbase + kk;
        float4 h4 = *(const float4*)&hs[k*68 + sbg*4];
        float wr = ws[k*5 + u_l];
        float wz = ws[(256 + k)*5 + u_l];
        float wn = ws[(512 + k)*5 + u_l];
        ar.x += wr*h4.x; ar.y += wr*h4.y; ar.z += wr*h4.z; ar.w += wr*h4.w;
        az.x += wz*h4.x; az.y += wz*h4.y; az.z += wz*h4.z; az.w += wz*h4.w;
        an.x += wn*h4.x; an.y += wn*h4.y; an.z += wn*h4.z; an.w += wn*h4.w;
    }
    // stage partials
    int pair = tid & 63;
    float* rp = &red[(ks*64 + pair)*12];
    rp[0] = ar.x; rp[1] = ar.y; rp[2]  = ar.z; rp[3]  = ar.w;
    rp[4] = az.x; rp[5] = az.y; rp[6]  = az.z; rp[7]  = az.w;
    rp[8] = an.x; rp[9] = an.y; rp[10] = an.z; rp[11] = an.w;
    __syncthreads();
    // finalize: thread handles sb = sbg*4 + ks (q = ks)
    {
        int q = ks;
        float sr = 0.f, sz = 0.f, sn = 0.f;
        #pragma unroll
        for (int kp = 0; kp < 4; kp++){
            const float* r2 = &red[(kp*64 + pair)*12];
            sr += r2[q]; sz += r2[4 + q]; sn += r2[8 + q];
        }
        int sb = sbg*4 + q;
        int u = u0 + u_l;
        const float* xi = g_XI + (size_t)((dir*TT + tt)*SBN + sb)*G3 + u;
        float br = bhh[dir*G3 + u], bz = bhh[dir*G3 + 256 + u], bn = bhh[dir*G3 + 512 + u];
        float r = 1.f/(1.f + expf(-(xi[0]   + sr + br)));
        float z = 1.f/(1.f + expf(-(xi[256] + sz + bz)));
        float n = tanhf(xi[512] + r*(sn + bn));
        float hv = (1.f - z)*n + z*hs[u*68 + sb];
        hTn[dir*HT_DIR + u*64 + sb] = hv;
        Y[(size_t)(sb*TT + tt)*HH2 + dir*HH + u] = hv;
    }
}

// ---------------- mma.sync pairwise highway scores (R11) ----------------
#define LSTR 516
#define ASTR 1040
#define LS_OFF 0
#define RS_OFF (8*LSTR*4)
#define AHI_OFF (RS_OFF + 8*LSTR*4)
#define ALO_OFF (AHI_OFF + 64*ASTR)
#define WT_OFF  (ALO_OFF + 64*ASTR)
#define BIAS_OFF (WT_OFF + 4*64*144)
#define SRED_OFF (BIAS_OFF + 192*4)
#define SMEM_SC  (SRED_OFF + 128*4)

__global__ void __launch_bounds__(256) k_scores_mma(const float* __restrict__ emb,
        const float* __restrict__ bnp, const float* __restrict__ bgp,
        const float* __restrict__ lwp){
    extern __shared__ char smc[];
    float* Ls = (float*)(smc + LS_OFF);
    float* Rs = (float*)(smc + RS_OFF);
    float* bias = (float*)(smc + BIAS_OFF);
    float* sred = (float*)(smc + SRED_OFF);
    const unsigned sbase = smem_u32(smc);
    int tid = threadIdx.x, w = tid >> 5, l = tid & 31;
    int b = blockIdx.y;
    int i0 = (blockIdx.x >> 3)*8, j0 = (blockIdx.x & 7)*8;
    int mw = w >> 1, nw = w & 1;

    for (int idx = tid; idx < 8*128; idx += 256){
        int row = idx >> 7, c4 = idx & 127;
        int itok = i0 + row, fi = itok >> 5, ti = itok & 31;
        *(float4*)&Ls[row*LSTR + c4*4] = *(const float4*)&emb[(size_t)((fi*BSZ + b)*TT + ti)*HH2 + c4*4];
        int jtok = j0 + row, fj = (jtok >> 5) + 2, tj = jtok & 31;
        *(float4*)&Rs[row*LSTR + c4*4] = *(const float4*)&emb[(size_t)((fj*BSZ + b)*TT + tj)*HH2 + c4*4];
    }
    __syncthreads();

    {
        int pb = tid >> 2, q = tid & 3;
        const float* lr = &Ls[(pb >> 3)*LSTR + q*128];
        const float* rr = &Rs[(pb & 7)*LSTR + q*128];
        char* ahi = smc + AHI_OFF + pb*ASTR + q*256;
        char* alo = smc + ALO_OFF + pb*ASTR + q*256;
        #pragma unroll
        for (int kk = 0; kk < 128; kk += 2){
            float d0 = fabsf(lr[kk]   - rr[kk]);
            float d1 = fabsf(lr[kk+1] - rr[kk+1]);
            __nv_bfloat16 h0 = __float2bfloat16(d0), h1 = __float2bfloat16(d1);
            __nv_bfloat16 e0 = __float2bfloat16(d0 - __bfloat162float(h0));
            __nv_bfloat16 e1 = __float2bfloat16(d1 - __bfloat162float(h1));
            unsigned hp = ((unsigned)*(unsigned short*)&h0) | (((unsigned)*(unsigned short*)&h1) << 16);
            unsigned lp = ((unsigned)*(unsigned short*)&e0) | (((unsigned)*(unsigned short*)&e1) << 16);
            *(unsigned*)(ahi + kk*2) = hp;
            *(unsigned*)(alo + kk*2) = lp;
        }
    }

    float sl[2] = {0.f, 0.f};

    for (int nc = 0; nc < 8; nc++){
        float acc[8][4];
        #pragma unroll
        for (int nt=0;nt<8;nt++){acc[nt][0]=0.f;acc[nt][1]=0.f;acc[nt][2]=0.f;acc[nt][3]=0.f;}
        __syncthreads();
        if (tid < 192){
            int t3 = tid >> 6, g = tid & 63;
            const float* src = (t3==0) ? bnp : (t3==1) ? bgp : lwp;
            bias[t3*64 + g] = src[nc*64 + g];
        }
        for (int kc = 0; kc < 8; kc++){
            __syncthreads();
            #pragma unroll
            for (int it = 0; it < 8; it++){
                int u = tid + it*256;
                int t4 = u >> 9, rem = u & 511, row = rem >> 3, c8 = rem & 7;
                const uint4* src = (const uint4*)&g_WS[((size_t)t4*512 + nc*64 + row)*512 + kc*64 + c8*8];
                *(uint4*)(smc + WT_OFF + t4*9216 + row*144 + c8*16) = *src;
            }
            __syncthreads();
            #pragma unroll
            for (int ks = 0; ks < 4; ks++){
                unsigned ah[4], al[4];
                unsigned arow = 16*mw + (l & 15);
                unsigned aoff = AHI_OFF + arow*ASTR + (unsigned)((kc*64 + ks*16 + (l>>4)*8)*2);
                ldsm4(ah, sbase + aoff);
                ldsm4(al, sbase + aoff + (ALO_OFF - AHI_OFF));
                #pragma unroll
                for (int nt = 0; nt < 8; nt++){
                    int thi = (nt < 4) ? 0 : 2;
                    unsigned grow = nw*32 + (nt & 3)*8 + (l & 7);
                    unsigned boff = WT_OFF + thi*9216 + grow*144 + (unsigned)((ks*16 + ((l>>3)&1)*8)*2);
                    unsigned bh[2], bl[2];
                    ldsm2(bh, sbase + boff);
                    ldsm2(bl, sbase + boff + 9216);
                    mma_bf16(acc[nt], ah, bh);
                    mma_bf16(acc[nt], al, bh);
                    mma_bf16(acc[nt], ah, bl);
                }
            }
        }
        #pragma unroll
        for (int nt = 0; nt < 4; nt++)
        #pragma unroll
        for (int rh = 0; rh < 2; rh++)
        #pragma unroll
        for (int cc = 0; cc < 2; cc++){
            float an = acc[nt][rh*2 + cc];
            float ag = acc[nt+4][rh*2 + cc];
            int kgl = nw*32 + nt*8 + (l & 3)*2 + cc;
            int kg = nc*64 + kgl;
            int r = 16*mw + 8*rh + (l >> 2);
            float d = fabsf(Ls[(r>>3)*LSTR + kg] - Rs[(r&7)*LSTR + kg]);
            float nn = fmaxf(an + bias[kgl], 0.f);
            float gv = 1.f/(1.f + __expf(-(ag + bias[64 + kgl])));
            sl[rh] += bias[128 + kgl]*(nn*gv + (1.f - gv)*d);
        }
    }
    #pragma unroll
    for (int rh = 0; rh < 2; rh++){
        float s = sl[rh];
        s += __shfl_xor_sync(0xffffffffu, s, 1);
        s += __shfl_xor_sync(0xffffffffu, s, 2);
        if ((l & 3) == 0){
            int r = 16*mw + 8*rh + (l >> 2);
            sred[r*2 + nw] = s;
        }
    }
    __syncthreads();
    if (tid < 64){
        float s = sred[tid*2] + sred[tid*2 + 1];
        int il = tid >> 3, jl = tid & 7;
        g_SP[(b*NTOK + i0 + il)*NTOK + j0 + jl] = s;
    }
}

// masked softmax; transposed=1 -> softmax over i for fixed j
__global__ void k_soft(const float* __restrict__ mask, float* __restrict__ Wout,
                       const float* __restrict__ lintb, int transposed){
    int b = blockIdx.y, r = blockIdx.x, j = threadIdx.x;
    float v = lintb[0] + (transposed ? g_SP[(b*NTOK + j)*NTOK + r]
                                     : g_SP[(b*NTOK + r)*NTOK + j]);
    v += (mask[b*NTOK + j] > 0.5f) ? 0.f : -1e10f;
    __shared__ float red[2];
    float m = v;
    #pragma unroll
    for (int off = 16; off; off >>= 1) m = fmaxf(m, __shfl_xor_sync(0xffffffffu, m, off));
    if ((j & 31) == 0) red[j >> 5] = m;
    __syncthreads();
    m = fmaxf(red[0], red[1]);
    __syncthreads();
    float e = expf(v - m), s = e;
    #pragma unroll
    for (int off = 16; off; off >>= 1) s += __shfl_xor_sync(0xffffffffu, s, off);
    if ((j & 31) == 0) red[j >> 5] = s;
    __syncthreads();
    Wout[(b*NTOK + r)*NTOK + j] = e / (red[0] + red[1]);
}

__global__ void __launch_bounds__(256) k_cmp(const float* __restrict__ emb,
        const float* __restrict__ W, float* __restrict__ OUT, int rside){
    int b = blockIdx.y, r = blockIdx.x, tid = threadIdx.x;
    __shared__ float w[64];
    __shared__ float a[512];
    if (tid < 64) w[tid] = W[(b*NTOK + r)*NTOK + tid];
    int f_own = (r >> 5) + (rside ? 2 : 0), t_own = r & 31;
    for (int k = tid; k < 512; k += 256)
        a[k] = emb[(size_t)((f_own*BSZ + b)*TT + t_own)*HH2 + k];
    __syncthreads();
    int k0 = tid, k1 = tid + 256;
    float acc0 = 0.f, acc1 = 0.f;
    for (int o = 0; o < 64; o++){
        int f_o = (o >> 5) + (rside ? 0 : 2), t_o = o & 31;
        const float* row = emb + (size_t)((f_o*BSZ + b)*TT + t_o)*HH2;
        float wv = w[o];
        acc0 += wv*fabsf(a[k0] - row[k0]);
        acc1 += wv*fabsf(a[k1] - row[k1]);
    }
    OUT[(size_t)(b*NTOK + r)*HH2 + k0] = acc0;
    OUT[(size_t)(b*NTOK + r)*HH2 + k1] = acc1;
}

__global__ void k_attw(const float* __restrict__ emb, const float* __restrict__ attrL,
                       const float* __restrict__ attrR){
    int t = blockIdx.x*4 + (threadIdx.x >> 5), lane = threadIdx.x & 31;
    int sf = blockIdx.y, b = blockIdx.z;
    const float* av = (sf < 2 ? attrL + sf*HH2 : attrR + (sf-2)*HH2);
    const float* row = emb + (size_t)((sf*BSZ + b)*TT + t)*HH2;
    float s = 0.f;
    for (int k = lane; k < HH2; k += 32) s += row[k]*av[k];
    #pragma unroll
    for (int off = 16; off; off >>= 1) s += __shfl_xor_sync(0xffffffffu, s, off);
    if (lane == 0) g_ATTS[(sf*BSZ + b)*TT + t] = s;
}

__global__ void k_attsoft(){
    int sf = blockIdx.x, b = blockIdx.y, t = threadIdx.x;
    float mk = (sf < 2) ? g_MTL[b*NTOK + sf*32 + t] : g_MTR[b*NTOK + (sf-2)*32 + t];
    float v = g_ATTS[(sf*BSZ + b)*TT + t] + (mk > 0.5f ? 0.f : -1e10f);
    float m = v;
    #pragma unroll
    for (int off = 16; off; off >>= 1) m = fmaxf(m, __shfl_xor_sync(0xffffffffu, m, off));
    float e = expf(v - m), s = e;
    #pragma unroll
    for (int off = 16; off; off >>= 1) s += __shfl_xor_sync(0xffffffffu, s, off);
    g_ATTW[(sf*BSZ + b)*TT + t] = e / s;
}

__global__ void __launch_bounds__(256) k_rep(const float* __restrict__ empty_attr){
    int sf = blockIdx.x, b = blockIdx.y, tid = threadIdx.x;
    const float* MT = (sf < 2) ? g_MTL + b*NTOK + sf*32 : g_MTR + b*NTOK + (sf-2)*32;
    float am = 0.f;
    for (int t = 0; t < 32; t++) am = fmaxf(am, MT[t]);
    const float* cmp = (sf < 2) ? g_LC : g_RC;
    int tok0 = (sf & 1)*32;
    for (int k = tid; k < HH2; k += 256){
        float acc = 0.f;
        for (int t = 0; t < 32; t++)
            acc += cmp[(size_t)(b*NTOK + tok0 + t)*HH2 + k]*g_ATTW[(sf*BSZ + b)*TT + t];
        g_CAT[b*DEDIM + sf*HH2 + k] = (am > 0.5f) ? acc : empty_attr[k];
    }
}

__global__ void __launch_bounds__(256) k_hwe(const float* __restrict__ Wn,
        const float* __restrict__ bn, const float* __restrict__ Wg,
        const float* __restrict__ bg){
    int n = blockIdx.x*8 + (threadIdx.x >> 5), lane = threadIdx.x & 31;
    int b = blockIdx.y;
    const float* c = g_CAT + b*DEDIM;
    float sn = 0.f, sg = 0.f;
    for (int k = lane; k < DEDIM; k += 32){
        float cv = c[k];
        sn += Wn[(size_t)n*DEDIM + k]*cv;
        sg += Wg[(size_t)n*DEDIM + k]*cv;
    }
    #pragma unroll
    for (int off = 16; off; off >>= 1){
        sn += __shfl_xor_sync(0xffffffffu, sn, off);
        sg += __shfl_xor_sync(0xffffffffu, sg, off);
    }
    if (lane == 0){
        float nn = fmaxf(sn + bn[n], 0.f);
        float gv = 1.f/(1.f + expf(-(sg + bg[n])));
        g_HW[b*DEDIM + n] = nn*gv + (1.f - gv)*c[n];
    }
}

__global__ void __launch_bounds__(256) k_logits(const float* __restrict__ lW,
        const float* __restrict__ lb, float* __restrict__ out){
    int b = blockIdx.x, tid = threadIdx.x;
    const float* h = g_HW + b*DEDIM;
    float a0 = 0.f, a1 = 0.f;
    for (int k = tid; k < DEDIM; k += 256){
        float hv = h[k];
        a0 += hv*lW[k];
        a1 += hv*lW[DEDIM + k];
    }
    #pragma unroll
    for (int off = 16; off; off >>= 1){
        a0 += __shfl_xor_sync(0xffffffffu, a0, off);
        a1 += __shfl_xor_sync(0xffffffffu, a1, off);
    }
    __shared__ float r0[8], r1[8];
    if ((tid & 31) == 0){ r0[tid >> 5] = a0; r1[tid >> 5] = a1; }
    __syncthreads();
    if (tid == 0){
        float s0 = 0.f, s1 = 0.f;
        for (int w = 0; w < 8; w++){ s0 += r0[w]; s1 += r1[w]; }
        s0 += lb[0]; s1 += lb[1];
        float m = fmaxf(s0, s1);
        float lse = m + logf(expf(s0 - m) + expf(s1 - m));
        out[b*2 + 0] = s0 - lse;
        out[b*2 + 1] = s1 - lse;
    }
}

extern "C" void kernel_launch(void* const* d_in, const int* in_sizes, int n_in,
                              void* d_out, int out_size) {
    const float* lf0 = (const float*)d_in[0];
    const float* lf1 = (const float*)d_in[1];
    const float* rf0 = (const float*)d_in[2];
    const float* rf1 = (const float*)d_in[3];
    const float* Wih0 = (const float*)d_in[4];
    const float* Whh0 = (const float*)d_in[5];
    const float* bih0 = (const float*)d_in[6];
    const float* bhh0 = (const float*)d_in[7];
    const float* Wih12 = (const float*)d_in[8];
    const float* Whh12 = (const float*)d_in[9];
    const float* bih12 = (const float*)d_in[10];
    const float* bhh12 = (const float*)d_in[11];
    const float* hwt_Wn = (const float*)d_in[12];
    const float* hwt_bn = (const float*)d_in[13];
    const float* hwt_Wg = (const float*)d_in[14];
    const float* hwt_bg = (const float*)d_in[15];
    const float* lint_W = (const float*)d_in[16];
    const float* lint_b = (const float*)d_in[17];
    const float* attrL = (const float*)d_in[18];
    const float* attrR = (const float*)d_in[19];
    const float* empty_attr = (const float*)d_in[20];
    const float* hwe_Wn = (const float*)d_in[21];
    const float* hwe_bn = (const float*)d_in[22];
    const float* hwe_Wg = (const float*)d_in[23];
    const float* hwe_bg = (const float*)d_in[24];
    const float* line_W = (const float*)d_in[25];
    const float* line_b = (const float*)d_in[26];
    float* out = (float*)d_out;

    float *X0, *HA, *HB, *HT0, *HT1, *WHT, *WL, *WR, *LC, *RC, *MTL, *MTR;
    cudaGetSymbolAddress((void**)&X0, g_X0);
    cudaGetSymbolAddress((void**)&HA, g_HA);
    cudaGetSymbolAddress((void**)&HB, g_HB);
    cudaGetSymbolAddress((void**)&HT0, g_HT0);
    cudaGetSymbolAddress((void**)&HT1, g_HT1);
    cudaGetSymbolAddress((void**)&WHT, g_WHT);
    cudaGetSymbolAddress((void**)&WL, g_WL);
    cudaGetSymbolAddress((void**)&WR, g_WR);
    cudaGetSymbolAddress((void**)&LC, g_LC);
    cudaGetSymbolAddress((void**)&RC, g_RC);
    cudaGetSymbolAddress((void**)&MTL, g_MTL);
    cudaGetSymbolAddress((void**)&MTR, g_MTR);

    cudaFuncSetAttribute(k_scores_mma, cudaFuncAttributeMaxDynamicSharedMemorySize, SMEM_SC);
    cudaFuncSetAttribute(k_gru_step, cudaFuncAttributeMaxDynamicSharedMemorySize, SMEM_GRU);

    k_gather<<<1536, 256>>>(lf0, lf1, rf0, rf1);
    k_masks<<<256, 256>>>(lf0, lf1, rf0, rf1);
    k_wsplit<<<1024, 256>>>(hwt_Wn, hwt_Wg);
    k_wtrans<<<4608, 256>>>(Whh0, Whh12);

    for (int l = 0; l < 3; l++){
        const float* A = (l == 0) ? X0 : ((l == 1) ? HA : HB);
        int K = (l == 0) ? EDIM : HH2;
        const float* Wih = (l == 0) ? Wih0 : Wih12 + (size_t)(l-1)*2*G3*HH2;
        const float* bih = (l == 0) ? bih0 : bih12 + (size_t)(l-1)*2*G3;
        const float* bhh = (l == 0) ? bhh0 : bhh12 + (size_t)(l-1)*2*G3;
        const float* WhT = WHT + (size_t)l*2*HH*G3;
        float* Y = (l == 1) ? HB : HA;
        k_sgemm_xi<<<dim3(24, 16), 256>>>(A, K, Wih, bih);
        k_zero<<<128, 256>>>(HT0, 2*HT_DIR);
        for (int t = 0; t < 32; t++){
            const float* hp = (t & 1) ? HT1 : HT0;
            float* hn = (t & 1) ? HT0 : HT1;
            k_gru_step<<<dim3(64, 1, 2), 256, SMEM_GRU>>>(hp, hn, WhT, bhh, Y, t);
        }
    }

    k_scores_mma<<<dim3(64, 16), 256, SMEM_SC>>>(HA, hwt_bn, hwt_bg, lint_W);
    k_soft<<<dim3(64, 16), 64>>>(MTR, WL, lint_b, 0);
    k_soft<<<dim3(64, 16), 64>>>(MTL, WR, lint_b, 1);
    k_cmp<<<dim3(64, 16), 256>>>(HA, WL, LC, 0);
    k_cmp<<<dim3(64, 16), 256>>>(HA, WR, RC, 1);
    k_attw<<<dim3(8, 4, 16), 128>>>(HA, attrL, attrR);
    k_attsoft<<<dim3(4, 16), 32>>>();
    k_rep<<<dim3(4, 16), 256>>>(empty_attr);
    k_hwe<<<dim3(256, 16), 256>>>(hwe_Wn, hwe_bn, hwe_Wg, hwe_bg);
    k_logits<<<16, 256>>>(line_W, line_b, out);
}

// round 13
// speedup vs baseline: 2.0900x; 1.0496x over previous
#include <cuda_runtime.h>
#include <cuda_bf16.h>
#include <math.h>

#define BSZ 16
#define TT 32
#define EDIM 768
#define HH 256
#define HH2 512
#define G3 768
#define SBN 64
#define NTOK 64
#define DEDIM 2048
#define HT_DIR 16384   // 256*64

// ---- scratch (device globals, no allocation) ----
__device__ float g_X0[SBN*TT*EDIM];
__device__ float g_XI[2*TT*SBN*G3];
__device__ float g_HA[SBN*TT*HH2];
__device__ float g_HB[SBN*TT*HH2];
__device__ float g_HT0[2*HT_DIR];
__device__ float g_HT1[2*HT_DIR];
__device__ float g_WHT[3*2*HH*G3];      // [layer][dir][k=256][row=768]
__device__ unsigned g_bar[2];
__device__ float g_SP[BSZ*NTOK*NTOK];
__device__ float g_WL[BSZ*NTOK*NTOK];
__device__ float g_WR[BSZ*NTOK*NTOK];
__device__ float g_LC[BSZ*NTOK*HH2];
__device__ float g_RC[BSZ*NTOK*HH2];
__device__ float g_MTL[BSZ*NTOK];
__device__ float g_MTR[BSZ*NTOK];
__device__ float g_ATTS[4*BSZ*TT];
__device__ float g_ATTW[4*BSZ*TT];
__device__ float g_CAT[BSZ*DEDIM];
__device__ float g_HW[BSZ*DEDIM];
// split weights: tile 0 = Wn-hi, 1 = Wn-lo, 2 = Wg-hi, 3 = Wg-lo; each [512 gates][512 k] bf16
__device__ __nv_bfloat16 g_WS[4*512*512];

__device__ __forceinline__ unsigned smem_u32(const void* p){
    unsigned a;
    asm("{ .reg .u64 t; cvta.to.shared.u64 t, %1; cvt.u32.u64 %0, t; }" : "=r"(a) : "l"(p));
    return a;
}
__device__ __forceinline__ void ldsm4(unsigned* r, unsigned addr){
    asm volatile("ldmatrix.sync.aligned.m8n8.x4.shared.b16 {%0,%1,%2,%3}, [%4];"
        : "=r"(r[0]), "=r"(r[1]), "=r"(r[2]), "=r"(r[3]) : "r"(addr));
}
__device__ __forceinline__ void ldsm2(unsigned* r, unsigned addr){
    asm volatile("ldmatrix.sync.aligned.m8n8.x2.shared.b16 {%0,%1}, [%2];"
        : "=r"(r[0]), "=r"(r[1]) : "r"(addr));
}
__device__ __forceinline__ void mma_bf16(float* c, const unsigned* a, const unsigned* b){
    asm volatile("mma.sync.aligned.m16n8k16.row.col.f32.bf16.bf16.f32 "
        "{%0,%1,%2,%3}, {%4,%5,%6,%7}, {%8,%9}, {%0,%1,%2,%3};"
        : "+f"(c[0]), "+f"(c[1]), "+f"(c[2]), "+f"(c[3])
        : "r"(a[0]), "r"(a[1]), "r"(a[2]), "r"(a[3]), "r"(b[0]), "r"(b[1]));
}

// ---------------- small kernels ----------------
__global__ void k_zero(float* p, int n){
    int i = blockIdx.x*256 + threadIdx.x;
    if (i < n) p[i] = 0.f;
}

// zero hidden ping buffer + barrier counters (before each persistent GRU layer)
__global__ void k_prep(){
    int i = blockIdx.x*256 + threadIdx.x;
    if (i < 2*HT_DIR) g_HT0[i] = 0.f;
    if (i < 2) g_bar[i] = 0u;
}

__global__ void k_gather(const float* __restrict__ f0, const float* __restrict__ f1,
                         const float* __restrict__ f2, const float* __restrict__ f3){
    int i = blockIdx.x*256 + threadIdx.x;
    const int per = (BSZ*TT*EDIM)/4;
    int f = i / per, r = i - f*per;
    const float4* src = (f==0)?(const float4*)f0:(f==1)?(const float4*)f1
                      :(f==2)?(const float4*)f2:(const float4*)f3;
    ((float4*)g_X0)[i] = src[r];
}

__global__ void k_masks(const float* __restrict__ f0, const float* __restrict__ f1,
                        const float* __restrict__ f2, const float* __restrict__ f3){
    int warp = (blockIdx.x*256 + threadIdx.x) >> 5;
    int lane = threadIdx.x & 31;
    int f = warp / (BSZ*TT), r = warp % (BSZ*TT);
    const float* src = (f==0)?f0:(f==1)?f1:(f==2)?f2:f3;
    const float* row = src + (size_t)r*EDIM;
    bool nz = false;
    for (int k = lane; k < EDIM; k += 32) nz |= (row[k] != 0.f);
    unsigned any = __ballot_sync(0xffffffffu, nz);
    if (lane == 0){
        int b = r / TT, t = r % TT;
        float v = any ? 1.f : 0.f;
        if (f < 2) g_MTL[b*NTOK + f*32 + t] = v;
        else       g_MTR[b*NTOK + (f-2)*32 + t] = v;
    }
}

__global__ void k_wsplit(const float* __restrict__ Wn, const float* __restrict__ Wg){
    int i = blockIdx.x*256 + threadIdx.x;
    if (i < 512*512){
        float wn = Wn[i], wg = Wg[i];
        __nv_bfloat16 h;
        h = __float2bfloat16(wn);
        g_WS[0*262144 + i] = h;
        g_WS[1*262144 + i] = __float2bfloat16(wn - __bfloat162float(h));
        h = __float2bfloat16(wg);
        g_WS[2*262144 + i] = h;
        g_WS[3*262144 + i] = __float2bfloat16(wg - __bfloat162float(h));
    }
}

// transpose Whh into [ld = layer*2+dir][k][row] layout
__global__ void k_wtrans(const float* __restrict__ Whh0, const float* __restrict__ Whh12){
    int idx = blockIdx.x*256 + threadIdx.x;     // over 3*2*768*256
    if (idx >= 3*2*768*256) return;
    int k = idx & 255, rest = idx >> 8;
    int row = rest % 768, ld = rest / 768;
    const float* src = (ld < 2) ? &Whh0[(size_t)ld*768*256]
                                : &Whh12[(size_t)(ld-2)*768*256];
    g_WHT[((size_t)ld*256 + k)*768 + row] = src[row*256 + k];
}

// XI = A(2048,K) @ W(1536,K)^T + bias ; 128x64 block tile, 8x4 per thread
__global__ void __launch_bounds__(256) k_sgemm_xi(const float* __restrict__ A, int K,
        const float* __restrict__ W, const float* __restrict__ bias){
    __shared__ float As[16][136];
    __shared__ float Ws[16][72];
    int tid = threadIdx.x, tx = tid & 15, ty = tid >> 4;
    int n0 = blockIdx.x*64, m0 = blockIdx.y*128;
    float acc[8][4];
    #pragma unroll
    for (int u=0;u<8;u++){acc[u][0]=0.f;acc[u][1]=0.f;acc[u][2]=0.f;acc[u][3]=0.f;}
    for (int k0 = 0; k0 < K; k0 += 16){
        __syncthreads();
        #pragma unroll
        for (int i = 0; i < 8; i++){
            int l = tid + i*256, mm = l >> 4, kk = l & 15;
            As[kk][mm] = A[(size_t)(m0+mm)*K + k0 + kk];
        }
        #pragma unroll
        for (int i = 0; i < 4; i++){
            int l = tid + i*256, mm = l >> 4, kk = l & 15;
            Ws[kk][mm] = W[(size_t)(n0+mm)*K + k0 + kk];
        }
        __syncthreads();
        #pragma unroll
        for (int kk = 0; kk < 16; kk++){
            float4 a0 = *(const float4*)&As[kk][ty*8];
            float4 a1 = *(const float4*)&As[kk][ty*8+4];
            float4 b0 = *(const float4*)&Ws[kk][tx*4];
            float av[8] = {a0.x,a0.y,a0.z,a0.w,a1.x,a1.y,a1.z,a1.w};
            float bv[4] = {b0.x,b0.y,b0.z,b0.w};
            #pragma unroll
            for (int u=0;u<8;u++)
                #pragma unroll
                for (int v=0;v<4;v++) acc[u][v] += av[u]*bv[v];
        }
    }
    #pragma unroll
    for (int u=0;u<8;u++){
        int m = m0 + ty*8 + u, sb = m >> 5, t = m & 31;
        #pragma unroll
        for (int v=0;v<4;v++){
            int n = n0 + tx*4 + v, dir = (n >= G3) ? 1 : 0, g = n - dir*G3;
            g_XI[(size_t)((dir*TT + t)*SBN + sb)*G3 + g] = acc[u][v] + bias[n];
        }
    }
}

// ---------------- persistent GRU layer: all 32 steps in one launch ----------------
// grid (64, 1, 2): bx = unit-tile of 4; bz = dir. 256 threads. 1 block/SM, 128 blocks
// co-resident -> software inter-block barrier between time steps is safe.
#define GRU_HS_F 17408
#define GRU_WS_F 3840
#define GRU_RED_F 3072
#define SMEM_GRU ((GRU_HS_F + GRU_WS_F + GRU_RED_F)*4)

__global__ void __launch_bounds__(256) k_gru_seq(const float* __restrict__ WhT,
        const float* __restrict__ bhh, float* __restrict__ Y){
    extern __shared__ float sm[];
    float* hs  = sm;
    float* ws  = sm + GRU_HS_F;
    float* red = sm + GRU_HS_F + GRU_WS_F;
    int dir = blockIdx.z;
    int tid = threadIdx.x;
    int u_l = tid & 3, sbg = (tid >> 2) & 15, ks = tid >> 6;
    int u0 = blockIdx.x * 4;
    // load w^T once: 3 gates x 256 k x 4 units
    const float* wt = WhT + (size_t)dir*HH*G3;
    #pragma unroll
    for (int i = 0; i < 3; i++){
        int id = tid + i*256;
        int g = id >> 8, k = id & 255;
        float4 v = *(const float4*)&wt[(size_t)k*G3 + g*HH + u0];
        float* d = &ws[(g*256 + k)*5];
        d[0] = v.x; d[1] = v.y; d[2] = v.z; d[3] = v.w;
    }
    int u = u0 + u_l;
    int sb = sbg*4 + ks;
    float br = bhh[dir*G3 + u], bz = bhh[dir*G3 + 256 + u], bn = bhh[dir*G3 + 512 + u];
    int kbase = ks*64;
    int pair = tid & 63;

    for (int t = 0; t < 32; t++){
        int tt = dir ? (31 - t) : t;
        const float* hp = ((t & 1) ? g_HT1 : g_HT0) + dir*HT_DIR;
        float* hn = ((t & 1) ? g_HT0 : g_HT1) + dir*HT_DIR;
        __syncthreads();
        // load h^T [k][sb] (L2-coherent: other blocks wrote it last step)
        #pragma unroll
        for (int i = 0; i < 16; i++){
            int id = tid + i*256;
            int k = id >> 4, s4 = id & 15;
            float4 v = __ldcg((const float4*)&hp[k*64 + s4*4]);
            *(float4*)&hs[k*68 + s4*4] = v;
        }
        __syncthreads();
        float4 ar = make_float4(0.f,0.f,0.f,0.f), az = ar, an = ar;
        #pragma unroll 8
        for (int kk = 0; kk < 64; kk++){
            int k = kbase + kk;
            float4 h4 = *(const float4*)&hs[k*68 + sbg*4];
            float wr = ws[k*5 + u_l];
            float wz = ws[(256 + k)*5 + u_l];
            float wn = ws[(512 + k)*5 + u_l];
            ar.x += wr*h4.x; ar.y += wr*h4.y; ar.z += wr*h4.z; ar.w += wr*h4.w;
            az.x += wz*h4.x; az.y += wz*h4.y; az.z += wz*h4.z; az.w += wz*h4.w;
            an.x += wn*h4.x; an.y += wn*h4.y; an.z += wn*h4.z; an.w += wn*h4.w;
        }
        float* rp = &red[(ks*64 + pair)*12];
        rp[0] = ar.x; rp[1] = ar.y; rp[2]  = ar.z; rp[3]  = ar.w;
        rp[4] = az.x; rp[5] = az.y; rp[6]  = az.z; rp[7]  = az.w;
        rp[8] = an.x; rp[9] = an.y; rp[10] = an.z; rp[11] = an.w;
        __syncthreads();
        {
            int q = ks;
            float sr = 0.f, sz = 0.f, sn = 0.f;
            #pragma unroll
            for (int kp = 0; kp < 4; kp++){
                const float* r2 = &red[(kp*64 + pair)*12];
                sr += r2[q]; sz += r2[4 + q]; sn += r2[8 + q];
            }
            const float* xi = g_XI + (size_t)((dir*TT + tt)*SBN + sb)*G3 + u;
            float r = 1.f/(1.f + expf(-(xi[0]   + sr + br)));
            float z = 1.f/(1.f + expf(-(xi[256] + sz + bz)));
            float n = tanhf(xi[512] + r*(sn + bn));
            float hv = (1.f - z)*n + z*hs[u*68 + sb];
            __stcg(&hn[u*64 + sb], hv);
            Y[(size_t)(sb*TT + tt)*HH2 + dir*HH + u] = hv;
        }
        // inter-block barrier among the 64 blocks of this dir
        __threadfence();
        __syncthreads();
        if (tid == 0){
            atomicAdd(&g_bar[dir], 1u);
            unsigned target = 64u*(unsigned)(t + 1);
            while (*(volatile unsigned*)&g_bar[dir] < target){}
        }
        __syncthreads();
    }
}

// ---------------- mma.sync pairwise highway scores ----------------
#define LSTR 516
#define ASTR 1040
#define LS_OFF 0
#define RS_OFF (8*LSTR*4)
#define AHI_OFF (RS_OFF + 8*LSTR*4)
#define ALO_OFF (AHI_OFF + 64*ASTR)
#define WT_OFF  (ALO_OFF + 64*ASTR)
#define BIAS_OFF (WT_OFF + 4*64*144)
#define SRED_OFF (BIAS_OFF + 192*4)
#define SMEM_SC  (SRED_OFF + 128*4)

__global__ void __launch_bounds__(256) k_scores_mma(const float* __restrict__ emb,
        const float* __restrict__ bnp, const float* __restrict__ bgp,
        const float* __restrict__ lwp){
    extern __shared__ char smc[];
    float* Ls = (float*)(smc + LS_OFF);
    float* Rs = (float*)(smc + RS_OFF);
    float* bias = (float*)(smc + BIAS_OFF);
    float* sred = (float*)(smc + SRED_OFF);
    const unsigned sbase = smem_u32(smc);
    int tid = threadIdx.x, w = tid >> 5, l = tid & 31;
    int b = blockIdx.y;
    int i0 = (blockIdx.x >> 3)*8, j0 = (blockIdx.x & 7)*8;
    int mw = w >> 1, nw = w & 1;

    for (int idx = tid; idx < 8*128; idx += 256){
        int row = idx >> 7, c4 = idx & 127;
        int itok = i0 + row, fi = itok >> 5, ti = itok & 31;
        *(float4*)&Ls[row*LSTR + c4*4] = *(const float4*)&emb[(size_t)((fi*BSZ + b)*TT + ti)*HH2 + c4*4];
        int jtok = j0 + row, fj = (jtok >> 5) + 2, tj = jtok & 31;
        *(float4*)&Rs[row*LSTR + c4*4] = *(const float4*)&emb[(size_t)((fj*BSZ + b)*TT + tj)*HH2 + c4*4];
    }
    __syncthreads();

    {
        int pb = tid >> 2, q = tid & 3;
        const float* lr = &Ls[(pb >> 3)*LSTR + q*128];
        const float* rr = &Rs[(pb & 7)*LSTR + q*128];
        char* ahi = smc + AHI_OFF + pb*ASTR + q*256;
        char* alo = smc + ALO_OFF + pb*ASTR + q*256;
        #pragma unroll
        for (int kk = 0; kk < 128; kk += 2){
            float d0 = fabsf(lr[kk]   - rr[kk]);
            float d1 = fabsf(lr[kk+1] - rr[kk+1]);
            __nv_bfloat16 h0 = __float2bfloat16(d0), h1 = __float2bfloat16(d1);
            __nv_bfloat16 e0 = __float2bfloat16(d0 - __bfloat162float(h0));
            __nv_bfloat16 e1 = __float2bfloat16(d1 - __bfloat162float(h1));
            unsigned hp = ((unsigned)*(unsigned short*)&h0) | (((unsigned)*(unsigned short*)&h1) << 16);
            unsigned lp = ((unsigned)*(unsigned short*)&e0) | (((unsigned)*(unsigned short*)&e1) << 16);
            *(unsigned*)(ahi + kk*2) = hp;
            *(unsigned*)(alo + kk*2) = lp;
        }
    }

    float sl[2] = {0.f, 0.f};

    for (int nc = 0; nc < 8; nc++){
        float acc[8][4];
        #pragma unroll
        for (int nt=0;nt<8;nt++){acc[nt][0]=0.f;acc[nt][1]=0.f;acc[nt][2]=0.f;acc[nt][3]=0.f;}
        __syncthreads();
        if (tid < 192){
            int t3 = tid >> 6, g = tid & 63;
            const float* src = (t3==0) ? bnp : (t3==1) ? bgp : lwp;
            bias[t3*64 + g] = src[nc*64 + g];
        }
        for (int kc = 0; kc < 8; kc++){
            __syncthreads();
            #pragma unroll
            for (int it = 0; it < 8; it++){
                int u = tid + it*256;
                int t4 = u >> 9, rem = u & 511, row = rem >> 3, c8 = rem & 7;
                const uint4* src = (const uint4*)&g_WS[((size_t)t4*512 + nc*64 + row)*512 + kc*64 + c8*8];
                *(uint4*)(smc + WT_OFF + t4*9216 + row*144 + c8*16) = *src;
            }
            __syncthreads();
            #pragma unroll
            for (int ks = 0; ks < 4; ks++){
                unsigned ah[4], al[4];
                unsigned arow = 16*mw + (l & 15);
                unsigned aoff = AHI_OFF + arow*ASTR + (unsigned)((kc*64 + ks*16 + (l>>4)*8)*2);
                ldsm4(ah, sbase + aoff);
                ldsm4(al, sbase + aoff + (ALO_OFF - AHI_OFF));
                #pragma unroll
                for (int nt = 0; nt < 8; nt++){
                    int thi = (nt < 4) ? 0 : 2;
                    unsigned grow = nw*32 + (nt & 3)*8 + (l & 7);
                    unsigned boff = WT_OFF + thi*9216 + grow*144 + (unsigned)((ks*16 + ((l>>3)&1)*8)*2);
                    unsigned bh[2], bl[2];
                    ldsm2(bh, sbase + boff);
                    ldsm2(bl, sbase + boff + 9216);
                    mma_bf16(acc[nt], ah, bh);
                    mma_bf16(acc[nt], al, bh);
                    mma_bf16(acc[nt], ah, bl);
                }
            }
        }
        #pragma unroll
        for (int nt = 0; nt < 4; nt++)
        #pragma unroll
        for (int rh = 0; rh < 2; rh++)
        #pragma unroll
        for (int cc = 0; cc < 2; cc++){
            float an = acc[nt][rh*2 + cc];
            float ag = acc[nt+4][rh*2 + cc];
            int kgl = nw*32 + nt*8 + (l & 3)*2 + cc;
            int kg = nc*64 + kgl;
            int r = 16*mw + 8*rh + (l >> 2);
            float d = fabsf(Ls[(r>>3)*LSTR + kg] - Rs[(r&7)*LSTR + kg]);
            float nn = fmaxf(an + bias[kgl], 0.f);
            float gv = 1.f/(1.f + __expf(-(ag + bias[64 + kgl])));
            sl[rh] += bias[128 + kgl]*(nn*gv + (1.f - gv)*d);
        }
    }
    #pragma unroll
    for (int rh = 0; rh < 2; rh++){
        float s = sl[rh];
        s += __shfl_xor_sync(0xffffffffu, s, 1);
        s += __shfl_xor_sync(0xffffffffu, s, 2);
        if ((l & 3) == 0){
            int r = 16*mw + 8*rh + (l >> 2);
            sred[r*2 + nw] = s;
        }
    }
    __syncthreads();
    if (tid < 64){
        float s = sred[tid*2] + sred[tid*2 + 1];
        int il = tid >> 3, jl = tid & 7;
        g_SP[(b*NTOK + i0 + il)*NTOK + j0 + jl] = s;
    }
}

// masked softmax; transposed=1 -> softmax over i for fixed j
__global__ void k_soft(const float* __restrict__ mask, float* __restrict__ Wout,
                       const float* __restrict__ lintb, int transposed){
    int b = blockIdx.y, r = blockIdx.x, j = threadIdx.x;
    float v = lintb[0] + (transposed ? g_SP[(b*NTOK + j)*NTOK + r]
                                     : g_SP[(b*NTOK + r)*NTOK + j]);
    v += (mask[b*NTOK + j] > 0.5f) ? 0.f : -1e10f;
    __shared__ float red[2];
    float m = v;
    #pragma unroll
    for (int off = 16; off; off >>= 1) m = fmaxf(m, __shfl_xor_sync(0xffffffffu, m, off));
    if ((j & 31) == 0) red[j >> 5] = m;
    __syncthreads();
    m = fmaxf(red[0], red[1]);
    __syncthreads();
    float e = expf(v - m), s = e;
    #pragma unroll
    for (int off = 16; off; off >>= 1) s += __shfl_xor_sync(0xffffffffu, s, off);
    if ((j & 31) == 0) red[j >> 5] = s;
    __syncthreads();
    Wout[(b*NTOK + r)*NTOK + j] = e / (red[0] + red[1]);
}

__global__ void __launch_bounds__(256) k_cmp(const float* __restrict__ emb,
        const float* __restrict__ W, float* __restrict__ OUT, int rside){
    int b = blockIdx.y, r = blockIdx.x, tid = threadIdx.x;
    __shared__ float w[64];
    __shared__ float a[512];
    if (tid < 64) w[tid] = W[(b*NTOK + r)*NTOK + tid];
    int f_own = (r >> 5) + (rside ? 2 : 0), t_own = r & 31;
    for (int k = tid; k < 512; k += 256)
        a[k] = emb[(size_t)((f_own*BSZ + b)*TT + t_own)*HH2 + k];
    __syncthreads();
    int k0 = tid, k1 = tid + 256;
    float acc0 = 0.f, acc1 = 0.f;
    for (int o = 0; o < 64; o++){
        int f_o = (o >> 5) + (rside ? 0 : 2), t_o = o & 31;
        const float* row = emb + (size_t)((f_o*BSZ + b)*TT + t_o)*HH2;
        float wv = w[o];
        acc0 += wv*fabsf(a[k0] - row[k0]);
        acc1 += wv*fabsf(a[k1] - row[k1]);
    }
    OUT[(size_t)(b*NTOK + r)*HH2 + k0] = acc0;
    OUT[(size_t)(b*NTOK + r)*HH2 + k1] = acc1;
}

__global__ void k_attw(const float* __restrict__ emb, const float* __restrict__ attrL,
                       const float* __restrict__ attrR){
    int t = blockIdx.x*4 + (threadIdx.x >> 5), lane = threadIdx.x & 31;
    int sf = blockIdx.y, b = blockIdx.z;
    const float* av = (sf < 2 ? attrL + sf*HH2 : attrR + (sf-2)*HH2);
    const float* row = emb + (size_t)((sf*BSZ + b)*TT + t)*HH2;
    float s = 0.f;
    for (int k = lane; k < HH2; k += 32) s += row[k]*av[k];
    #pragma unroll
    for (int off = 16; off; off >>= 1) s += __shfl_xor_sync(0xffffffffu, s, off);
    if (lane == 0) g_ATTS[(sf*BSZ + b)*TT + t] = s;
}

__global__ void k_attsoft(){
    int sf = blockIdx.x, b = blockIdx.y, t = threadIdx.x;
    float mk = (sf < 2) ? g_MTL[b*NTOK + sf*32 + t] : g_MTR[b*NTOK + (sf-2)*32 + t];
    float v = g_ATTS[(sf*BSZ + b)*TT + t] + (mk > 0.5f ? 0.f : -1e10f);
    float m = v;
    #pragma unroll
    for (int off = 16; off; off >>= 1) m = fmaxf(m, __shfl_xor_sync(0xffffffffu, m, off));
    float e = expf(v - m), s = e;
    #pragma unroll
    for (int off = 16; off; off >>= 1) s += __shfl_xor_sync(0xffffffffu, s, off);
    g_ATTW[(sf*BSZ + b)*TT + t] = e / s;
}

__global__ void __launch_bounds__(256) k_rep(const float* __restrict__ empty_attr){
    int sf = blockIdx.x, b = blockIdx.y, tid = threadIdx.x;
    const float* MT = (sf < 2) ? g_MTL + b*NTOK + sf*32 : g_MTR + b*NTOK + (sf-2)*32;
    float am = 0.f;
    for (int t = 0; t < 32; t++) am = fmaxf(am, MT[t]);
    const float* cmp = (sf < 2) ? g_LC : g_RC;
    int tok0 = (sf & 1)*32;
    for (int k = tid; k < HH2; k += 256){
        float acc = 0.f;
        for (int t = 0; t < 32; t++)
            acc += cmp[(size_t)(b*NTOK + tok0 + t)*HH2 + k]*g_ATTW[(sf*BSZ + b)*TT + t];
        g_CAT[b*DEDIM + sf*HH2 + k] = (am > 0.5f) ? acc : empty_attr[k];
    }
}

__global__ void __launch_bounds__(256) k_hwe(const float* __restrict__ Wn,
        const float* __restrict__ bn, const float* __restrict__ Wg,
        const float* __restrict__ bg){
    int n = blockIdx.x*8 + (threadIdx.x >> 5), lane = threadIdx.x & 31;
    int b = blockIdx.y;
    const float* c = g_CAT + b*DEDIM;
    float sn = 0.f, sg = 0.f;
    for (int k = lane; k < DEDIM; k += 32){
        float cv = c[k];
        sn += Wn[(size_t)n*DEDIM + k]*cv;
        sg += Wg[(size_t)n*DEDIM + k]*cv;
    }
    #pragma unroll
    for (int off = 16; off; off >>= 1){
        sn += __shfl_xor_sync(0xffffffffu, sn, off);
        sg += __shfl_xor_sync(0xffffffffu, sg, off);
    }
    if (lane == 0){
        float nn = fmaxf(sn + bn[n], 0.f);
        float gv = 1.f/(1.f + expf(-(sg + bg[n])));
        g_HW[b*DEDIM + n] = nn*gv + (1.f - gv)*c[n];
    }
}

__global__ void __launch_bounds__(256) k_logits(const float* __restrict__ lW,
        const float* __restrict__ lb, float* __restrict__ out){
    int b = blockIdx.x, tid = threadIdx.x;
    const float* h = g_HW + b*DEDIM;
    float a0 = 0.f, a1 = 0.f;
    for (int k = tid; k < DEDIM; k += 256){
        float hv = h[k];
        a0 += hv*lW[k];
        a1 += hv*lW[DEDIM + k];
    }
    #pragma unroll
    for (int off = 16; off; off >>= 1){
        a0 += __shfl_xor_sync(0xffffffffu, a0, off);
        a1 += __shfl_xor_sync(0xffffffffu, a1, off);
    }
    __shared__ float r0[8], r1[8];
    if ((tid & 31) == 0){ r0[tid >> 5] = a0; r1[tid >> 5] = a1; }
    __syncthreads();
    if (tid == 0){
        float s0 = 0.f, s1 = 0.f;
        for (int w = 0; w < 8; w++){ s0 += r0[w]; s1 += r1[w]; }
        s0 += lb[0]; s1 += lb[1];
        float m = fmaxf(s0, s1);
        float lse = m + logf(expf(s0 - m) + expf(s1 - m));
        out[b*2 + 0] = s0 - lse;
        out[b*2 + 1] = s1 - lse;
    }
}

extern "C" void kernel_launch(void* const* d_in, const int* in_sizes, int n_in,
                              void* d_out, int out_size) {
    const float* lf0 = (const float*)d_in[0];
    const float* lf1 = (const float*)d_in[1];
    const float* rf0 = (const float*)d_in[2];
    const float* rf1 = (const float*)d_in[3];
    const float* Wih0 = (const float*)d_in[4];
    const float* Whh0 = (const float*)d_in[5];
    const float* bih0 = (const float*)d_in[6];
    const float* bhh0 = (const float*)d_in[7];
    const float* Wih12 = (const float*)d_in[8];
    const float* Whh12 = (const float*)d_in[9];
    const float* bih12 = (const float*)d_in[10];
    const float* bhh12 = (const float*)d_in[11];
    const float* hwt_Wn = (const float*)d_in[12];
    const float* hwt_bn = (const float*)d_in[13];
    const float* hwt_Wg = (const float*)d_in[14];
    const float* hwt_bg = (const float*)d_in[15];
    const float* lint_W = (const float*)d_in[16];
    const float* lint_b = (const float*)d_in[17];
    const float* attrL = (const float*)d_in[18];
    const float* attrR = (const float*)d_in[19];
    const float* empty_attr = (const float*)d_in[20];
    const float* hwe_Wn = (const float*)d_in[21];
    const float* hwe_bn = (const float*)d_in[22];
    const float* hwe_Wg = (const float*)d_in[23];
    const float* hwe_bg = (const float*)d_in[24];
    const float* line_W = (const float*)d_in[25];
    const float* line_b = (const float*)d_in[26];
    float* out = (float*)d_out;

    float *X0, *HA, *HB, *WHT, *WL, *WR, *LC, *RC, *MTL, *MTR;
    cudaGetSymbolAddress((void**)&X0, g_X0);
    cudaGetSymbolAddress((void**)&HA, g_HA);
    cudaGetSymbolAddress((void**)&HB, g_HB);
    cudaGetSymbolAddress((void**)&WHT, g_WHT);
    cudaGetSymbolAddress((void**)&WL, g_WL);
    cudaGetSymbolAddress((void**)&WR, g_WR);
    cudaGetSymbolAddress((void**)&LC, g_LC);
    cudaGetSymbolAddress((void**)&RC, g_RC);
    cudaGetSymbolAddress((void**)&MTL, g_MTL);
    cudaGetSymbolAddress((void**)&MTR, g_MTR);

    cudaFuncSetAttribute(k_scores_mma, cudaFuncAttributeMaxDynamicSharedMemorySize, SMEM_SC);
    cudaFuncSetAttribute(k_gru_seq, cudaFuncAttributeMaxDynamicSharedMemorySize, SMEM_GRU);

    k_gather<<<1536, 256>>>(lf0, lf1, rf0, rf1);
    k_masks<<<256, 256>>>(lf0, lf1, rf0, rf1);
    k_wsplit<<<1024, 256>>>(hwt_Wn, hwt_Wg);
    k_wtrans<<<4608, 256>>>(Whh0, Whh12);

    for (int l = 0; l < 3; l++){
        const float* A = (l == 0) ? X0 : ((l == 1) ? HA : HB);
        int K = (l == 0) ? EDIM : HH2;
        const float* Wih = (l == 0) ? Wih0 : Wih12 + (size_t)(l-1)*2*G3*HH2;
        const float* bih = (l == 0) ? bih0 : bih12 + (size_t)(l-1)*2*G3;
        const float* bhh = (l == 0) ? bhh0 : bhh12 + (size_t)(l-1)*2*G3;
        const float* WhT = WHT + (size_t)l*2*HH*G3;
        float* Y = (l == 1) ? HB : HA;
        k_sgemm_xi<<<dim3(24, 16), 256>>>(A, K, Wih, bih);
        k_prep<<<128, 256>>>();
        k_gru_seq<<<dim3(64, 1, 2), 256, SMEM_GRU>>>(WhT, bhh, Y);
    }

    k_scores_mma<<<dim3(64, 16), 256, SMEM_SC>>>(HA, hwt_bn, hwt_bg, lint_W);
    k_soft<<<dim3(64, 16), 64>>>(MTR, WL, lint_b, 0);
    k_soft<<<dim3(64, 16), 64>>>(MTL, WR, lint_b, 1);
    k_cmp<<<dim3(64, 16), 256>>>(HA, WL, LC, 0);
    k_cmp<<<dim3(64, 16), 256>>>(HA, WR, RC, 1);
    k_attw<<<dim3(8, 4, 16), 128>>>(HA, attrL, attrR);
    k_attsoft<<<dim3(4, 16), 32>>>();
    k_rep<<<dim3(4, 16), 256>>>(empty_attr);
    k_hwe<<<dim3(256, 16), 256>>>(hwe_Wn, hwe_bn, hwe_Wg, hwe_bg);
    k_logits<<<16, 256>>>(line_W, line_b, out);
}

// round 14
// speedup vs baseline: 2.3105x; 1.1055x over previous
#include <cuda_runtime.h>
#include <cuda_bf16.h>
#include <math.h>

#define BSZ 16
#define TT 32
#define EDIM 768
#define HH 256
#define HH2 512
#define G3 768
#define SBN 64
#define NTOK 64
#define DEDIM 2048
#define HT_DIR 16384   // 256*64

// ---- scratch (device globals, no allocation) ----
__device__ float g_X0[SBN*TT*EDIM];
__device__ float g_XI[2*TT*SBN*G3];
__device__ float g_HA[SBN*TT*HH2];
__device__ float g_HB[SBN*TT*HH2];
__device__ float g_HT0[2*HT_DIR];
__device__ float g_HT1[2*HT_DIR];
__device__ float g_WHT[3*2*HH*G3];      // [layer][dir][k=256][row=768]
__device__ unsigned g_bar[2];
__device__ float g_SP[BSZ*NTOK*NTOK];
__device__ float g_WL[BSZ*NTOK*NTOK];
__device__ float g_WR[BSZ*NTOK*NTOK];
__device__ float g_LC[BSZ*NTOK*HH2];
__device__ float g_RC[BSZ*NTOK*HH2];
__device__ float g_MTL[BSZ*NTOK];
__device__ float g_MTR[BSZ*NTOK];
__device__ float g_ATTS[4*BSZ*TT];
__device__ float g_ATTW[4*BSZ*TT];
__device__ float g_CAT[BSZ*DEDIM];
__device__ float g_HW[BSZ*DEDIM];
// highway split weights: 0 = Wn-hi, 1 = Wn-lo, 2 = Wg-hi, 3 = Wg-lo; each [512][512] bf16
__device__ __nv_bfloat16 g_WS[4*512*512];
// xi GEMM splits: A (activations) hi then lo, each [2048][K<=768]
__device__ __nv_bfloat16 g_AS[2*2048*768];
// Wih splits: [layer][hi/lo][1536][768 padded] bf16
__device__ __nv_bfloat16 g_WIS[3*2*1536*768];

__device__ __forceinline__ unsigned smem_u32(const void* p){
    unsigned a;
    asm("{ .reg .u64 t; cvta.to.shared.u64 t, %1; cvt.u32.u64 %0, t; }" : "=r"(a) : "l"(p));
    return a;
}
__device__ __forceinline__ void ldsm4(unsigned* r, unsigned addr){
    asm volatile("ldmatrix.sync.aligned.m8n8.x4.shared.b16 {%0,%1,%2,%3}, [%4];"
        : "=r"(r[0]), "=r"(r[1]), "=r"(r[2]), "=r"(r[3]) : "r"(addr));
}
__device__ __forceinline__ void ldsm2(unsigned* r, unsigned addr){
    asm volatile("ldmatrix.sync.aligned.m8n8.x2.shared.b16 {%0,%1}, [%2];"
        : "=r"(r[0]), "=r"(r[1]) : "r"(addr));
}
__device__ __forceinline__ void mma_bf16(float* c, const unsigned* a, const unsigned* b){
    asm volatile("mma.sync.aligned.m16n8k16.row.col.f32.bf16.bf16.f32 "
        "{%0,%1,%2,%3}, {%4,%5,%6,%7}, {%8,%9}, {%0,%1,%2,%3};"
        : "+f"(c[0]), "+f"(c[1]), "+f"(c[2]), "+f"(c[3])
        : "r"(a[0]), "r"(a[1]), "r"(a[2]), "r"(a[3]), "r"(b[0]), "r"(b[1]));
}

// ---------------- small kernels ----------------
__global__ void k_prep(){
    int i = blockIdx.x*256 + threadIdx.x;
    if (i < 2*HT_DIR) g_HT0[i] = 0.f;
    if (i < 2) g_bar[i] = 0u;
}

__global__ void k_gather(const float* __restrict__ f0, const float* __restrict__ f1,
                         const float* __restrict__ f2, const float* __restrict__ f3){
    int i = blockIdx.x*256 + threadIdx.x;
    const int per = (BSZ*TT*EDIM)/4;
    int f = i / per, r = i - f*per;
    const float4* src = (f==0)?(const float4*)f0:(f==1)?(const float4*)f1
                      :(f==2)?(const float4*)f2:(const float4*)f3;
    ((float4*)g_X0)[i] = src[r];
}

__global__ void k_masks(const float* __restrict__ f0, const float* __restrict__ f1,
                        const float* __restrict__ f2, const float* __restrict__ f3){
    int warp = (blockIdx.x*256 + threadIdx.x) >> 5;
    int lane = threadIdx.x & 31;
    int f = warp / (BSZ*TT), r = warp % (BSZ*TT);
    const float* src = (f==0)?f0:(f==1)?f1:(f==2)?f2:f3;
    const float* row = src + (size_t)r*EDIM;
    bool nz = false;
    for (int k = lane; k < EDIM; k += 32) nz |= (row[k] != 0.f);
    unsigned any = __ballot_sync(0xffffffffu, nz);
    if (lane == 0){
        int b = r / TT, t = r % TT;
        float v = any ? 1.f : 0.f;
        if (f < 2) g_MTL[b*NTOK + f*32 + t] = v;
        else       g_MTR[b*NTOK + (f-2)*32 + t] = v;
    }
}

__global__ void k_wsplit(const float* __restrict__ Wn, const float* __restrict__ Wg){
    int i = blockIdx.x*256 + threadIdx.x;
    if (i < 512*512){
        float wn = Wn[i], wg = Wg[i];
        __nv_bfloat16 h;
        h = __float2bfloat16(wn);
        g_WS[0*262144 + i] = h;
        g_WS[1*262144 + i] = __float2bfloat16(wn - __bfloat162float(h));
        h = __float2bfloat16(wg);
        g_WS[2*262144 + i] = h;
        g_WS[3*262144 + i] = __float2bfloat16(wg - __bfloat162float(h));
    }
}

// split Wih (all 3 layers) into hi/lo bf16, padded stride 768
__global__ void k_wisplit(const float* __restrict__ Wih0, const float* __restrict__ Wih12){
    int idx = blockIdx.x*256 + threadIdx.x;      // over 3*1536*768
    if (idx >= 3*1536*768) return;
    int k = idx % 768, rest = idx / 768;
    int n = rest % 1536, l = rest / 1536;
    int Kl = (l == 0) ? 768 : 512;
    float v = 0.f;
    if (k < Kl)
        v = (l == 0) ? Wih0[(size_t)n*768 + k]
                     : Wih12[(size_t)(l-1)*1536*512 + (size_t)n*512 + k];
    __nv_bfloat16 h = __float2bfloat16(v);
    size_t base = (size_t)l*2*1536*768;
    g_WIS[base + (size_t)n*768 + k] = h;
    g_WIS[base + 1536*768 + (size_t)n*768 + k] = __float2bfloat16(v - __bfloat162float(h));
}

// split activations A[2048][K] into hi/lo bf16 (stride K)
__global__ void k_asplit(const float* __restrict__ A, int K){
    int idx = blockIdx.x*256 + threadIdx.x;
    if (idx >= 2048*K) return;
    float v = A[idx];
    __nv_bfloat16 h = __float2bfloat16(v);
    g_AS[idx] = h;
    g_AS[2048*768 + idx] = __float2bfloat16(v - __bfloat162float(h));
}

// transpose Whh into [ld = layer*2+dir][k][row] layout
__global__ void k_wtrans(const float* __restrict__ Whh0, const float* __restrict__ Whh12){
    int idx = blockIdx.x*256 + threadIdx.x;
    if (idx >= 3*2*768*256) return;
    int k = idx & 255, rest = idx >> 8;
    int row = rest % 768, ld = rest / 768;
    const float* src = (ld < 2) ? &Whh0[(size_t)ld*768*256]
                                : &Whh12[(size_t)(ld-2)*768*256];
    g_WHT[((size_t)ld*256 + k)*768 + row] = src[row*256 + k];
}

// ---------------- xi GEMM on tensor cores (3-term bf16 split) ----------------
// XI[m -> (dir,t,sb)][n -> (dir,g)] = A[2048][K] @ W[1536][K]^T + bih
// grid (24, 32): n0 = bx*64, m0 = by*64. 256 threads = 8 warps.
#define XA_HI 0
#define XA_LO 9216
#define XW_HI 18432
#define XW_LO 27648
#define SMEM_XI 36864

__global__ void __launch_bounds__(256) k_xi_mma(int K, int layer,
        const float* __restrict__ bih){
    extern __shared__ char smx[];
    const unsigned sbase = smem_u32(smx);
    int tid = threadIdx.x, w = tid >> 5, l = tid & 31;
    int n0 = blockIdx.x*64, m0 = blockIdx.y*64;
    int mw = w >> 1, nw = w & 1;
    const __nv_bfloat16* Ahi = g_AS;
    const __nv_bfloat16* Alo = g_AS + 2048*768;
    const __nv_bfloat16* Whi = g_WIS + (size_t)layer*2*1536*768;
    const __nv_bfloat16* Wlo = Whi + 1536*768;

    float acc[4][4];
    #pragma unroll
    for (int nt=0;nt<4;nt++){acc[nt][0]=0.f;acc[nt][1]=0.f;acc[nt][2]=0.f;acc[nt][3]=0.f;}

    int nkc = K >> 6;
    for (int kc = 0; kc < nkc; kc++){
        __syncthreads();
        // load A hi/lo tiles: 64 rows x 64 bf16 each (8 uint4 per row)
        #pragma unroll
        for (int it = 0; it < 2; it++){
            int id = tid + it*256;
            int row = id >> 3, c8 = id & 7;
            *(uint4*)(smx + XA_HI + row*144 + c8*16) =
                *(const uint4*)&Ahi[(size_t)(m0+row)*K + kc*64 + c8*8];
            *(uint4*)(smx + XA_LO + row*144 + c8*16) =
                *(const uint4*)&Alo[(size_t)(m0+row)*K + kc*64 + c8*8];
            *(uint4*)(smx + XW_HI + row*144 + c8*16) =
                *(const uint4*)&Whi[(size_t)(n0+row)*768 + kc*64 + c8*8];
            *(uint4*)(smx + XW_LO + row*144 + c8*16) =
                *(const uint4*)&Wlo[(size_t)(n0+row)*768 + kc*64 + c8*8];
        }
        __syncthreads();
        #pragma unroll
        for (int ks = 0; ks < 4; ks++){
            unsigned ah[4], al[4];
            unsigned arow = 16*mw + (l & 15);
            unsigned aoff = (unsigned)(arow*144 + (ks*16 + (l>>4)*8)*2);
            ldsm4(ah, sbase + XA_HI + aoff);
            ldsm4(al, sbase + XA_LO + aoff);
            #pragma unroll
            for (int nt = 0; nt < 4; nt++){
                unsigned grow = nw*32 + nt*8 + (l & 7);
                unsigned boff = (unsigned)(grow*144 + (ks*16 + ((l>>3)&1)*8)*2);
                unsigned bh[2], bl[2];
                ldsm2(bh, sbase + XW_HI + boff);
                ldsm2(bl, sbase + XW_LO + boff);
                mma_bf16(acc[nt], ah, bh);
                mma_bf16(acc[nt], al, bh);
                mma_bf16(acc[nt], ah, bl);
            }
        }
    }
    // epilogue: write XI with bias
    #pragma unroll
    for (int nt = 0; nt < 4; nt++)
    #pragma unroll
    for (int rh = 0; rh < 2; rh++)
    #pragma unroll
    for (int cc = 0; cc < 2; cc++){
        int r = 16*mw + 8*rh + (l >> 2);
        int col = nw*32 + nt*8 + (l & 3)*2 + cc;
        int m = m0 + r, n = n0 + col;
        int sb = m >> 5, t = m & 31;
        int dir = (n >= G3) ? 1 : 0, g = n - dir*G3;
        g_XI[(size_t)((dir*TT + t)*SBN + sb)*G3 + g] = acc[nt][rh*2 + cc] + bih[n];
    }
}

// ---------------- persistent GRU layer ----------------
#define GRU_HS_F 17408
#define GRU_WS_F 3840
#define GRU_RED_F 3072
#define SMEM_GRU ((GRU_HS_F + GRU_WS_F + GRU_RED_F)*4)

__global__ void __launch_bounds__(256) k_gru_seq(const float* __restrict__ WhT,
        const float* __restrict__ bhh, float* __restrict__ Y){
    extern __shared__ float sm[];
    float* hs  = sm;
    float* ws  = sm + GRU_HS_F;
    float* red = sm + GRU_HS_F + GRU_WS_F;
    int dir = blockIdx.z;
    int tid = threadIdx.x;
    int u_l = tid & 3, sbg = (tid >> 2) & 15, ks = tid >> 6;
    int u0 = blockIdx.x * 4;
    const float* wt = WhT + (size_t)dir*HH*G3;
    #pragma unroll
    for (int i = 0; i < 3; i++){
        int id = tid + i*256;
        int g = id >> 8, k = id & 255;
        float4 v = *(const float4*)&wt[(size_t)k*G3 + g*HH + u0];
        float* d = &ws[(g*256 + k)*5];
        d[0] = v.x; d[1] = v.y; d[2] = v.z; d[3] = v.w;
    }
    int u = u0 + u_l;
    int sb = sbg*4 + ks;
    float br = bhh[dir*G3 + u], bz = bhh[dir*G3 + 256 + u], bn = bhh[dir*G3 + 512 + u];
    int kbase = ks*64;
    int pair = tid & 63;

    for (int t = 0; t < 32; t++){
        int tt = dir ? (31 - t) : t;
        const float* hp = ((t & 1) ? g_HT1 : g_HT0) + dir*HT_DIR;
        float* hn = ((t & 1) ? g_HT0 : g_HT1) + dir*HT_DIR;
        __syncthreads();
        #pragma unroll
        for (int i = 0; i < 16; i++){
            int id = tid + i*256;
            int k = id >> 4, s4 = id & 15;
            float4 v = __ldcg((const float4*)&hp[k*64 + s4*4]);
            *(float4*)&hs[k*68 + s4*4] = v;
        }
        __syncthreads();
        float4 ar = make_float4(0.f,0.f,0.f,0.f), az = ar, an = ar;
        #pragma unroll 8
        for (int kk = 0; kk < 64; kk++){
            int k = kbase + kk;
            float4 h4 = *(const float4*)&hs[k*68 + sbg*4];
            float wr = ws[k*5 + u_l];
            float wz = ws[(256 + k)*5 + u_l];
            float wn = ws[(512 + k)*5 + u_l];
            ar.x += wr*h4.x; ar.y += wr*h4.y; ar.z += wr*h4.z; ar.w += wr*h4.w;
            az.x += wz*h4.x; az.y += wz*h4.y; az.z += wz*h4.z; az.w += wz*h4.w;
            an.x += wn*h4.x; an.y += wn*h4.y; an.z += wn*h4.z; an.w += wn*h4.w;
        }
        float* rp = &red[(ks*64 + pair)*12];
        rp[0] = ar.x; rp[1] = ar.y; rp[2]  = ar.z; rp[3]  = ar.w;
        rp[4] = az.x; rp[5] = az.y; rp[6]  = az.z; rp[7]  = az.w;
        rp[8] = an.x; rp[9] = an.y; rp[10] = an.z; rp[11] = an.w;
        __syncthreads();
        {
            int q = ks;
            float sr = 0.f, sz = 0.f, sn = 0.f;
            #pragma unroll
            for (int kp = 0; kp < 4; kp++){
                const float* r2 = &red[(kp*64 + pair)*12];
                sr += r2[q]; sz += r2[4 + q]; sn += r2[8 + q];
            }
            const float* xi = g_XI + (size_t)((dir*TT + tt)*SBN + sb)*G3 + u;
            float r = 1.f/(1.f + expf(-(xi[0]   + sr + br)));
            float z = 1.f/(1.f + expf(-(xi[256] + sz + bz)));
            float n = tanhf(xi[512] + r*(sn + bn));
            float hv = (1.f - z)*n + z*hs[u*68 + sb];
            __stcg(&hn[u*64 + sb], hv);
            Y[(size_t)(sb*TT + tt)*HH2 + dir*HH + u] = hv;
        }
        __threadfence();
        __syncthreads();
        if (tid == 0){
            atomicAdd(&g_bar[dir], 1u);
            unsigned target = 64u*(unsigned)(t + 1);
            while (*(volatile unsigned*)&g_bar[dir] < target){}
        }
        __syncthreads();
    }
}

// ---------------- mma.sync pairwise highway scores ----------------
#define LSTR 516
#define ASTR 1040
#define LS_OFF 0
#define RS_OFF (8*LSTR*4)
#define AHI_OFF (RS_OFF + 8*LSTR*4)
#define ALO_OFF (AHI_OFF + 64*ASTR)
#define WT_OFF  (ALO_OFF + 64*ASTR)
#define BIAS_OFF (WT_OFF + 4*64*144)
#define SRED_OFF (BIAS_OFF + 192*4)
#define SMEM_SC  (SRED_OFF + 128*4)

__global__ void __launch_bounds__(256) k_scores_mma(const float* __restrict__ emb,
        const float* __restrict__ bnp, const float* __restrict__ bgp,
        const float* __restrict__ lwp){
    extern __shared__ char smc[];
    float* Ls = (float*)(smc + LS_OFF);
    float* Rs = (float*)(smc + RS_OFF);
    float* bias = (float*)(smc + BIAS_OFF);
    float* sred = (float*)(smc + SRED_OFF);
    const unsigned sbase = smem_u32(smc);
    int tid = threadIdx.x, w = tid >> 5, l = tid & 31;
    int b = blockIdx.y;
    int i0 = (blockIdx.x >> 3)*8, j0 = (blockIdx.x & 7)*8;
    int mw = w >> 1, nw = w & 1;

    for (int idx = tid; idx < 8*128; idx += 256){
        int row = idx >> 7, c4 = idx & 127;
        int itok = i0 + row, fi = itok >> 5, ti = itok & 31;
        *(float4*)&Ls[row*LSTR + c4*4] = *(const float4*)&emb[(size_t)((fi*BSZ + b)*TT + ti)*HH2 + c4*4];
        int jtok = j0 + row, fj = (jtok >> 5) + 2, tj = jtok & 31;
        *(float4*)&Rs[row*LSTR + c4*4] = *(const float4*)&emb[(size_t)((fj*BSZ + b)*TT + tj)*HH2 + c4*4];
    }
    __syncthreads();

    {
        int pb = tid >> 2, q = tid & 3;
        const float* lr = &Ls[(pb >> 3)*LSTR + q*128];
        const float* rr = &Rs[(pb & 7)*LSTR + q*128];
        char* ahi = smc + AHI_OFF + pb*ASTR + q*256;
        char* alo = smc + ALO_OFF + pb*ASTR + q*256;
        #pragma unroll
        for (int kk = 0; kk < 128; kk += 2){
            float d0 = fabsf(lr[kk]   - rr[kk]);
            float d1 = fabsf(lr[kk+1] - rr[kk+1]);
            __nv_bfloat16 h0 = __float2bfloat16(d0), h1 = __float2bfloat16(d1);
            __nv_bfloat16 e0 = __float2bfloat16(d0 - __bfloat162float(h0));
            __nv_bfloat16 e1 = __float2bfloat16(d1 - __bfloat162float(h1));
            unsigned hp = ((unsigned)*(unsigned short*)&h0) | (((unsigned)*(unsigned short*)&h1) << 16);
            unsigned lp = ((unsigned)*(unsigned short*)&e0) | (((unsigned)*(unsigned short*)&e1) << 16);
            *(unsigned*)(ahi + kk*2) = hp;
            *(unsigned*)(alo + kk*2) = lp;
        }
    }

    float sl[2] = {0.f, 0.f};

    for (int nc = 0; nc < 8; nc++){
        float acc[8][4];
        #pragma unroll
        for (int nt=0;nt<8;nt++){acc[nt][0]=0.f;acc[nt][1]=0.f;acc[nt][2]=0.f;acc[nt][3]=0.f;}
        __syncthreads();
        if (tid < 192){
            int t3 = tid >> 6, g = tid & 63;
            const float* src = (t3==0) ? bnp : (t3==1) ? bgp : lwp;
            bias[t3*64 + g] = src[nc*64 + g];
        }
        for (int kc = 0; kc < 8; kc++){
            __syncthreads();
            #pragma unroll
            for (int it = 0; it < 8; it++){
                int u = tid + it*256;
                int t4 = u >> 9, rem = u & 511, row = rem >> 3, c8 = rem & 7;
                const uint4* src = (const uint4*)&g_WS[((size_t)t4*512 + nc*64 + row)*512 + kc*64 + c8*8];
                *(uint4*)(smc + WT_OFF + t4*9216 + row*144 + c8*16) = *src;
            }
            __syncthreads();
            #pragma unroll
            for (int ks = 0; ks < 4; ks++){
                unsigned ah[4], al[4];
                unsigned arow = 16*mw + (l & 15);
                unsigned aoff = AHI_OFF + arow*ASTR + (unsigned)((kc*64 + ks*16 + (l>>4)*8)*2);
                ldsm4(ah, sbase + aoff);
                ldsm4(al, sbase + aoff + (ALO_OFF - AHI_OFF));
                #pragma unroll
                for (int nt = 0; nt < 8; nt++){
                    int thi = (nt < 4) ? 0 : 2;
                    unsigned grow = nw*32 + (nt & 3)*8 + (l & 7);
                    unsigned boff = WT_OFF + thi*9216 + grow*144 + (unsigned)((ks*16 + ((l>>3)&1)*8)*2);
                    unsigned bh[2], bl[2];
                    ldsm2(bh, sbase + boff);
                    ldsm2(bl, sbase + boff + 9216);
                    mma_bf16(acc[nt], ah, bh);
                    mma_bf16(acc[nt], al, bh);
                    mma_bf16(acc[nt], ah, bl);
                }
            }
        }
        #pragma unroll
        for (int nt = 0; nt < 4; nt++)
        #pragma unroll
        for (int rh = 0; rh < 2; rh++)
        #pragma unroll
        for (int cc = 0; cc < 2; cc++){
            float an = acc[nt][rh*2 + cc];
            float ag = acc[nt+4][rh*2 + cc];
            int kgl = nw*32 + nt*8 + (l & 3)*2 + cc;
            int kg = nc*64 + kgl;
            int r = 16*mw + 8*rh + (l >> 2);
            float d = fabsf(Ls[(r>>3)*LSTR + kg] - Rs[(r&7)*LSTR + kg]);
            float nn = fmaxf(an + bias[kgl], 0.f);
            float gv = 1.f/(1.f + __expf(-(ag + bias[64 + kgl])));
            sl[rh] += bias[128 + kgl]*(nn*gv + (1.f - gv)*d);
        }
    }
    #pragma unroll
    for (int rh = 0; rh < 2; rh++){
        float s = sl[rh];
        s += __shfl_xor_sync(0xffffffffu, s, 1);
        s += __shfl_xor_sync(0xffffffffu, s, 2);
        if ((l & 3) == 0){
            int r = 16*mw + 8*rh + (l >> 2);
            sred[r*2 + nw] = s;
        }
    }
    __syncthreads();
    if (tid < 64){
        float s = sred[tid*2] + sred[tid*2 + 1];
        int il = tid >> 3, jl = tid & 7;
        g_SP[(b*NTOK + i0 + il)*NTOK + j0 + jl] = s;
    }
}

// masked softmax; transposed=1 -> softmax over i for fixed j
__global__ void k_soft(const float* __restrict__ mask, float* __restrict__ Wout,
                       const float* __restrict__ lintb, int transposed){
    int b = blockIdx.y, r = blockIdx.x, j = threadIdx.x;
    float v = lintb[0] + (transposed ? g_SP[(b*NTOK + j)*NTOK + r]
                                     : g_SP[(b*NTOK + r)*NTOK + j]);
    v += (mask[b*NTOK + j] > 0.5f) ? 0.f : -1e10f;
    __shared__ float red[2];
    float m = v;
    #pragma unroll
    for (int off = 16; off; off >>= 1) m = fmaxf(m, __shfl_xor_sync(0xffffffffu, m, off));
    if ((j & 31) == 0) red[j >> 5] = m;
    __syncthreads();
    m = fmaxf(red[0], red[1]);
    __syncthreads();
    float e = expf(v - m), s = e;
    #pragma unroll
    for (int off = 16; off; off >>= 1) s += __shfl_xor_sync(0xffffffffu, s, off);
    if ((j & 31) == 0) red[j >> 5] = s;
    __syncthreads();
    Wout[(b*NTOK + r)*NTOK + j] = e / (red[0] + red[1]);
}

__global__ void __launch_bounds__(256) k_cmp(const float* __restrict__ emb,
        const float* __restrict__ W, float* __restrict__ OUT, int rside){
    int b = blockIdx.y, r = blockIdx.x, tid = threadIdx.x;
    __shared__ float w[64];
    __shared__ float a[512];
    if (tid < 64) w[tid] = W[(b*NTOK + r)*NTOK + tid];
    int f_own = (r >> 5) + (rside ? 2 : 0), t_own = r & 31;
    for (int k = tid; k < 512; k += 256)
        a[k] = emb[(size_t)((f_own*BSZ + b)*TT + t_own)*HH2 + k];
    __syncthreads();
    int k0 = tid, k1 = tid + 256;
    float acc0 = 0.f, acc1 = 0.f;
    for (int o = 0; o < 64; o++){
        int f_o = (o >> 5) + (rside ? 0 : 2), t_o = o & 31;
        const float* row = emb + (size_t)((f_o*BSZ + b)*TT + t_o)*HH2;
        float wv = w[o];
        acc0 += wv*fabsf(a[k0] - row[k0]);
        acc1 += wv*fabsf(a[k1] - row[k1]);
    }
    OUT[(size_t)(b*NTOK + r)*HH2 + k0] = acc0;
    OUT[(size_t)(b*NTOK + r)*HH2 + k1] = acc1;
}

__global__ void k_attw(const float* __restrict__ emb, const float* __restrict__ attrL,
                       const float* __restrict__ attrR){
    int t = blockIdx.x*4 + (threadIdx.x >> 5), lane = threadIdx.x & 31;
    int sf = blockIdx.y, b = blockIdx.z;
    const float* av = (sf < 2 ? attrL + sf*HH2 : attrR + (sf-2)*HH2);
    const float* row = emb + (size_t)((sf*BSZ + b)*TT + t)*HH2;
    float s = 0.f;
    for (int k = lane; k < HH2; k += 32) s += row[k]*av[k];
    #pragma unroll
    for (int off = 16; off; off >>= 1) s += __shfl_xor_sync(0xffffffffu, s, off);
    if (lane == 0) g_ATTS[(sf*BSZ + b)*TT + t] = s;
}

__global__ void k_attsoft(){
    int sf = blockIdx.x, b = blockIdx.y, t = threadIdx.x;
    float mk = (sf < 2) ? g_MTL[b*NTOK + sf*32 + t] : g_MTR[b*NTOK + (sf-2)*32 + t];
    float v = g_ATTS[(sf*BSZ + b)*TT + t] + (mk > 0.5f ? 0.f : -1e10f);
    float m = v;
    #pragma unroll
    for (int off = 16; off; off >>= 1) m = fmaxf(m, __shfl_xor_sync(0xffffffffu, m, off));
    float e = expf(v - m), s = e;
    #pragma unroll
    for (int off = 16; off; off >>= 1) s += __shfl_xor_sync(0xffffffffu, s, off);
    g_ATTW[(sf*BSZ + b)*TT + t] = e / s;
}

__global__ void __launch_bounds__(256) k_rep(const float* __restrict__ empty_attr){
    int sf = blockIdx.x, b = blockIdx.y, tid = threadIdx.x;
    const float* MT = (sf < 2) ? g_MTL + b*NTOK + sf*32 : g_MTR + b*NTOK + (sf-2)*32;
    float am = 0.f;
    for (int t = 0; t < 32; t++) am = fmaxf(am, MT[t]);
    const float* cmp = (sf < 2) ? g_LC : g_RC;
    int tok0 = (sf & 1)*32;
    for (int k = tid; k < HH2; k += 256){
        float acc = 0.f;
        for (int t = 0; t < 32; t++)
            acc += cmp[(size_t)(b*NTOK + tok0 + t)*HH2 + k]*g_ATTW[(sf*BSZ + b)*TT + t];
        g_CAT[b*DEDIM + sf*HH2 + k] = (am > 0.5f) ? acc : empty_attr[k];
    }
}

__global__ void __launch_bounds__(256) k_hwe(const float* __restrict__ Wn,
        const float* __restrict__ bn, const float* __restrict__ Wg,
        const float* __restrict__ bg){
    int n = blockIdx.x*8 + (threadIdx.x >> 5), lane = threadIdx.x & 31;
    int b = blockIdx.y;
    const float* c = g_CAT + b*DEDIM;
    float sn = 0.f, sg = 0.f;
    for (int k = lane; k < DEDIM; k += 32){
        float cv = c[k];
        sn += Wn[(size_t)n*DEDIM + k]*cv;
        sg += Wg[(size_t)n*DEDIM + k]*cv;
    }
    #pragma unroll
    for (int off = 16; off; off >>= 1){
        sn += __shfl_xor_sync(0xffffffffu, sn, off);
        sg += __shfl_xor_sync(0xffffffffu, sg, off);
    }
    if (lane == 0){
        float nn = fmaxf(sn + bn[n], 0.f);
        float gv = 1.f/(1.f + expf(-(sg + bg[n])));
        g_HW[b*DEDIM + n] = nn*gv + (1.f - gv)*c[n];
    }
}

__global__ void __launch_bounds__(256) k_logits(const float* __restrict__ lW,
        const float* __restrict__ lb, float* __restrict__ out){
    int b = blockIdx.x, tid = threadIdx.x;
    const float* h = g_HW + b*DEDIM;
    float a0 = 0.f, a1 = 0.f;
    for (int k = tid; k < DEDIM; k += 256){
        float hv = h[k];
        a0 += hv*lW[k];
        a1 += hv*lW[DEDIM + k];
    }
    #pragma unroll
    for (int off = 16; off; off >>= 1){
        a0 += __shfl_xor_sync(0xffffffffu, a0, off);
        a1 += __shfl_xor_sync(0xffffffffu, a1, off);
    }
    __shared__ float r0[8], r1[8];
    if ((tid & 31) == 0){ r0[tid >> 5] = a0; r1[tid >> 5] = a1; }
    __syncthreads();
    if (tid == 0){
        float s0 = 0.f, s1 = 0.f;
        for (int w = 0; w < 8; w++){ s0 += r0[w]; s1 += r1[w]; }
        s0 += lb[0]; s1 += lb[1];
        float m = fmaxf(s0, s1);
        float lse = m + logf(expf(s0 - m) + expf(s1 - m));
        out[b*2 + 0] = s0 - lse;
        out[b*2 + 1] = s1 - lse;
    }
}

extern "C" void kernel_launch(void* const* d_in, const int* in_sizes, int n_in,
                              void* d_out, int out_size) {
    const float* lf0 = (const float*)d_in[0];
    const float* lf1 = (const float*)d_in[1];
    const float* rf0 = (const float*)d_in[2];
    const float* rf1 = (const float*)d_in[3];
    const float* Wih0 = (const float*)d_in[4];
    const float* Whh0 = (const float*)d_in[5];
    const float* bih0 = (const float*)d_in[6];
    const float* bhh0 = (const float*)d_in[7];
    const float* Wih12 = (const float*)d_in[8];
    const float* Whh12 = (const float*)d_in[9];
    const float* bih12 = (const float*)d_in[10];
    const float* bhh12 = (const float*)d_in[11];
    const float* hwt_Wn = (const float*)d_in[12];
    const float* hwt_bn = (const float*)d_in[13];
    const float* hwt_Wg = (const float*)d_in[14];
    const float* hwt_bg = (const float*)d_in[15];
    const float* lint_W = (const float*)d_in[16];
    const float* lint_b = (const float*)d_in[17];
    const float* attrL = (const float*)d_in[18];
    const float* attrR = (const float*)d_in[19];
    const float* empty_attr = (const float*)d_in[20];
    const float* hwe_Wn = (const float*)d_in[21];
    const float* hwe_bn = (const float*)d_in[22];
    const float* hwe_Wg = (const float*)d_in[23];
    const float* hwe_bg = (const float*)d_in[24];
    const float* line_W = (const float*)d_in[25];
    const float* line_b = (const float*)d_in[26];
    float* out = (float*)d_out;

    float *X0, *HA, *HB, *WHT, *WL, *WR, *LC, *RC, *MTL, *MTR;
    cudaGetSymbolAddress((void**)&X0, g_X0);
    cudaGetSymbolAddress((void**)&HA, g_HA);
    cudaGetSymbolAddress((void**)&HB, g_HB);
    cudaGetSymbolAddress((void**)&WHT, g_WHT);
    cudaGetSymbolAddress((void**)&WL, g_WL);
    cudaGetSymbolAddress((void**)&WR, g_WR);
    cudaGetSymbolAddress((void**)&LC, g_LC);
    cudaGetSymbolAddress((void**)&RC, g_RC);
    cudaGetSymbolAddress((void**)&MTL, g_MTL);
    cudaGetSymbolAddress((void**)&MTR, g_MTR);

    cudaFuncSetAttribute(k_scores_mma, cudaFuncAttributeMaxDynamicSharedMemorySize, SMEM_SC);
    cudaFuncSetAttribute(k_gru_seq, cudaFuncAttributeMaxDynamicSharedMemorySize, SMEM_GRU);
    cudaFuncSetAttribute(k_xi_mma, cudaFuncAttributeMaxDynamicSharedMemorySize, SMEM_XI);

    k_gather<<<1536, 256>>>(lf0, lf1, rf0, rf1);
    k_masks<<<256, 256>>>(lf0, lf1, rf0, rf1);
    k_wsplit<<<1024, 256>>>(hwt_Wn, hwt_Wg);
    k_wisplit<<<13824, 256>>>(Wih0, Wih12);
    k_wtrans<<<4608, 256>>>(Whh0, Whh12);

    for (int l = 0; l < 3; l++){
        const float* A = (l == 0) ? X0 : ((l == 1) ? HA : HB);
        int K = (l == 0) ? EDIM : HH2;
        const float* bih = (l == 0) ? bih0 : bih12 + (size_t)(l-1)*2*G3;
        const float* bhh = (l == 0) ? bhh0 : bhh12 + (size_t)(l-1)*2*G3;
        const float* WhT = WHT + (size_t)l*2*HH*G3;
        float* Y = (l == 1) ? HB : HA;
        k_asplit<<<(2048*K + 255)/256, 256>>>(A, K);
        k_xi_mma<<<dim3(24, 32), 256, SMEM_XI>>>(K, l, bih);
        k_prep<<<128, 256>>>();
        k_gru_seq<<<dim3(64, 1, 2), 256, SMEM_GRU>>>(WhT, bhh, Y);
    }

    k_scores_mma<<<dim3(64, 16), 256, SMEM_SC>>>(HA, hwt_bn, hwt_bg, lint_W);
    k_soft<<<dim3(64, 16), 64>>>(MTR, WL, lint_b, 0);
    k_soft<<<dim3(64, 16), 64>>>(MTL, WR, lint_b, 1);
    k_cmp<<<dim3(64, 16), 256>>>(HA, WL, LC, 0);
    k_cmp<<<dim3(64, 16), 256>>>(HA, WR, RC, 1);
    k_attw<<<dim3(8, 4, 16), 128>>>(HA, attrL, attrR);
    k_attsoft<<<dim3(4, 16), 32>>>();
    k_rep<<<dim3(4, 16), 256>>>(empty_attr);
    k_hwe<<<dim3(256, 16), 256>>>(hwe_Wn, hwe_bn, hwe_Wg, hwe_bg);
    k_logits<<<16, 256>>>(line_W, line_b, out);
}

// round 15
// speedup vs baseline: 2.4609x; 1.0651x over previous
#include <cuda_runtime.h>
#include <cuda_bf16.h>
#include <math.h>

#define BSZ 16
#define TT 32
#define EDIM 768
#define HH 256
#define HH2 512
#define G3 768
#define SBN 64
#define NTOK 64
#define DEDIM 2048
#define HT_DIR 16384   // 256*64

// ---- scratch (device globals, no allocation) ----
__device__ float g_X0[SBN*TT*EDIM];
__device__ float g_XI[2*TT*SBN*G3];
__device__ float g_HA[SBN*TT*HH2];
__device__ float g_HB[SBN*TT*HH2];
__device__ float g_HT0[2*HT_DIR];
__device__ float g_HT1[2*HT_DIR];
__device__ float g_WHT[3*2*HH*G3];      // [layer][dir][k=256][row=768]
__device__ unsigned g_bar[2];
__device__ float g_SP[BSZ*NTOK*NTOK];
__device__ float g_WL[BSZ*NTOK*NTOK];
__device__ float g_WR[BSZ*NTOK*NTOK];
__device__ float g_LC[BSZ*NTOK*HH2];
__device__ float g_RC[BSZ*NTOK*HH2];
__device__ float g_MTL[BSZ*NTOK];
__device__ float g_MTR[BSZ*NTOK];
__device__ float g_ATTS[4*BSZ*TT];
__device__ float g_ATTW[4*BSZ*TT];
__device__ float g_CAT[BSZ*DEDIM];
__device__ float g_HW[BSZ*DEDIM];
// highway split weights: 0 = Wn-hi, 1 = Wn-lo, 2 = Wg-hi, 3 = Wg-lo; each [512][512] bf16
__device__ __nv_bfloat16 g_WS[4*512*512];
// xi GEMM splits: A (activations) hi then lo, each [2048][K<=768]
__device__ __nv_bfloat16 g_AS[2*2048*768];
// Wih splits: [layer][hi/lo][1536][768 padded] bf16
__device__ __nv_bfloat16 g_WIS[3*2*1536*768];

__device__ __forceinline__ unsigned smem_u32(const void* p){
    unsigned a;
    asm("{ .reg .u64 t; cvta.to.shared.u64 t, %1; cvt.u32.u64 %0, t; }" : "=r"(a) : "l"(p));
    return a;
}
__device__ __forceinline__ void ldsm4(unsigned* r, unsigned addr){
    asm volatile("ldmatrix.sync.aligned.m8n8.x4.shared.b16 {%0,%1,%2,%3}, [%4];"
        : "=r"(r[0]), "=r"(r[1]), "=r"(r[2]), "=r"(r[3]) : "r"(addr));
}
__device__ __forceinline__ void ldsm2(unsigned* r, unsigned addr){
    asm volatile("ldmatrix.sync.aligned.m8n8.x2.shared.b16 {%0,%1}, [%2];"
        : "=r"(r[0]), "=r"(r[1]) : "r"(addr));
}
__device__ __forceinline__ void mma_bf16(float* c, const unsigned* a, const unsigned* b){
    asm volatile("mma.sync.aligned.m16n8k16.row.col.f32.bf16.bf16.f32 "
        "{%0,%1,%2,%3}, {%4,%5,%6,%7}, {%8,%9}, {%0,%1,%2,%3};"
        : "+f"(c[0]), "+f"(c[1]), "+f"(c[2]), "+f"(c[3])
        : "r"(a[0]), "r"(a[1]), "r"(a[2]), "r"(a[3]), "r"(b[0]), "r"(b[1]));
}
__device__ __forceinline__ void cpasync16(unsigned dst, const void* src){
    asm volatile("cp.async.cg.shared.global [%0], [%1], 16;" :: "r"(dst), "l"(src));
}
#define CP_COMMIT() asm volatile("cp.async.commit_group;" ::: "memory")
#define CP_WAIT0()  asm volatile("cp.async.wait_group 0;" ::: "memory")

// ---------------- small kernels ----------------
__global__ void k_prep(){
    int i = blockIdx.x*256 + threadIdx.x;
    if (i < 2*HT_DIR) g_HT0[i] = 0.f;
    if (i < 2) g_bar[i] = 0u;
}

__global__ void k_gather(const float* __restrict__ f0, const float* __restrict__ f1,
                         const float* __restrict__ f2, const float* __restrict__ f3){
    int i = blockIdx.x*256 + threadIdx.x;
    const int per = (BSZ*TT*EDIM)/4;
    int f = i / per, r = i - f*per;
    const float4* src = (f==0)?(const float4*)f0:(f==1)?(const float4*)f1
                      :(f==2)?(const float4*)f2:(const float4*)f3;
    ((float4*)g_X0)[i] = src[r];
}

__global__ void k_masks(const float* __restrict__ f0, const float* __restrict__ f1,
                        const float* __restrict__ f2, const float* __restrict__ f3){
    int warp = (blockIdx.x*256 + threadIdx.x) >> 5;
    int lane = threadIdx.x & 31;
    int f = warp / (BSZ*TT), r = warp % (BSZ*TT);
    const float* src = (f==0)?f0:(f==1)?f1:(f==2)?f2:f3;
    const float* row = src + (size_t)r*EDIM;
    bool nz = false;
    for (int k = lane; k < EDIM; k += 32) nz |= (row[k] != 0.f);
    unsigned any = __ballot_sync(0xffffffffu, nz);
    if (lane == 0){
        int b = r / TT, t = r % TT;
        float v = any ? 1.f : 0.f;
        if (f < 2) g_MTL[b*NTOK + f*32 + t] = v;
        else       g_MTR[b*NTOK + (f-2)*32 + t] = v;
    }
}

__global__ void k_wsplit(const float* __restrict__ Wn, const float* __restrict__ Wg){
    int i = blockIdx.x*256 + threadIdx.x;
    if (i < 512*512){
        float wn = Wn[i], wg = Wg[i];
        __nv_bfloat16 h;
        h = __float2bfloat16(wn);
        g_WS[0*262144 + i] = h;
        g_WS[1*262144 + i] = __float2bfloat16(wn - __bfloat162float(h));
        h = __float2bfloat16(wg);
        g_WS[2*262144 + i] = h;
        g_WS[3*262144 + i] = __float2bfloat16(wg - __bfloat162float(h));
    }
}

__global__ void k_wisplit(const float* __restrict__ Wih0, const float* __restrict__ Wih12){
    int idx = blockIdx.x*256 + threadIdx.x;
    if (idx >= 3*1536*768) return;
    int k = idx % 768, rest = idx / 768;
    int n = rest % 1536, l = rest / 1536;
    int Kl = (l == 0) ? 768 : 512;
    float v = 0.f;
    if (k < Kl)
        v = (l == 0) ? Wih0[(size_t)n*768 + k]
                     : Wih12[(size_t)(l-1)*1536*512 + (size_t)n*512 + k];
    __nv_bfloat16 h = __float2bfloat16(v);
    size_t base = (size_t)l*2*1536*768;
    g_WIS[base + (size_t)n*768 + k] = h;
    g_WIS[base + 1536*768 + (size_t)n*768 + k] = __float2bfloat16(v - __bfloat162float(h));
}

__global__ void k_asplit(const float* __restrict__ A, int K){
    int idx = blockIdx.x*256 + threadIdx.x;
    if (idx >= 2048*K) return;
    float v = A[idx];
    __nv_bfloat16 h = __float2bfloat16(v);
    g_AS[idx] = h;
    g_AS[2048*768 + idx] = __float2bfloat16(v - __bfloat162float(h));
}

__global__ void k_wtrans(const float* __restrict__ Whh0, const float* __restrict__ Whh12){
    int idx = blockIdx.x*256 + threadIdx.x;
    if (idx >= 3*2*768*256) return;
    int k = idx & 255, rest = idx >> 8;
    int row = rest % 768, ld = rest / 768;
    const float* src = (ld < 2) ? &Whh0[(size_t)ld*768*256]
                                : &Whh12[(size_t)(ld-2)*768*256];
    g_WHT[((size_t)ld*256 + k)*768 + row] = src[row*256 + k];
}

// ---------------- xi GEMM on tensor cores (3-term bf16 split) ----------------
#define XA_HI 0
#define XA_LO 9216
#define XW_HI 18432
#define XW_LO 27648
#define SMEM_XI 36864

__global__ void __launch_bounds__(256) k_xi_mma(int K, int layer,
        const float* __restrict__ bih){
    extern __shared__ char smx[];
    const unsigned sbase = smem_u32(smx);
    int tid = threadIdx.x, w = tid >> 5, l = tid & 31;
    int n0 = blockIdx.x*64, m0 = blockIdx.y*64;
    int mw = w >> 1, nw = w & 1;
    const __nv_bfloat16* Ahi = g_AS;
    const __nv_bfloat16* Alo = g_AS + 2048*768;
    const __nv_bfloat16* Whi = g_WIS + (size_t)layer*2*1536*768;
    const __nv_bfloat16* Wlo = Whi + 1536*768;

    float acc[4][4];
    #pragma unroll
    for (int nt=0;nt<4;nt++){acc[nt][0]=0.f;acc[nt][1]=0.f;acc[nt][2]=0.f;acc[nt][3]=0.f;}

    int nkc = K >> 6;
    for (int kc = 0; kc < nkc; kc++){
        __syncthreads();
        #pragma unroll
        for (int it = 0; it < 2; it++){
            int id = tid + it*256;
            int row = id >> 3, c8 = id & 7;
            *(uint4*)(smx + XA_HI + row*144 + c8*16) =
                *(const uint4*)&Ahi[(size_t)(m0+row)*K + kc*64 + c8*8];
            *(uint4*)(smx + XA_LO + row*144 + c8*16) =
                *(const uint4*)&Alo[(size_t)(m0+row)*K + kc*64 + c8*8];
            *(uint4*)(smx + XW_HI + row*144 + c8*16) =
                *(const uint4*)&Whi[(size_t)(n0+row)*768 + kc*64 + c8*8];
            *(uint4*)(smx + XW_LO + row*144 + c8*16) =
                *(const uint4*)&Wlo[(size_t)(n0+row)*768 + kc*64 + c8*8];
        }
        __syncthreads();
        #pragma unroll
        for (int ks = 0; ks < 4; ks++){
            unsigned ah[4], al[4];
            unsigned arow = 16*mw + (l & 15);
            unsigned aoff = (unsigned)(arow*144 + (ks*16 + (l>>4)*8)*2);
            ldsm4(ah, sbase + XA_HI + aoff);
            ldsm4(al, sbase + XA_LO + aoff);
            #pragma unroll
            for (int nt = 0; nt < 4; nt++){
                unsigned grow = nw*32 + nt*8 + (l & 7);
                unsigned boff = (unsigned)(grow*144 + (ks*16 + ((l>>3)&1)*8)*2);
                unsigned bh[2], bl[2];
                ldsm2(bh, sbase + XW_HI + boff);
                ldsm2(bl, sbase + XW_LO + boff);
                mma_bf16(acc[nt], ah, bh);
                mma_bf16(acc[nt], al, bh);
                mma_bf16(acc[nt], ah, bl);
            }
        }
    }
    #pragma unroll
    for (int nt = 0; nt < 4; nt++)
    #pragma unroll
    for (int rh = 0; rh < 2; rh++)
    #pragma unroll
    for (int cc = 0; cc < 2; cc++){
        int r = 16*mw + 8*rh + (l >> 2);
        int col = nw*32 + nt*8 + (l & 3)*2 + cc;
        int m = m0 + r, n = n0 + col;
        int sb = m >> 5, t = m & 31;
        int dir = (n >= G3) ? 1 : 0, g = n - dir*G3;
        g_XI[(size_t)((dir*TT + t)*SBN + sb)*G3 + g] = acc[nt][rh*2 + cc] + bih[n];
    }
}

// ---------------- persistent GRU layer ----------------
#define GRU_HS_F 17408
#define GRU_WS_F 3840
#define GRU_RED_F 3072
#define SMEM_GRU ((GRU_HS_F + GRU_WS_F + GRU_RED_F)*4)

__global__ void __launch_bounds__(256) k_gru_seq(const float* __restrict__ WhT,
        const float* __restrict__ bhh, float* __restrict__ Y){
    extern __shared__ float sm[];
    float* hs  = sm;
    float* ws  = sm + GRU_HS_F;
    float* red = sm + GRU_HS_F + GRU_WS_F;
    int dir = blockIdx.z;
    int tid = threadIdx.x;
    int u_l = tid & 3, sbg = (tid >> 2) & 15, ks = tid >> 6;
    int u0 = blockIdx.x * 4;
    const float* wt = WhT + (size_t)dir*HH*G3;
    #pragma unroll
    for (int i = 0; i < 3; i++){
        int id = tid + i*256;
        int g = id >> 8, k = id & 255;
        float4 v = *(const float4*)&wt[(size_t)k*G3 + g*HH + u0];
        float* d = &ws[(g*256 + k)*5];
        d[0] = v.x; d[1] = v.y; d[2] = v.z; d[3] = v.w;
    }
    int u = u0 + u_l;
    int sb = sbg*4 + ks;
    float br = bhh[dir*G3 + u], bz = bhh[dir*G3 + 256 + u], bn = bhh[dir*G3 + 512 + u];
    int kbase = ks*64;
    int pair = tid & 63;

    for (int t = 0; t < 32; t++){
        int tt = dir ? (31 - t) : t;
        const float* hp = ((t & 1) ? g_HT1 : g_HT0) + dir*HT_DIR;
        float* hn = ((t & 1) ? g_HT0 : g_HT1) + dir*HT_DIR;
        __syncthreads();
        #pragma unroll
        for (int i = 0; i < 16; i++){
            int id = tid + i*256;
            int k = id >> 4, s4 = id & 15;
            float4 v = __ldcg((const float4*)&hp[k*64 + s4*4]);
            *(float4*)&hs[k*68 + s4*4] = v;
        }
        __syncthreads();
        float4 ar = make_float4(0.f,0.f,0.f,0.f), az = ar, an = ar;
        #pragma unroll 8
        for (int kk = 0; kk < 64; kk++){
            int k = kbase + kk;
            float4 h4 = *(const float4*)&hs[k*68 + sbg*4];
            float wr = ws[k*5 + u_l];
            float wz = ws[(256 + k)*5 + u_l];
            float wn = ws[(512 + k)*5 + u_l];
            ar.x += wr*h4.x; ar.y += wr*h4.y; ar.z += wr*h4.z; ar.w += wr*h4.w;
            az.x += wz*h4.x; az.y += wz*h4.y; az.z += wz*h4.z; az.w += wz*h4.w;
            an.x += wn*h4.x; an.y += wn*h4.y; an.z += wn*h4.z; an.w += wn*h4.w;
        }
        float* rp = &red[(ks*64 + pair)*12];
        rp[0] = ar.x; rp[1] = ar.y; rp[2]  = ar.z; rp[3]  = ar.w;
        rp[4] = az.x; rp[5] = az.y; rp[6]  = az.z; rp[7]  = az.w;
        rp[8] = an.x; rp[9] = an.y; rp[10] = an.z; rp[11] = an.w;
        __syncthreads();
        {
            int q = ks;
            float sr = 0.f, sz = 0.f, sn = 0.f;
            #pragma unroll
            for (int kp = 0; kp < 4; kp++){
                const float* r2 = &red[(kp*64 + pair)*12];
                sr += r2[q]; sz += r2[4 + q]; sn += r2[8 + q];
            }
            const float* xi = g_XI + (size_t)((dir*TT + tt)*SBN + sb)*G3 + u;
            float r = 1.f/(1.f + expf(-(xi[0]   + sr + br)));
            float z = 1.f/(1.f + expf(-(xi[256] + sz + bz)));
            float n = tanhf(xi[512] + r*(sn + bn));
            float hv = (1.f - z)*n + z*hs[u*68 + sb];
            __stcg(&hn[u*64 + sb], hv);
            Y[(size_t)(sb*TT + tt)*HH2 + dir*HH + u] = hv;
        }
        __threadfence();
        __syncthreads();
        if (tid == 0){
            atomicAdd(&g_bar[dir], 1u);
            unsigned target = 64u*(unsigned)(t + 1);
            while (*(volatile unsigned*)&g_bar[dir] < target){}
        }
        __syncthreads();
    }
}

// ---------------- mma.sync pairwise highway scores v3 (cp.async pipelined) ----------------
// grid (64,16). M = 64 pairs (8i x 8j); A hi/lo built once from global; epilogue
// reconstructs d = ahi + alo (no Ls/Rs). Double-buffered W via cp.async.
#define ASTR 1040
#define AHI_OFF 0
#define ALO_OFF (64*ASTR)
#define WT0_OFF (2*64*ASTR)
#define WT1_OFF (WT0_OFF + 4*64*144)
#define BIAS_OFF (WT1_OFF + 4*64*144)
#define SRED_OFF (BIAS_OFF + 192*4)
#define SMEM_SC  (SRED_OFF + 128*4)

__global__ void __launch_bounds__(256) k_scores_mma(const float* __restrict__ emb,
        const float* __restrict__ bnp, const float* __restrict__ bgp,
        const float* __restrict__ lwp){
    extern __shared__ char smc[];
    float* bias = (float*)(smc + BIAS_OFF);
    float* sred = (float*)(smc + SRED_OFF);
    const unsigned sbase = smem_u32(smc);
    int tid = threadIdx.x, w = tid >> 5, l = tid & 31;
    int b = blockIdx.y;
    int i0 = (blockIdx.x >> 3)*8, j0 = (blockIdx.x & 7)*8;
    int mw = w >> 1, nw = w & 1;

    // prefetch W tile for it=0 into buffer 0 (overlaps A build)
    {
        #pragma unroll
        for (int it = 0; it < 8; it++){
            int u = tid + it*256;
            int t4 = u >> 9, rem = u & 511, row = rem >> 3, c8 = rem & 7;
            cpasync16(sbase + WT0_OFF + (unsigned)(t4*9216 + row*144 + c8*16),
                      &g_WS[((size_t)t4*512 + row)*512 + c8*8]);
        }
        CP_COMMIT();
    }

    // build |L-R| hi/lo bf16 A-tile from global: pair pb=tid>>2, quarter q=tid&3
    {
        int pb = tid >> 2, q = tid & 3;
        int itok = i0 + (pb >> 3), fi = itok >> 5, ti = itok & 31;
        int jtok = j0 + (pb & 7), fj = (jtok >> 5) + 2, tj = jtok & 31;
        const float* lr = &emb[(size_t)((fi*BSZ + b)*TT + ti)*HH2 + q*128];
        const float* rr = &emb[(size_t)((fj*BSZ + b)*TT + tj)*HH2 + q*128];
        char* ahi = smc + AHI_OFF + pb*ASTR + q*256;
        char* alo = smc + ALO_OFF + pb*ASTR + q*256;
        #pragma unroll
        for (int kk = 0; kk < 128; kk += 4){
            float4 lv = *(const float4*)&lr[kk];
            float4 rv = *(const float4*)&rr[kk];
            float d0 = fabsf(lv.x - rv.x), d1 = fabsf(lv.y - rv.y);
            float d2 = fabsf(lv.z - rv.z), d3 = fabsf(lv.w - rv.w);
            __nv_bfloat16 h0 = __float2bfloat16(d0), h1 = __float2bfloat16(d1);
            __nv_bfloat16 h2 = __float2bfloat16(d2), h3 = __float2bfloat16(d3);
            __nv_bfloat16 e0 = __float2bfloat16(d0 - __bfloat162float(h0));
            __nv_bfloat16 e1 = __float2bfloat16(d1 - __bfloat162float(h1));
            __nv_bfloat16 e2 = __float2bfloat16(d2 - __bfloat162float(h2));
            __nv_bfloat16 e3 = __float2bfloat16(d3 - __bfloat162float(h3));
            unsigned hp0 = ((unsigned)*(unsigned short*)&h0) | (((unsigned)*(unsigned short*)&h1) << 16);
            unsigned hp1 = ((unsigned)*(unsigned short*)&h2) | (((unsigned)*(unsigned short*)&h3) << 16);
            unsigned lp0 = ((unsigned)*(unsigned short*)&e0) | (((unsigned)*(unsigned short*)&e1) << 16);
            unsigned lp1 = ((unsigned)*(unsigned short*)&e2) | (((unsigned)*(unsigned short*)&e3) << 16);
            *(unsigned*)(ahi + kk*2) = hp0; *(unsigned*)(ahi + kk*2 + 4) = hp1;
            *(unsigned*)(alo + kk*2) = lp0; *(unsigned*)(alo + kk*2 + 4) = lp1;
        }
    }

    float sl[2] = {0.f, 0.f};

    for (int nc = 0; nc < 8; nc++){
        __syncthreads();     // protect bias from previous epilogue readers
        float acc[8][4];
        #pragma unroll
        for (int nt=0;nt<8;nt++){acc[nt][0]=0.f;acc[nt][1]=0.f;acc[nt][2]=0.f;acc[nt][3]=0.f;}
        if (tid < 192){
            int t3 = tid >> 6, g = tid & 63;
            const float* src = (t3==0) ? bnp : (t3==1) ? bgp : lwp;
            bias[t3*64 + g] = src[nc*64 + g];
        }
        for (int kc = 0; kc < 8; kc++){
            int it = nc*8 + kc;
            unsigned wbuf = (it & 1) ? WT1_OFF : WT0_OFF;
            CP_WAIT0();
            __syncthreads();
            if (it + 1 < 64){
                int nit = it + 1;
                int nnc = nit >> 3, nkc = nit & 7;
                unsigned obuf = (nit & 1) ? WT1_OFF : WT0_OFF;
                #pragma unroll
                for (int itr = 0; itr < 8; itr++){
                    int u = tid + itr*256;
                    int t4 = u >> 9, rem = u & 511, row = rem >> 3, c8 = rem & 7;
                    cpasync16(sbase + obuf + (unsigned)(t4*9216 + row*144 + c8*16),
                              &g_WS[((size_t)t4*512 + nnc*64 + row)*512 + nkc*64 + c8*8]);
                }
                CP_COMMIT();
            }
            #pragma unroll
            for (int ks = 0; ks < 4; ks++){
                unsigned ah[4], al[4];
                unsigned arow = 16*mw + (l & 15);
                unsigned aoff = AHI_OFF + arow*ASTR + (unsigned)((kc*64 + ks*16 + (l>>4)*8)*2);
                ldsm4(ah, sbase + aoff);
                ldsm4(al, sbase + aoff + (ALO_OFF - AHI_OFF));
                #pragma unroll
                for (int nt = 0; nt < 8; nt++){
                    int thi = (nt < 4) ? 0 : 2;
                    unsigned grow = nw*32 + (nt & 3)*8 + (l & 7);
                    unsigned boff = wbuf + thi*9216 + grow*144 + (unsigned)((ks*16 + ((l>>3)&1)*8)*2);
                    unsigned bh[2], bl[2];
                    ldsm2(bh, sbase + boff);
                    ldsm2(bl, sbase + boff + 9216);
                    mma_bf16(acc[nt], ah, bh);
                    mma_bf16(acc[nt], al, bh);
                    mma_bf16(acc[nt], ah, bl);
                }
            }
        }
        // epilogue: d reconstructed from A hi+lo
        #pragma unroll
        for (int nt = 0; nt < 4; nt++)
        #pragma unroll
        for (int rh = 0; rh < 2; rh++)
        #pragma unroll
        for (int cc = 0; cc < 2; cc++){
            float an = acc[nt][rh*2 + cc];
            float ag = acc[nt+4][rh*2 + cc];
            int kgl = nw*32 + nt*8 + (l & 3)*2 + cc;
            int kg = nc*64 + kgl;
            int r = 16*mw + 8*rh + (l >> 2);
            const unsigned short* dh = (const unsigned short*)(smc + AHI_OFF + r*ASTR + kg*2);
            const unsigned short* dl = (const unsigned short*)(smc + ALO_OFF + r*ASTR + kg*2);
            float d = __bfloat162float(*(const __nv_bfloat16*)dh)
                    + __bfloat162float(*(const __nv_bfloat16*)dl);
            float nn = fmaxf(an + bias[kgl], 0.f);
            float gv = 1.f/(1.f + __expf(-(ag + bias[64 + kgl])));
            sl[rh] += bias[128 + kgl]*(nn*gv + (1.f - gv)*d);
        }
    }
    #pragma unroll
    for (int rh = 0; rh < 2; rh++){
        float s = sl[rh];
        s += __shfl_xor_sync(0xffffffffu, s, 1);
        s += __shfl_xor_sync(0xffffffffu, s, 2);
        if ((l & 3) == 0){
            int r = 16*mw + 8*rh + (l >> 2);
            sred[r*2 + nw] = s;
        }
    }
    __syncthreads();
    if (tid < 64){
        float s = sred[tid*2] + sred[tid*2 + 1];
        int il = tid >> 3, jl = tid & 7;
        g_SP[(b*NTOK + i0 + il)*NTOK + j0 + jl] = s;
    }
}

// masked softmax; transposed=1 -> softmax over i for fixed j
__global__ void k_soft(const float* __restrict__ mask, float* __restrict__ Wout,
                       const float* __restrict__ lintb, int transposed){
    int b = blockIdx.y, r = blockIdx.x, j = threadIdx.x;
    float v = lintb[0] + (transposed ? g_SP[(b*NTOK + j)*NTOK + r]
                                     : g_SP[(b*NTOK + r)*NTOK + j]);
    v += (mask[b*NTOK + j] > 0.5f) ? 0.f : -1e10f;
    __shared__ float red[2];
    float m = v;
    #pragma unroll
    for (int off = 16; off; off >>= 1) m = fmaxf(m, __shfl_xor_sync(0xffffffffu, m, off));
    if ((j & 31) == 0) red[j >> 5] = m;
    __syncthreads();
    m = fmaxf(red[0], red[1]);
    __syncthreads();
    float e = expf(v - m), s = e;
    #pragma unroll
    for (int off = 16; off; off >>= 1) s += __shfl_xor_sync(0xffffffffu, s, off);
    if ((j & 31) == 0) red[j >> 5] = s;
    __syncthreads();
    Wout[(b*NTOK + r)*NTOK + j] = e / (red[0] + red[1]);
}

__global__ void __launch_bounds__(256) k_cmp(const float* __restrict__ emb,
        const float* __restrict__ W, float* __restrict__ OUT, int rside){
    int b = blockIdx.y, r = blockIdx.x, tid = threadIdx.x;
    __shared__ float w[64];
    __shared__ float a[512];
    if (tid < 64) w[tid] = W[(b*NTOK + r)*NTOK + tid];
    int f_own = (r >> 5) + (rside ? 2 : 0), t_own = r & 31;
    for (int k = tid; k < 512; k += 256)
        a[k] = emb[(size_t)((f_own*BSZ + b)*TT + t_own)*HH2 + k];
    __syncthreads();
    int k0 = tid, k1 = tid + 256;
    float acc0 = 0.f, acc1 = 0.f;
    for (int o = 0; o < 64; o++){
        int f_o = (o >> 5) + (rside ? 0 : 2), t_o = o & 31;
        const float* row = emb + (size_t)((f_o*BSZ + b)*TT + t_o)*HH2;
        float wv = w[o];
        acc0 += wv*fabsf(a[k0] - row[k0]);
        acc1 += wv*fabsf(a[k1] - row[k1]);
    }
    OUT[(size_t)(b*NTOK + r)*HH2 + k0] = acc0;
    OUT[(size_t)(b*NTOK + r)*HH2 + k1] = acc1;
}

__global__ void k_attw(const float* __restrict__ emb, const float* __restrict__ attrL,
                       const float* __restrict__ attrR){
    int t = blockIdx.x*4 + (threadIdx.x >> 5), lane = threadIdx.x & 31;
    int sf = blockIdx.y, b = blockIdx.z;
    const float* av = (sf < 2 ? attrL + sf*HH2 : attrR + (sf-2)*HH2);
    const float* row = emb + (size_t)((sf*BSZ + b)*TT + t)*HH2;
    float s = 0.f;
    for (int k = lane; k < HH2; k += 32) s += row[k]*av[k];
    #pragma unroll
    for (int off = 16; off; off >>= 1) s += __shfl_xor_sync(0xffffffffu, s, off);
    if (lane == 0) g_ATTS[(sf*BSZ + b)*TT + t] = s;
}

__global__ void k_attsoft(){
    int sf = blockIdx.x, b = blockIdx.y, t = threadIdx.x;
    float mk = (sf < 2) ? g_MTL[b*NTOK + sf*32 + t] : g_MTR[b*NTOK + (sf-2)*32 + t];
    float v = g_ATTS[(sf*BSZ + b)*TT + t] + (mk > 0.5f ? 0.f : -1e10f);
    float m = v;
    #pragma unroll
    for (int off = 16; off; off >>= 1) m = fmaxf(m, __shfl_xor_sync(0xffffffffu, m, off));
    float e = expf(v - m), s = e;
    #pragma unroll
    for (int off = 16; off; off >>= 1) s += __shfl_xor_sync(0xffffffffu, s, off);
    g_ATTW[(sf*BSZ + b)*TT + t] = e / s;
}

__global__ void __launch_bounds__(256) k_rep(const float* __restrict__ empty_attr){
    int sf = blockIdx.x, b = blockIdx.y, tid = threadIdx.x;
    const float* MT = (sf < 2) ? g_MTL + b*NTOK + sf*32 : g_MTR + b*NTOK + (sf-2)*32;
    float am = 0.f;
    for (int t = 0; t < 32; t++) am = fmaxf(am, MT[t]);
    const float* cmp = (sf < 2) ? g_LC : g_RC;
    int tok0 = (sf & 1)*32;
    for (int k = tid; k < HH2; k += 256){
        float acc = 0.f;
        for (int t = 0; t < 32; t++)
            acc += cmp[(size_t)(b*NTOK + tok0 + t)*HH2 + k]*g_ATTW[(sf*BSZ + b)*TT + t];
        g_CAT[b*DEDIM + sf*HH2 + k] = (am > 0.5f) ? acc : empty_attr[k];
    }
}

__global__ void __launch_bounds__(256) k_hwe(const float* __restrict__ Wn,
        const float* __restrict__ bn, const float* __restrict__ Wg,
        const float* __restrict__ bg){
    int n = blockIdx.x*8 + (threadIdx.x >> 5), lane = threadIdx.x & 31;
    int b = blockIdx.y;
    const float* c = g_CAT + b*DEDIM;
    float sn = 0.f, sg = 0.f;
    for (int k = lane; k < DEDIM; k += 32){
        float cv = c[k];
        sn += Wn[(size_t)n*DEDIM + k]*cv;
        sg += Wg[(size_t)n*DEDIM + k]*cv;
    }
    #pragma unroll
    for (int off = 16; off; off >>= 1){
        sn += __shfl_xor_sync(0xffffffffu, sn, off);
        sg += __shfl_xor_sync(0xffffffffu, sg, off);
    }
    if (lane == 0){
        float nn = fmaxf(sn + bn[n], 0.f);
        float gv = 1.f/(1.f + expf(-(sg + bg[n])));
        g_HW[b*DEDIM + n] = nn*gv + (1.f - gv)*c[n];
    }
}

__global__ void __launch_bounds__(256) k_logits(const float* __restrict__ lW,
        const float* __restrict__ lb, float* __restrict__ out){
    int b = blockIdx.x, tid = threadIdx.x;
    const float* h = g_HW + b*DEDIM;
    float a0 = 0.f, a1 = 0.f;
    for (int k = tid; k < DEDIM; k += 256){
        float hv = h[k];
        a0 += hv*lW[k];
        a1 += hv*lW[DEDIM + k];
    }
    #pragma unroll
    for (int off = 16; off; off >>= 1){
        a0 += __shfl_xor_sync(0xffffffffu, a0, off);
        a1 += __shfl_xor_sync(0xffffffffu, a1, off);
    }
    __shared__ float r0[8], r1[8];
    if ((tid & 31) == 0){ r0[tid >> 5] = a0; r1[tid >> 5] = a1; }
    __syncthreads();
    if (tid == 0){
        float s0 = 0.f, s1 = 0.f;
        for (int w = 0; w < 8; w++){ s0 += r0[w]; s1 += r1[w]; }
        s0 += lb[0]; s1 += lb[1];
        float m = fmaxf(s0, s1);
        float lse = m + logf(expf(s0 - m) + expf(s1 - m));
        out[b*2 + 0] = s0 - lse;
        out[b*2 + 1] = s1 - lse;
    }
}

extern "C" void kernel_launch(void* const* d_in, const int* in_sizes, int n_in,
                              void* d_out, int out_size) {
    const float* lf0 = (const float*)d_in[0];
    const float* lf1 = (const float*)d_in[1];
    const float* rf0 = (const float*)d_in[2];
    const float* rf1 = (const float*)d_in[3];
    const float* Wih0 = (const float*)d_in[4];
    const float* Whh0 = (const float*)d_in[5];
    const float* bih0 = (const float*)d_in[6];
    const float* bhh0 = (const float*)d_in[7];
    const float* Wih12 = (const float*)d_in[8];
    const float* Whh12 = (const float*)d_in[9];
    const float* bih12 = (const float*)d_in[10];
    const float* bhh12 = (const float*)d_in[11];
    const float* hwt_Wn = (const float*)d_in[12];
    const float* hwt_bn = (const float*)d_in[13];
    const float* hwt_Wg = (const float*)d_in[14];
    const float* hwt_bg = (const float*)d_in[15];
    const float* lint_W = (const float*)d_in[16];
    const float* lint_b = (const float*)d_in[17];
    const float* attrL = (const float*)d_in[18];
    const float* attrR = (const float*)d_in[19];
    const float* empty_attr = (const float*)d_in[20];
    const float* hwe_Wn = (const float*)d_in[21];
    const float* hwe_bn = (const float*)d_in[22];
    const float* hwe_Wg = (const float*)d_in[23];
    const float* hwe_bg = (const float*)d_in[24];
    const float* line_W = (const float*)d_in[25];
    const float* line_b = (const float*)d_in[26];
    float* out = (float*)d_out;

    float *X0, *HA, *HB, *WHT, *WL, *WR, *LC, *RC, *MTL, *MTR;
    cudaGetSymbolAddress((void**)&X0, g_X0);
    cudaGetSymbolAddress((void**)&HA, g_HA);
    cudaGetSymbolAddress((void**)&HB, g_HB);
    cudaGetSymbolAddress((void**)&WHT, g_WHT);
    cudaGetSymbolAddress((void**)&WL, g_WL);
    cudaGetSymbolAddress((void**)&WR, g_WR);
    cudaGetSymbolAddress((void**)&LC, g_LC);
    cudaGetSymbolAddress((void**)&RC, g_RC);
    cudaGetSymbolAddress((void**)&MTL, g_MTL);
    cudaGetSymbolAddress((void**)&MTR, g_MTR);

    cudaFuncSetAttribute(k_scores_mma, cudaFuncAttributeMaxDynamicSharedMemorySize, SMEM_SC);
    cudaFuncSetAttribute(k_gru_seq, cudaFuncAttributeMaxDynamicSharedMemorySize, SMEM_GRU);
    cudaFuncSetAttribute(k_xi_mma, cudaFuncAttributeMaxDynamicSharedMemorySize, SMEM_XI);

    k_gather<<<1536, 256>>>(lf0, lf1, rf0, rf1);
    k_masks<<<256, 256>>>(lf0, lf1, rf0, rf1);
    k_wsplit<<<1024, 256>>>(hwt_Wn, hwt_Wg);
    k_wisplit<<<13824, 256>>>(Wih0, Wih12);
    k_wtrans<<<4608, 256>>>(Whh0, Whh12);

    for (int l = 0; l < 3; l++){
        const float* A = (l == 0) ? X0 : ((l == 1) ? HA : HB);
        int K = (l == 0) ? EDIM : HH2;
        const float* bih = (l == 0) ? bih0 : bih12 + (size_t)(l-1)*2*G3;
        const float* bhh = (l == 0) ? bhh0 : bhh12 + (size_t)(l-1)*2*G3;
        const float* WhT = WHT + (size_t)l*2*HH*G3;
        float* Y = (l == 1) ? HB : HA;
        k_asplit<<<(2048*K + 255)/256, 256>>>(A, K);
        k_xi_mma<<<dim3(24, 32), 256, SMEM_XI>>>(K, l, bih);
        k_prep<<<128, 256>>>();
        k_gru_seq<<<dim3(64, 1, 2), 256, SMEM_GRU>>>(WhT, bhh, Y);
    }

    k_scores_mma<<<dim3(64, 16), 256, SMEM_SC>>>(HA, hwt_bn, hwt_bg, lint_W);
    k_soft<<<dim3(64, 16), 64>>>(MTR, WL, lint_b, 0);
    k_soft<<<dim3(64, 16), 64>>>(MTL, WR, lint_b, 1);
    k_cmp<<<dim3(64, 16), 256>>>(HA, WL, LC, 0);
    k_cmp<<<dim3(64, 16), 256>>>(HA, WR, RC, 1);
    k_attw<<<dim3(8, 4, 16), 128>>>(HA, attrL, attrR);
    k_attsoft<<<dim3(4, 16), 32>>>();
    k_rep<<<dim3(4, 16), 256>>>(empty_attr);
    k_hwe<<<dim3(256, 16), 256>>>(hwe_Wn, hwe_bn, hwe_Wg, hwe_bg);
    k_logits<<<16, 256>>>(line_W, line_b, out);
}

// round 16
// speedup vs baseline: 2.5779x; 1.0475x over previous
#include <cuda_runtime.h>
#include <cuda_bf16.h>
#include <math.h>

#define BSZ 16
#define TT 32
#define EDIM 768
#define HH 256
#define HH2 512
#define G3 768
#define SBN 64
#define NTOK 64
#define DEDIM 2048
#define HT_DIR 16384   // 256*64

// ---- scratch (device globals, no allocation) ----
__device__ float g_X0[SBN*TT*EDIM];
__device__ float g_XI[2*TT*SBN*G3];
__device__ float g_HA[SBN*TT*HH2];
__device__ float g_HB[SBN*TT*HH2];
__device__ float g_HT0[2*HT_DIR];
__device__ float g_HT1[2*HT_DIR];
__device__ float g_WHT[3*2*HH*G3];      // [layer][dir][k=256][row=768]
__device__ unsigned g_bar[2];
__device__ float g_SP[BSZ*NTOK*NTOK];
__device__ float g_WL[BSZ*NTOK*NTOK];
__device__ float g_WR[BSZ*NTOK*NTOK];
__device__ float g_LC[BSZ*NTOK*HH2];
__device__ float g_RC[BSZ*NTOK*HH2];
__device__ float g_MTL[BSZ*NTOK];
__device__ float g_MTR[BSZ*NTOK];
__device__ float g_ATTS[4*BSZ*TT];
__device__ float g_ATTW[4*BSZ*TT];
__device__ float g_CAT[BSZ*DEDIM];
__device__ float g_HW[BSZ*DEDIM];
// highway split weights: 0 = Wn-hi, 1 = Wn-lo, 2 = Wg-hi, 3 = Wg-lo; each [512][512] bf16
__device__ __nv_bfloat16 g_WS[4*512*512];
// xi GEMM splits: A (activations) hi then lo, each [2048][K<=768]
__device__ __nv_bfloat16 g_AS[2*2048*768];
// Wih splits: [layer][hi/lo][1536][768 padded] bf16
__device__ __nv_bfloat16 g_WIS[3*2*1536*768];

__device__ __forceinline__ unsigned smem_u32(const void* p){
    unsigned a;
    asm("{ .reg .u64 t; cvta.to.shared.u64 t, %1; cvt.u32.u64 %0, t; }" : "=r"(a) : "l"(p));
    return a;
}
__device__ __forceinline__ void ldsm4(unsigned* r, unsigned addr){
    asm volatile("ldmatrix.sync.aligned.m8n8.x4.shared.b16 {%0,%1,%2,%3}, [%4];"
        : "=r"(r[0]), "=r"(r[1]), "=r"(r[2]), "=r"(r[3]) : "r"(addr));
}
__device__ __forceinline__ void mma_bf16(float* c, const unsigned* a, const unsigned* b){
    asm volatile("mma.sync.aligned.m16n8k16.row.col.f32.bf16.bf16.f32 "
        "{%0,%1,%2,%3}, {%4,%5,%6,%7}, {%8,%9}, {%0,%1,%2,%3};"
        : "+f"(c[0]), "+f"(c[1]), "+f"(c[2]), "+f"(c[3])
        : "r"(a[0]), "r"(a[1]), "r"(a[2]), "r"(a[3]), "r"(b[0]), "r"(b[1]));
}
__device__ __forceinline__ void cpasync16(unsigned dst, const void* src){
    asm volatile("cp.async.cg.shared.global [%0], [%1], 16;" :: "r"(dst), "l"(src));
}
#define CP_COMMIT() asm volatile("cp.async.commit_group;" ::: "memory")
#define CP_WAIT0()  asm volatile("cp.async.wait_group 0;" ::: "memory")

// ---------------- small kernels ----------------
__global__ void k_gather(const float* __restrict__ f0, const float* __restrict__ f1,
                         const float* __restrict__ f2, const float* __restrict__ f3){
    int i = blockIdx.x*256 + threadIdx.x;
    if (i < 2) g_bar[i] = 0u;
    const int per = (BSZ*TT*EDIM)/4;
    int f = i / per, r = i - f*per;
    const float4* src = (f==0)?(const float4*)f0:(f==1)?(const float4*)f1
                      :(f==2)?(const float4*)f2:(const float4*)f3;
    ((float4*)g_X0)[i] = src[r];
}

__global__ void k_masks(const float* __restrict__ f0, const float* __restrict__ f1,
                        const float* __restrict__ f2, const float* __restrict__ f3){
    int warp = (blockIdx.x*256 + threadIdx.x) >> 5;
    int lane = threadIdx.x & 31;
    int f = warp / (BSZ*TT), r = warp % (BSZ*TT);
    const float* src = (f==0)?f0:(f==1)?f1:(f==2)?f2:f3;
    const float* row = src + (size_t)r*EDIM;
    bool nz = false;
    for (int k = lane; k < EDIM; k += 32) nz |= (row[k] != 0.f);
    unsigned any = __ballot_sync(0xffffffffu, nz);
    if (lane == 0){
        int b = r / TT, t = r % TT;
        float v = any ? 1.f : 0.f;
        if (f < 2) g_MTL[b*NTOK + f*32 + t] = v;
        else       g_MTR[b*NTOK + (f-2)*32 + t] = v;
    }
}

__global__ void k_wsplit(const float* __restrict__ Wn, const float* __restrict__ Wg){
    int i = blockIdx.x*256 + threadIdx.x;
    if (i < 512*512){
        float wn = Wn[i], wg = Wg[i];
        __nv_bfloat16 h;
        h = __float2bfloat16(wn);
        g_WS[0*262144 + i] = h;
        g_WS[1*262144 + i] = __float2bfloat16(wn - __bfloat162float(h));
        h = __float2bfloat16(wg);
        g_WS[2*262144 + i] = h;
        g_WS[3*262144 + i] = __float2bfloat16(wg - __bfloat162float(h));
    }
}

__global__ void k_wisplit(const float* __restrict__ Wih0, const float* __restrict__ Wih12){
    int idx = blockIdx.x*256 + threadIdx.x;
    if (idx >= 3*1536*768) return;
    int k = idx % 768, rest = idx / 768;
    int n = rest % 1536, l = rest / 1536;
    int Kl = (l == 0) ? 768 : 512;
    float v = 0.f;
    if (k < Kl)
        v = (l == 0) ? Wih0[(size_t)n*768 + k]
                     : Wih12[(size_t)(l-1)*1536*512 + (size_t)n*512 + k];
    __nv_bfloat16 h = __float2bfloat16(v);
    size_t base = (size_t)l*2*1536*768;
    g_WIS[base + (size_t)n*768 + k] = h;
    g_WIS[base + 1536*768 + (size_t)n*768 + k] = __float2bfloat16(v - __bfloat162float(h));
}

__global__ void k_asplit(const float* __restrict__ A, int K){
    int idx = blockIdx.x*256 + threadIdx.x;
    if (idx >= 2048*K) return;
    float v = A[idx];
    __nv_bfloat16 h = __float2bfloat16(v);
    g_AS[idx] = h;
    g_AS[2048*768 + idx] = __float2bfloat16(v - __bfloat162float(h));
}

__global__ void k_wtrans(const float* __restrict__ Whh0, const float* __restrict__ Whh12){
    int idx = blockIdx.x*256 + threadIdx.x;
    if (idx >= 3*2*768*256) return;
    int k = idx & 255, rest = idx >> 8;
    int row = rest % 768, ld = rest / 768;
    const float* src = (ld < 2) ? &Whh0[(size_t)ld*768*256]
                                : &Whh12[(size_t)(ld-2)*768*256];
    g_WHT[((size_t)ld*256 + k)*768 + row] = src[row*256 + k];
}

// ---------------- xi GEMM on tensor cores (3-term split, cp.async pipelined) ----------------
// stage: 4 tiles x 64 rows x 144B
#define XST 36864
#define SMEM_XI (2*XST)

__global__ void __launch_bounds__(256) k_xi_mma(int K, int layer,
        const float* __restrict__ bih){
    extern __shared__ char smx[];
    const unsigned sbase = smem_u32(smx);
    int tid = threadIdx.x, w = tid >> 5, l = tid & 31;
    int n0 = blockIdx.x*64, m0 = blockIdx.y*64;
    int mw = w >> 1, nw = w & 1;
    const __nv_bfloat16* Ahi = g_AS;
    const __nv_bfloat16* Alo = g_AS + 2048*768;
    const __nv_bfloat16* Whi = g_WIS + (size_t)layer*2*1536*768;
    const __nv_bfloat16* Wlo = Whi + 1536*768;

    float acc[4][4];
    #pragma unroll
    for (int nt=0;nt<4;nt++){acc[nt][0]=0.f;acc[nt][1]=0.f;acc[nt][2]=0.f;acc[nt][3]=0.f;}

    int nkc = K >> 6;
    // prefetch kc=0 into stage 0
    {
        #pragma unroll
        for (int it = 0; it < 8; it++){
            int id = tid + it*256;
            int t4 = id >> 9, rem = id & 511, row = rem >> 3, c8 = rem & 7;
            const void* src = (t4==0) ? (const void*)&Ahi[(size_t)(m0+row)*K + c8*8]
                            : (t4==1) ? (const void*)&Alo[(size_t)(m0+row)*K + c8*8]
                            : (t4==2) ? (const void*)&Whi[(size_t)(n0+row)*768 + c8*8]
                                      : (const void*)&Wlo[(size_t)(n0+row)*768 + c8*8];
            cpasync16(sbase + (unsigned)(t4*9216 + row*144 + c8*16), src);
        }
        CP_COMMIT();
    }
    for (int kc = 0; kc < nkc; kc++){
        unsigned stg = (kc & 1) ? XST : 0;
        CP_WAIT0();
        __syncthreads();
        if (kc + 1 < nkc){
            unsigned ostg = ((kc+1) & 1) ? XST : 0;
            int ko = (kc+1)*64;
            #pragma unroll
            for (int it = 0; it < 8; it++){
                int id = tid + it*256;
                int t4 = id >> 9, rem = id & 511, row = rem >> 3, c8 = rem & 7;
                const void* src = (t4==0) ? (const void*)&Ahi[(size_t)(m0+row)*K + ko + c8*8]
                                : (t4==1) ? (const void*)&Alo[(size_t)(m0+row)*K + ko + c8*8]
                                : (t4==2) ? (const void*)&Whi[(size_t)(n0+row)*768 + ko + c8*8]
                                          : (const void*)&Wlo[(size_t)(n0+row)*768 + ko + c8*8];
                cpasync16(sbase + ostg + (unsigned)(t4*9216 + row*144 + c8*16), src);
            }
            CP_COMMIT();
        }
        #pragma unroll
        for (int ks = 0; ks < 4; ks++){
            unsigned ah[4], al[4];
            unsigned arow = 16*mw + (l & 15);
            unsigned aoff = stg + (unsigned)(arow*144 + (ks*16 + (l>>4)*8)*2);
            ldsm4(ah, sbase + aoff);
            ldsm4(al, sbase + aoff + 9216);
            unsigned q = (unsigned)(l >> 3), nt_off = q >> 1, khalf = q & 1;
            #pragma unroll
            for (int np = 0; np < 2; np++){
                int ntb = np*2;
                unsigned grow = nw*32 + (ntb + nt_off)*8 + (l & 7);
                unsigned boff = stg + 18432 + grow*144 + (unsigned)((ks*16 + khalf*8)*2);
                unsigned bh[4], bl[4];
                ldsm4(bh, sbase + boff);
                ldsm4(bl, sbase + boff + 9216);
                mma_bf16(acc[ntb],   ah, bh);
                mma_bf16(acc[ntb],   al, bh);
                mma_bf16(acc[ntb],   ah, bl);
                mma_bf16(acc[ntb+1], ah, bh+2);
                mma_bf16(acc[ntb+1], al, bh+2);
                mma_bf16(acc[ntb+1], ah, bl+2);
            }
        }
    }
    #pragma unroll
    for (int nt = 0; nt < 4; nt++)
    #pragma unroll
    for (int rh = 0; rh < 2; rh++)
    #pragma unroll
    for (int cc = 0; cc < 2; cc++){
        int r = 16*mw + 8*rh + (l >> 2);
        int col = nw*32 + nt*8 + (l & 3)*2 + cc;
        int m = m0 + r, n = n0 + col;
        int sb = m >> 5, t = m & 31;
        int dir = (n >= G3) ? 1 : 0, g = n - dir*G3;
        g_XI[(size_t)((dir*TT + t)*SBN + sb)*G3 + g] = acc[nt][rh*2 + cc] + bih[n];
    }
}

// ---------------- persistent GRU layer ----------------
#define GRU_HS_F 17408
#define GRU_WS_F 3840
#define GRU_RED_F 3072
#define SMEM_GRU ((GRU_HS_F + GRU_WS_F + GRU_RED_F)*4)

__global__ void __launch_bounds__(256) k_gru_seq(const float* __restrict__ WhT,
        const float* __restrict__ bhh, float* __restrict__ Y, int layer){
    extern __shared__ float sm[];
    float* hs  = sm;
    float* ws  = sm + GRU_HS_F;
    float* red = sm + GRU_HS_F + GRU_WS_F;
    int dir = blockIdx.z;
    int tid = threadIdx.x;
    int u_l = tid & 3, sbg = (tid >> 2) & 15, ks = tid >> 6;
    int u0 = blockIdx.x * 4;
    const float* wt = WhT + (size_t)dir*HH*G3;
    #pragma unroll
    for (int i = 0; i < 3; i++){
        int id = tid + i*256;
        int g = id >> 8, k = id & 255;
        float4 v = *(const float4*)&wt[(size_t)k*G3 + g*HH + u0];
        float* d = &ws[(g*256 + k)*5];
        d[0] = v.x; d[1] = v.y; d[2] = v.z; d[3] = v.w;
    }
    int u = u0 + u_l;
    int sb = sbg*4 + ks;
    float br = bhh[dir*G3 + u], bz = bhh[dir*G3 + 256 + u], bn = bhh[dir*G3 + 512 + u];
    int kbase = ks*64;
    int pair = tid & 63;
    unsigned barbase = (unsigned)(layer*2048);

    for (int t = 0; t < 32; t++){
        int tt = dir ? (31 - t) : t;
        float* hn = ((t & 1) ? g_HT0 : g_HT1) + dir*HT_DIR;
        __syncthreads();
        if (t == 0){
            float4 z4 = make_float4(0.f,0.f,0.f,0.f);
            #pragma unroll
            for (int i = 0; i < 16; i++){
                int id = tid + i*256;
                int k = id >> 4, s4 = id & 15;
                *(float4*)&hs[k*68 + s4*4] = z4;
            }
        } else {
            const float* hp = ((t & 1) ? g_HT1 : g_HT0) + dir*HT_DIR;
            #pragma unroll
            for (int i = 0; i < 16; i++){
                int id = tid + i*256;
                int k = id >> 4, s4 = id & 15;
                float4 v = __ldcg((const float4*)&hp[k*64 + s4*4]);
                *(float4*)&hs[k*68 + s4*4] = v;
            }
        }
        __syncthreads();
        float4 ar = make_float4(0.f,0.f,0.f,0.f), az = ar, an = ar;
        #pragma unroll 8
        for (int kk = 0; kk < 64; kk++){
            int k = kbase + kk;
            float4 h4 = *(const float4*)&hs[k*68 + sbg*4];
            float wr = ws[k*5 + u_l];
            float wz = ws[(256 + k)*5 + u_l];
            float wn = ws[(512 + k)*5 + u_l];
            ar.x += wr*h4.x; ar.y += wr*h4.y; ar.z += wr*h4.z; ar.w += wr*h4.w;
            az.x += wz*h4.x; az.y += wz*h4.y; az.z += wz*h4.z; az.w += wz*h4.w;
            an.x += wn*h4.x; an.y += wn*h4.y; an.z += wn*h4.z; an.w += wn*h4.w;
        }
        float* rp = &red[(ks*64 + pair)*12];
        rp[0] = ar.x; rp[1] = ar.y; rp[2]  = ar.z; rp[3]  = ar.w;
        rp[4] = az.x; rp[5] = az.y; rp[6]  = az.z; rp[7]  = az.w;
        rp[8] = an.x; rp[9] = an.y; rp[10] = an.z; rp[11] = an.w;
        __syncthreads();
        {
            int q = ks;
            float sr = 0.f, sz = 0.f, sn = 0.f;
            #pragma unroll
            for (int kp = 0; kp < 4; kp++){
                const float* r2 = &red[(kp*64 + pair)*12];
                sr += r2[q]; sz += r2[4 + q]; sn += r2[8 + q];
            }
            const float* xi = g_XI + (size_t)((dir*TT + tt)*SBN + sb)*G3 + u;
            float r = 1.f/(1.f + expf(-(xi[0]   + sr + br)));
            float z = 1.f/(1.f + expf(-(xi[256] + sz + bz)));
            float n = tanhf(xi[512] + r*(sn + bn));
            float hv = (1.f - z)*n + z*hs[u*68 + sb];
            __stcg(&hn[u*64 + sb], hv);
            Y[(size_t)(sb*TT + tt)*HH2 + dir*HH + u] = hv;
        }
        __threadfence();
        __syncthreads();
        if (tid == 0){
            atomicAdd(&g_bar[dir], 1u);
            unsigned target = barbase + 64u*(unsigned)(t + 1);
            while (*(volatile unsigned*)&g_bar[dir] < target){}
        }
        __syncthreads();
    }
}

// ---------------- mma.sync pairwise highway scores (cp.async + ldsm4 B) ----------------
#define ASTR 1040
#define AHI_OFF 0
#define ALO_OFF (64*ASTR)
#define WT0_OFF (2*64*ASTR)
#define WT1_OFF (WT0_OFF + 4*64*144)
#define BIAS_OFF (WT1_OFF + 4*64*144)
#define SRED_OFF (BIAS_OFF + 192*4)
#define SMEM_SC  (SRED_OFF + 128*4)

__global__ void __launch_bounds__(256) k_scores_mma(const float* __restrict__ emb,
        const float* __restrict__ bnp, const float* __restrict__ bgp,
        const float* __restrict__ lwp){
    extern __shared__ char smc[];
    float* bias = (float*)(smc + BIAS_OFF);
    float* sred = (float*)(smc + SRED_OFF);
    const unsigned sbase = smem_u32(smc);
    int tid = threadIdx.x, w = tid >> 5, l = tid & 31;
    int b = blockIdx.y;
    int i0 = (blockIdx.x >> 3)*8, j0 = (blockIdx.x & 7)*8;
    int mw = w >> 1, nw = w & 1;

    {
        #pragma unroll
        for (int it = 0; it < 8; it++){
            int u = tid + it*256;
            int t4 = u >> 9, rem = u & 511, row = rem >> 3, c8 = rem & 7;
            cpasync16(sbase + WT0_OFF + (unsigned)(t4*9216 + row*144 + c8*16),
                      &g_WS[((size_t)t4*512 + row)*512 + c8*8]);
        }
        CP_COMMIT();
    }

    {
        int pb = tid >> 2, q = tid & 3;
        int itok = i0 + (pb >> 3), fi = itok >> 5, ti = itok & 31;
        int jtok = j0 + (pb & 7), fj = (jtok >> 5) + 2, tj = jtok & 31;
        const float* lr = &emb[(size_t)((fi*BSZ + b)*TT + ti)*HH2 + q*128];
        const float* rr = &emb[(size_t)((fj*BSZ + b)*TT + tj)*HH2 + q*128];
        char* ahi = smc + AHI_OFF + pb*ASTR + q*256;
        char* alo = smc + ALO_OFF + pb*ASTR + q*256;
        #pragma unroll
        for (int kk = 0; kk < 128; kk += 4){
            float4 lv = *(const float4*)&lr[kk];
            float4 rv = *(const float4*)&rr[kk];
            float d0 = fabsf(lv.x - rv.x), d1 = fabsf(lv.y - rv.y);
            float d2 = fabsf(lv.z - rv.z), d3 = fabsf(lv.w - rv.w);
            __nv_bfloat16 h0 = __float2bfloat16(d0), h1 = __float2bfloat16(d1);
            __nv_bfloat16 h2 = __float2bfloat16(d2), h3 = __float2bfloat16(d3);
            __nv_bfloat16 e0 = __float2bfloat16(d0 - __bfloat162float(h0));
            __nv_bfloat16 e1 = __float2bfloat16(d1 - __bfloat162float(h1));
            __nv_bfloat16 e2 = __float2bfloat16(d2 - __bfloat162float(h2));
            __nv_bfloat16 e3 = __float2bfloat16(d3 - __bfloat162float(h3));
            unsigned hp0 = ((unsigned)*(unsigned short*)&h0) | (((unsigned)*(unsigned short*)&h1) << 16);
            unsigned hp1 = ((unsigned)*(unsigned short*)&h2) | (((unsigned)*(unsigned short*)&h3) << 16);
            unsigned lp0 = ((unsigned)*(unsigned short*)&e0) | (((unsigned)*(unsigned short*)&e1) << 16);
            unsigned lp1 = ((unsigned)*(unsigned short*)&e2) | (((unsigned)*(unsigned short*)&e3) << 16);
            *(unsigned*)(ahi + kk*2) = hp0; *(unsigned*)(ahi + kk*2 + 4) = hp1;
            *(unsigned*)(alo + kk*2) = lp0; *(unsigned*)(alo + kk*2 + 4) = lp1;
        }
    }

    float sl[2] = {0.f, 0.f};

    for (int nc = 0; nc < 8; nc++){
        __syncthreads();
        float acc[8][4];
        #pragma unroll
        for (int nt=0;nt<8;nt++){acc[nt][0]=0.f;acc[nt][1]=0.f;acc[nt][2]=0.f;acc[nt][3]=0.f;}
        if (tid < 192){
            int t3 = tid >> 6, g = tid & 63;
            const float* src = (t3==0) ? bnp : (t3==1) ? bgp : lwp;
            bias[t3*64 + g] = src[nc*64 + g];
        }
        for (int kc = 0; kc < 8; kc++){
            int it = nc*8 + kc;
            unsigned wbuf = (it & 1) ? WT1_OFF : WT0_OFF;
            CP_WAIT0();
            __syncthreads();
            if (it + 1 < 64){
                int nit = it + 1;
                int nnc = nit >> 3, nkc = nit & 7;
                unsigned obuf = (nit & 1) ? WT1_OFF : WT0_OFF;
                #pragma unroll
                for (int itr = 0; itr < 8; itr++){
                    int u = tid + itr*256;
                    int t4 = u >> 9, rem = u & 511, row = rem >> 3, c8 = rem & 7;
                    cpasync16(sbase + obuf + (unsigned)(t4*9216 + row*144 + c8*16),
                              &g_WS[((size_t)t4*512 + nnc*64 + row)*512 + nkc*64 + c8*8]);
                }
                CP_COMMIT();
            }
            #pragma unroll
            for (int ks = 0; ks < 4; ks++){
                unsigned ah[4], al[4];
                unsigned arow = 16*mw + (l & 15);
                unsigned aoff = AHI_OFF + arow*ASTR + (unsigned)((kc*64 + ks*16 + (l>>4)*8)*2);
                ldsm4(ah, sbase + aoff);
                ldsm4(al, sbase + aoff + (ALO_OFF - AHI_OFF));
                unsigned q = (unsigned)(l >> 3), nt_off = q >> 1, khalf = q & 1;
                #pragma unroll
                for (int np = 0; np < 4; np++){
                    int ntb = np*2;
                    int thi = (ntb < 4) ? 0 : 2;
                    unsigned grow = nw*32 + (unsigned)(((ntb + nt_off) & 3)*8) + (l & 7);
                    unsigned boff = wbuf + thi*9216 + grow*144 + (unsigned)((ks*16 + khalf*8)*2);
                    unsigned bh[4], bl[4];
                    ldsm4(bh, sbase + boff);
                    ldsm4(bl, sbase + boff + 9216);
                    mma_bf16(acc[ntb],   ah, bh);
                    mma_bf16(acc[ntb],   al, bh);
                    mma_bf16(acc[ntb],   ah, bl);
                    mma_bf16(acc[ntb+1], ah, bh+2);
                    mma_bf16(acc[ntb+1], al, bh+2);
                    mma_bf16(acc[ntb+1], ah, bl+2);
                }
            }
        }
        #pragma unroll
        for (int nt = 0; nt < 4; nt++)
        #pragma unroll
        for (int rh = 0; rh < 2; rh++)
        #pragma unroll
        for (int cc = 0; cc < 2; cc++){
            float an = acc[nt][rh*2 + cc];
            float ag = acc[nt+4][rh*2 + cc];
            int kgl = nw*32 + nt*8 + (l & 3)*2 + cc;
            int kg = nc*64 + kgl;
            int r = 16*mw + 8*rh + (l >> 2);
            const unsigned short* dh = (const unsigned short*)(smc + AHI_OFF + r*ASTR + kg*2);
            const unsigned short* dl = (const unsigned short*)(smc + ALO_OFF + r*ASTR + kg*2);
            float d = __bfloat162float(*(const __nv_bfloat16*)dh)
                    + __bfloat162float(*(const __nv_bfloat16*)dl);
            float nn = fmaxf(an + bias[kgl], 0.f);
            float gv = 1.f/(1.f + __expf(-(ag + bias[64 + kgl])));
            sl[rh] += bias[128 + kgl]*(nn*gv + (1.f - gv)*d);
        }
    }
    #pragma unroll
    for (int rh = 0; rh < 2; rh++){
        float s = sl[rh];
        s += __shfl_xor_sync(0xffffffffu, s, 1);
        s += __shfl_xor_sync(0xffffffffu, s, 2);
        if ((l & 3) == 0){
            int r = 16*mw + 8*rh + (l >> 2);
            sred[r*2 + nw] = s;
        }
    }
    __syncthreads();
    if (tid < 64){
        float s = sred[tid*2] + sred[tid*2 + 1];
        int il = tid >> 3, jl = tid & 7;
        g_SP[(b*NTOK + i0 + il)*NTOK + j0 + jl] = s;
    }
}

// masked softmax; transposed=1 -> softmax over i for fixed j
__global__ void k_soft(const float* __restrict__ mask, float* __restrict__ Wout,
                       const float* __restrict__ lintb, int transposed){
    int b = blockIdx.y, r = blockIdx.x, j = threadIdx.x;
    float v = lintb[0] + (transposed ? g_SP[(b*NTOK + j)*NTOK + r]
                                     : g_SP[(b*NTOK + r)*NTOK + j]);
    v += (mask[b*NTOK + j] > 0.5f) ? 0.f : -1e10f;
    __shared__ float red[2];
    float m = v;
    #pragma unroll
    for (int off = 16; off; off >>= 1) m = fmaxf(m, __shfl_xor_sync(0xffffffffu, m, off));
    if ((j & 31) == 0) red[j >> 5] = m;
    __syncthreads();
    m = fmaxf(red[0], red[1]);
    __syncthreads();
    float e = expf(v - m), s = e;
    #pragma unroll
    for (int off = 16; off; off >>= 1) s += __shfl_xor_sync(0xffffffffu, s, off);
    if ((j & 31) == 0) red[j >> 5] = s;
    __syncthreads();
    Wout[(b*NTOK + r)*NTOK + j] = e / (red[0] + red[1]);
}

__global__ void __launch_bounds__(256) k_cmp(const float* __restrict__ emb,
        const float* __restrict__ W, float* __restrict__ OUT, int rside){
    int b = blockIdx.y, r = blockIdx.x, tid = threadIdx.x;
    __shared__ float w[64];
    __shared__ float a[512];
    if (tid < 64) w[tid] = W[(b*NTOK + r)*NTOK + tid];
    int f_own = (r >> 5) + (rside ? 2 : 0), t_own = r & 31;
    for (int k = tid; k < 512; k += 256)
        a[k] = emb[(size_t)((f_own*BSZ + b)*TT + t_own)*HH2 + k];
    __syncthreads();
    int k0 = tid, k1 = tid + 256;
    float acc0 = 0.f, acc1 = 0.f;
    for (int o = 0; o < 64; o++){
        int f_o = (o >> 5) + (rside ? 0 : 2), t_o = o & 31;
        const float* row = emb + (size_t)((f_o*BSZ + b)*TT + t_o)*HH2;
        float wv = w[o];
        acc0 += wv*fabsf(a[k0] - row[k0]);
        acc1 += wv*fabsf(a[k1] - row[k1]);
    }
    OUT[(size_t)(b*NTOK + r)*HH2 + k0] = acc0;
    OUT[(size_t)(b*NTOK + r)*HH2 + k1] = acc1;
}

__global__ void k_attw(const float* __restrict__ emb, const float* __restrict__ attrL,
                       const float* __restrict__ attrR){
    int t = blockIdx.x*4 + (threadIdx.x >> 5), lane = threadIdx.x & 31;
    int sf = blockIdx.y, b = blockIdx.z;
    const float* av = (sf < 2 ? attrL + sf*HH2 : attrR + (sf-2)*HH2);
    const float* row = emb + (size_t)((sf*BSZ + b)*TT + t)*HH2;
    float s = 0.f;
    for (int k = lane; k < HH2; k += 32) s += row[k]*av[k];
    #pragma unroll
    for (int off = 16; off; off >>= 1) s += __shfl_xor_sync(0xffffffffu, s, off);
    if (lane == 0) g_ATTS[(sf*BSZ + b)*TT + t] = s;
}

__global__ void k_attsoft(){
    int sf = blockIdx.x, b = blockIdx.y, t = threadIdx.x;
    float mk = (sf < 2) ? g_MTL[b*NTOK + sf*32 + t] : g_MTR[b*NTOK + (sf-2)*32 + t];
    float v = g_ATTS[(sf*BSZ + b)*TT + t] + (mk > 0.5f ? 0.f : -1e10f);
    float m = v;
    #pragma unroll
    for (int off = 16; off; off >>= 1) m = fmaxf(m, __shfl_xor_sync(0xffffffffu, m, off));
    float e = expf(v - m), s = e;
    #pragma unroll
    for (int off = 16; off; off >>= 1) s += __shfl_xor_sync(0xffffffffu, s, off);
    g_ATTW[(sf*BSZ + b)*TT + t] = e / s;
}

__global__ void __launch_bounds__(256) k_rep(const float* __restrict__ empty_attr){
    int sf = blockIdx.x, b = blockIdx.y, tid = threadIdx.x;
    const float* MT = (sf < 2) ? g_MTL + b*NTOK + sf*32 : g_MTR + b*NTOK + (sf-2)*32;
    float am = 0.f;
    for (int t = 0; t < 32; t++) am = fmaxf(am, MT[t]);
    const float* cmp = (sf < 2) ? g_LC : g_RC;
    int tok0 = (sf & 1)*32;
    for (int k = tid; k < HH2; k += 256){
        float acc = 0.f;
        for (int t = 0; t < 32; t++)
            acc += cmp[(size_t)(b*NTOK + tok0 + t)*HH2 + k]*g_ATTW[(sf*BSZ + b)*TT + t];
        g_CAT[b*DEDIM + sf*HH2 + k] = (am > 0.5f) ? acc : empty_attr[k];
    }
}

__global__ void __launch_bounds__(256) k_hwe(const float* __restrict__ Wn,
        const float* __restrict__ bn, const float* __restrict__ Wg,
        const float* __restrict__ bg){
    int n = blockIdx.x*8 + (threadIdx.x >> 5), lane = threadIdx.x & 31;
    int b = blockIdx.y;
    const float* c = g_CAT + b*DEDIM;
    float sn = 0.f, sg = 0.f;
    for (int k = lane; k < DEDIM; k += 32){
        float cv = c[k];
        sn += Wn[(size_t)n*DEDIM + k]*cv;
        sg += Wg[(size_t)n*DEDIM + k]*cv;
    }
    #pragma unroll
    for (int off = 16; off; off >>= 1){
        sn += __shfl_xor_sync(0xffffffffu, sn, off);
        sg += __shfl_xor_sync(0xffffffffu, sg, off);
    }
    if (lane == 0){
        float nn = fmaxf(sn + bn[n], 0.f);
        float gv = 1.f/(1.f + expf(-(sg + bg[n])));
        g_HW[b*DEDIM + n] = nn*gv + (1.f - gv)*c[n];
    }
}

__global__ void __launch_bounds__(256) k_logits(const float* __restrict__ lW,
        const float* __restrict__ lb, float* __restrict__ out){
    int b = blockIdx.x, tid = threadIdx.x;
    const float* h = g_HW + b*DEDIM;
    float a0 = 0.f, a1 = 0.f;
    for (int k = tid; k < DEDIM; k += 256){
        float hv = h[k];
        a0 += hv*lW[k];
        a1 += hv*lW[DEDIM + k];
    }
    #pragma unroll
    for (int off = 16; off; off >>= 1){
        a0 += __shfl_xor_sync(0xffffffffu, a0, off);
        a1 += __shfl_xor_sync(0xffffffffu, a1, off);
    }
    __shared__ float r0[8], r1[8];
    if ((tid & 31) == 0){ r0[tid >> 5] = a0; r1[tid >> 5] = a1; }
    __syncthreads();
    if (tid == 0){
        float s0 = 0.f, s1 = 0.f;
        for (int w = 0; w < 8; w++){ s0 += r0[w]; s1 += r1[w]; }
        s0 += lb[0]; s1 += lb[1];
        float m = fmaxf(s0, s1);
        float lse = m + logf(expf(s0 - m) + expf(s1 - m));
        out[b*2 + 0] = s0 - lse;
        out[b*2 + 1] = s1 - lse;
    }
}

extern "C" void kernel_launch(void* const* d_in, const int* in_sizes, int n_in,
                              void* d_out, int out_size) {
    const float* lf0 = (const float*)d_in[0];
    const float* lf1 = (const float*)d_in[1];
    const float* rf0 = (const float*)d_in[2];
    const float* rf1 = (const float*)d_in[3];
    const float* Wih0 = (const float*)d_in[4];
    const float* Whh0 = (const float*)d_in[5];
    const float* bih0 = (const float*)d_in[6];
    const float* bhh0 = (const float*)d_in[7];
    const float* Wih12 = (const float*)d_in[8];
    const float* Whh12 = (const float*)d_in[9];
    const float* bih12 = (const float*)d_in[10];
    const float* bhh12 = (const float*)d_in[11];
    const float* hwt_Wn = (const float*)d_in[12];
    const float* hwt_bn = (const float*)d_in[13];
    const float* hwt_Wg = (const float*)d_in[14];
    const float* hwt_bg = (const float*)d_in[15];
    const float* lint_W = (const float*)d_in[16];
    const float* lint_b = (const float*)d_in[17];
    const float* attrL = (const float*)d_in[18];
    const float* attrR = (const float*)d_in[19];
    const float* empty_attr = (const float*)d_in[20];
    const float* hwe_Wn = (const float*)d_in[21];
    const float* hwe_bn = (const float*)d_in[22];
    const float* hwe_Wg = (const float*)d_in[23];
    const float* hwe_bg = (const float*)d_in[24];
    const float* line_W = (const float*)d_in[25];
    const float* line_b = (const float*)d_in[26];
    float* out = (float*)d_out;

    float *X0, *HA, *HB, *WHT, *WL, *WR, *LC, *RC, *MTL, *MTR;
    cudaGetSymbolAddress((void**)&X0, g_X0);
    cudaGetSymbolAddress((void**)&HA, g_HA);
    cudaGetSymbolAddress((void**)&HB, g_HB);
    cudaGetSymbolAddress((void**)&WHT, g_WHT);
    cudaGetSymbolAddress((void**)&WL, g_WL);
    cudaGetSymbolAddress((void**)&WR, g_WR);
    cudaGetSymbolAddress((void**)&LC, g_LC);
    cudaGetSymbolAddress((void**)&RC, g_RC);
    cudaGetSymbolAddress((void**)&MTL, g_MTL);
    cudaGetSymbolAddress((void**)&MTR, g_MTR);

    cudaFuncSetAttribute(k_scores_mma, cudaFuncAttributeMaxDynamicSharedMemorySize, SMEM_SC);
    cudaFuncSetAttribute(k_gru_seq, cudaFuncAttributeMaxDynamicSharedMemorySize, SMEM_GRU);
    cudaFuncSetAttribute(k_xi_mma, cudaFuncAttributeMaxDynamicSharedMemorySize, SMEM_XI);

    k_gather<<<1536, 256>>>(lf0, lf1, rf0, rf1);
    k_masks<<<256, 256>>>(lf0, lf1, rf0, rf1);
    k_wsplit<<<1024, 256>>>(hwt_Wn, hwt_Wg);
    k_wisplit<<<13824, 256>>>(Wih0, Wih12);
    k_wtrans<<<4608, 256>>>(Whh0, Whh12);

    for (int l = 0; l < 3; l++){
        const float* A = (l == 0) ? X0 : ((l == 1) ? HA : HB);
        int K = (l == 0) ? EDIM : HH2;
        const float* bih = (l == 0) ? bih0 : bih12 + (size_t)(l-1)*2*G3;
        const float* bhh = (l == 0) ? bhh0 : bhh12 + (size_t)(l-1)*2*G3;
        const float* WhT = WHT + (size_t)l*2*HH*G3;
        float* Y = (l == 1) ? HB : HA;
        k_asplit<<<(2048*K + 255)/256, 256>>>(A, K);
        k_xi_mma<<<dim3(24, 32), 256, SMEM_XI>>>(K, l, bih);
        k_gru_seq<<<dim3(64, 1, 2), 256, SMEM_GRU>>>(WhT, bhh, Y, l);
    }

    k_scores_mma<<<dim3(64, 16), 256, SMEM_SC>>>(HA, hwt_bn, hwt_bg, lint_W);
    k_soft<<<dim3(64, 16), 64>>>(MTR, WL, lint_b, 0);
    k_soft<<<dim3(64, 16), 64>>>(MTL, WR, lint_b, 1);
    k_cmp<<<dim3(64, 16), 256>>>(HA, WL, LC, 0);
    k_cmp<<<dim3(64, 16), 256>>>(HA, WR, RC, 1);
    k_attw<<<dim3(8, 4, 16), 128>>>(HA, attrL, attrR);
    k_attsoft<<<dim3(4, 16), 32>>>();
    k_rep<<<dim3(4, 16), 256>>>(empty_attr);
    k_hwe<<<dim3(256, 16), 256>>>(hwe_Wn, hwe_bn, hwe_Wg, hwe_bg);
    k_logits<<<16, 256>>>(line_W, line_b, out);
}

// round 17
// speedup vs baseline: 2.5854x; 1.0029x over previous
#include <cuda_runtime.h>
#include <cuda_bf16.h>
#include <math.h>

#define BSZ 16
#define TT 32
#define EDIM 768
#define HH 256
#define HH2 512
#define G3 768
#define SBN 64
#define NTOK 64
#define DEDIM 2048
#define HT_DIR 16384   // 256*64

// ---- scratch (device globals, no allocation) ----
__device__ float g_X0[SBN*TT*EDIM];
__device__ float g_XI[2*TT*SBN*G3];
__device__ float g_HA[SBN*TT*HH2];
__device__ float g_HB[SBN*TT*HH2];
__device__ float g_HT0[2*HT_DIR];
__device__ float g_HT1[2*HT_DIR];
__device__ float g_WHT[3*2*HH*G3];      // [layer][dir][k=256][row=768]
__device__ unsigned g_bar[2];
__device__ float g_SP[BSZ*NTOK*NTOK];
__device__ float g_WL[BSZ*NTOK*NTOK];
__device__ float g_WR[BSZ*NTOK*NTOK];
__device__ float g_LC[BSZ*NTOK*HH2];
__device__ float g_RC[BSZ*NTOK*HH2];
__device__ float g_MTL[BSZ*NTOK];
__device__ float g_MTR[BSZ*NTOK];
__device__ float g_ATTW[4*BSZ*TT];
__device__ float g_CAT[BSZ*DEDIM];
__device__ float g_HW[BSZ*DEDIM];
// highway split weights: 0 = Wn-hi, 1 = Wn-lo, 2 = Wg-hi, 3 = Wg-lo; each [512][512] bf16
__device__ __nv_bfloat16 g_WS[4*512*512];
// xi GEMM splits: A (activations) hi then lo, each [2048][K<=768]
__device__ __nv_bfloat16 g_AS[2*2048*768];
// Wih splits: [layer][hi/lo][1536][768 padded] bf16
__device__ __nv_bfloat16 g_WIS[3*2*1536*768];

__device__ __forceinline__ unsigned smem_u32(const void* p){
    unsigned a;
    asm("{ .reg .u64 t; cvta.to.shared.u64 t, %1; cvt.u32.u64 %0, t; }" : "=r"(a) : "l"(p));
    return a;
}
__device__ __forceinline__ void ldsm4(unsigned* r, unsigned addr){
    asm volatile("ldmatrix.sync.aligned.m8n8.x4.shared.b16 {%0,%1,%2,%3}, [%4];"
        : "=r"(r[0]), "=r"(r[1]), "=r"(r[2]), "=r"(r[3]) : "r"(addr));
}
__device__ __forceinline__ void mma_bf16(float* c, const unsigned* a, const unsigned* b){
    asm volatile("mma.sync.aligned.m16n8k16.row.col.f32.bf16.bf16.f32 "
        "{%0,%1,%2,%3}, {%4,%5,%6,%7}, {%8,%9}, {%0,%1,%2,%3};"
        : "+f"(c[0]), "+f"(c[1]), "+f"(c[2]), "+f"(c[3])
        : "r"(a[0]), "r"(a[1]), "r"(a[2]), "r"(a[3]), "r"(b[0]), "r"(b[1]));
}
__device__ __forceinline__ void cpasync16(unsigned dst, const void* src){
    asm volatile("cp.async.cg.shared.global [%0], [%1], 16;" :: "r"(dst), "l"(src));
}
#define CP_COMMIT() asm volatile("cp.async.commit_group;" ::: "memory")
#define CP_WAIT0()  asm volatile("cp.async.wait_group 0;" ::: "memory")

// ---------------- small kernels ----------------
__global__ void k_gather(const float* __restrict__ f0, const float* __restrict__ f1,
                         const float* __restrict__ f2, const float* __restrict__ f3){
    int i = blockIdx.x*256 + threadIdx.x;
    if (i < 2) g_bar[i] = 0u;
    const int per = (BSZ*TT*EDIM)/4;
    int f = i / per, r = i - f*per;
    const float4* src = (f==0)?(const float4*)f0:(f==1)?(const float4*)f1
                      :(f==2)?(const float4*)f2:(const float4*)f3;
    ((float4*)g_X0)[i] = src[r];
}

__global__ void k_masks(const float* __restrict__ f0, const float* __restrict__ f1,
                        const float* __restrict__ f2, const float* __restrict__ f3){
    int warp = (blockIdx.x*256 + threadIdx.x) >> 5;
    int lane = threadIdx.x & 31;
    int f = warp / (BSZ*TT), r = warp % (BSZ*TT);
    const float* src = (f==0)?f0:(f==1)?f1:(f==2)?f2:f3;
    const float* row = src + (size_t)r*EDIM;
    bool nz = false;
    for (int k = lane; k < EDIM; k += 32) nz |= (row[k] != 0.f);
    unsigned any = __ballot_sync(0xffffffffu, nz);
    if (lane == 0){
        int b = r / TT, t = r % TT;
        float v = any ? 1.f : 0.f;
        if (f < 2) g_MTL[b*NTOK + f*32 + t] = v;
        else       g_MTR[b*NTOK + (f-2)*32 + t] = v;
    }
}

__global__ void k_wsplit(const float* __restrict__ Wn, const float* __restrict__ Wg){
    int i = blockIdx.x*256 + threadIdx.x;
    if (i < 512*512){
        float wn = Wn[i], wg = Wg[i];
        __nv_bfloat16 h;
        h = __float2bfloat16(wn);
        g_WS[0*262144 + i] = h;
        g_WS[1*262144 + i] = __float2bfloat16(wn - __bfloat162float(h));
        h = __float2bfloat16(wg);
        g_WS[2*262144 + i] = h;
        g_WS[3*262144 + i] = __float2bfloat16(wg - __bfloat162float(h));
    }
}

__global__ void k_wisplit(const float* __restrict__ Wih0, const float* __restrict__ Wih12){
    int idx = blockIdx.x*256 + threadIdx.x;
    if (idx >= 3*1536*768) return;
    int k = idx % 768, rest = idx / 768;
    int n = rest % 1536, l = rest / 1536;
    int Kl = (l == 0) ? 768 : 512;
    float v = 0.f;
    if (k < Kl)
        v = (l == 0) ? Wih0[(size_t)n*768 + k]
                     : Wih12[(size_t)(l-1)*1536*512 + (size_t)n*512 + k];
    __nv_bfloat16 h = __float2bfloat16(v);
    size_t base = (size_t)l*2*1536*768;
    g_WIS[base + (size_t)n*768 + k] = h;
    g_WIS[base + 1536*768 + (size_t)n*768 + k] = __float2bfloat16(v - __bfloat162float(h));
}

__global__ void k_asplit(const float* __restrict__ A, int K){
    int idx = blockIdx.x*256 + threadIdx.x;
    if (idx >= 2048*K) return;
    float v = A[idx];
    __nv_bfloat16 h = __float2bfloat16(v);
    g_AS[idx] = h;
    g_AS[2048*768 + idx] = __float2bfloat16(v - __bfloat162float(h));
}

__global__ void k_wtrans(const float* __restrict__ Whh0, const float* __restrict__ Whh12){
    int idx = blockIdx.x*256 + threadIdx.x;
    if (idx >= 3*2*768*256) return;
    int k = idx & 255, rest = idx >> 8;
    int row = rest % 768, ld = rest / 768;
    const float* src = (ld < 2) ? &Whh0[(size_t)ld*768*256]
                                : &Whh12[(size_t)(ld-2)*768*256];
    g_WHT[((size_t)ld*256 + k)*768 + row] = src[row*256 + k];
}

// ---------------- xi GEMM on tensor cores (3-term split, cp.async pipelined) ----------------
#define XST 36864
#define SMEM_XI (2*XST)

__global__ void __launch_bounds__(256) k_xi_mma(int K, int layer,
        const float* __restrict__ bih){
    extern __shared__ char smx[];
    const unsigned sbase = smem_u32(smx);
    int tid = threadIdx.x, w = tid >> 5, l = tid & 31;
    int n0 = blockIdx.x*64, m0 = blockIdx.y*64;
    int mw = w >> 1, nw = w & 1;
    const __nv_bfloat16* Ahi = g_AS;
    const __nv_bfloat16* Alo = g_AS + 2048*768;
    const __nv_bfloat16* Whi = g_WIS + (size_t)layer*2*1536*768;
    const __nv_bfloat16* Wlo = Whi + 1536*768;

    float acc[4][4];
    #pragma unroll
    for (int nt=0;nt<4;nt++){acc[nt][0]=0.f;acc[nt][1]=0.f;acc[nt][2]=0.f;acc[nt][3]=0.f;}

    int nkc = K >> 6;
    {
        #pragma unroll
        for (int it = 0; it < 8; it++){
            int id = tid + it*256;
            int t4 = id >> 9, rem = id & 511, row = rem >> 3, c8 = rem & 7;
            const void* src = (t4==0) ? (const void*)&Ahi[(size_t)(m0+row)*K + c8*8]
                            : (t4==1) ? (const void*)&Alo[(size_t)(m0+row)*K + c8*8]
                            : (t4==2) ? (const void*)&Whi[(size_t)(n0+row)*768 + c8*8]
                                      : (const void*)&Wlo[(size_t)(n0+row)*768 + c8*8];
            cpasync16(sbase + (unsigned)(t4*9216 + row*144 + c8*16), src);
        }
        CP_COMMIT();
    }
    for (int kc = 0; kc < nkc; kc++){
        unsigned stg = (kc & 1) ? XST : 0;
        CP_WAIT0();
        __syncthreads();
        if (kc + 1 < nkc){
            unsigned ostg = ((kc+1) & 1) ? XST : 0;
            int ko = (kc+1)*64;
            #pragma unroll
            for (int it = 0; it < 8; it++){
                int id = tid + it*256;
                int t4 = id >> 9, rem = id & 511, row = rem >> 3, c8 = rem & 7;
                const void* src = (t4==0) ? (const void*)&Ahi[(size_t)(m0+row)*K + ko + c8*8]
                                : (t4==1) ? (const void*)&Alo[(size_t)(m0+row)*K + ko + c8*8]
                                : (t4==2) ? (const void*)&Whi[(size_t)(n0+row)*768 + ko + c8*8]
                                          : (const void*)&Wlo[(size_t)(n0+row)*768 + ko + c8*8];
                cpasync16(sbase + ostg + (unsigned)(t4*9216 + row*144 + c8*16), src);
            }
            CP_COMMIT();
        }
        #pragma unroll
        for (int ks = 0; ks < 4; ks++){
            unsigned ah[4], al[4];
            unsigned arow = 16*mw + (l & 15);
            unsigned aoff = stg + (unsigned)(arow*144 + (ks*16 + (l>>4)*8)*2);
            ldsm4(ah, sbase + aoff);
            ldsm4(al, sbase + aoff + 9216);
            unsigned q = (unsigned)(l >> 3), nt_off = q >> 1, khalf = q & 1;
            #pragma unroll
            for (int np = 0; np < 2; np++){
                int ntb = np*2;
                unsigned grow = nw*32 + (ntb + nt_off)*8 + (l & 7);
                unsigned boff = stg + 18432 + grow*144 + (unsigned)((ks*16 + khalf*8)*2);
                unsigned bh[4], bl[4];
                ldsm4(bh, sbase + boff);
                ldsm4(bl, sbase + boff + 9216);
                mma_bf16(acc[ntb],   ah, bh);
                mma_bf16(acc[ntb],   al, bh);
                mma_bf16(acc[ntb],   ah, bl);
                mma_bf16(acc[ntb+1], ah, bh+2);
                mma_bf16(acc[ntb+1], al, bh+2);
                mma_bf16(acc[ntb+1], ah, bl+2);
            }
        }
    }
    #pragma unroll
    for (int nt = 0; nt < 4; nt++)
    #pragma unroll
    for (int rh = 0; rh < 2; rh++)
    #pragma unroll
    for (int cc = 0; cc < 2; cc++){
        int r = 16*mw + 8*rh + (l >> 2);
        int col = nw*32 + nt*8 + (l & 3)*2 + cc;
        int m = m0 + r, n = n0 + col;
        int sb = m >> 5, t = m & 31;
        int dir = (n >= G3) ? 1 : 0, g = n - dir*G3;
        g_XI[(size_t)((dir*TT + t)*SBN + sb)*G3 + g] = acc[nt][rh*2 + cc] + bih[n];
    }
}

// ---------------- persistent GRU layer ----------------
#define GRU_HS_F 17408
#define GRU_WS_F 3840
#define GRU_RED_F 3072
#define SMEM_GRU ((GRU_HS_F + GRU_WS_F + GRU_RED_F)*4)

__global__ void __launch_bounds__(256) k_gru_seq(const float* __restrict__ WhT,
        const float* __restrict__ bhh, float* __restrict__ Y, int layer){
    extern __shared__ float sm[];
    float* hs  = sm;
    float* ws  = sm + GRU_HS_F;
    float* red = sm + GRU_HS_F + GRU_WS_F;
    int dir = blockIdx.z;
    int tid = threadIdx.x;
    int u_l = tid & 3, sbg = (tid >> 2) & 15, ks = tid >> 6;
    int u0 = blockIdx.x * 4;
    const float* wt = WhT + (size_t)dir*HH*G3;
    #pragma unroll
    for (int i = 0; i < 3; i++){
        int id = tid + i*256;
        int g = id >> 8, k = id & 255;
        float4 v = *(const float4*)&wt[(size_t)k*G3 + g*HH + u0];
        float* d = &ws[(g*256 + k)*5];
        d[0] = v.x; d[1] = v.y; d[2] = v.z; d[3] = v.w;
    }
    int u = u0 + u_l;
    int sb = sbg*4 + ks;
    float br = bhh[dir*G3 + u], bz = bhh[dir*G3 + 256 + u], bn = bhh[dir*G3 + 512 + u];
    int kbase = ks*64;
    int pair = tid & 63;
    unsigned barbase = (unsigned)(layer*2048);
    __syncthreads();   // ws ready

    for (int t = 0; t < 32; t++){
        int tt = dir ? (31 - t) : t;
        float* hn = ((t & 1) ? g_HT0 : g_HT1) + dir*HT_DIR;
        // prefetch xi early (independent of h)
        const float* xi = g_XI + (size_t)((dir*TT + tt)*SBN + sb)*G3 + u;
        float x0 = __ldg(&xi[0]), x1 = __ldg(&xi[256]), x2 = __ldg(&xi[512]);
        if (t == 0){
            float4 z4 = make_float4(0.f,0.f,0.f,0.f);
            #pragma unroll
            for (int i = 0; i < 16; i++){
                int id = tid + i*256;
                int k = id >> 4, s4 = id & 15;
                *(float4*)&hs[k*68 + s4*4] = z4;
            }
        } else {
            const float* hp = ((t & 1) ? g_HT1 : g_HT0) + dir*HT_DIR;
            #pragma unroll
            for (int i = 0; i < 16; i++){
                int id = tid + i*256;
                int k = id >> 4, s4 = id & 15;
                float4 v = __ldcg((const float4*)&hp[k*64 + s4*4]);
                *(float4*)&hs[k*68 + s4*4] = v;
            }
        }
        __syncthreads();
        float4 ar = make_float4(0.f,0.f,0.f,0.f), az = ar, an = ar;
        #pragma unroll 8
        for (int kk = 0; kk < 64; kk++){
            int k = kbase + kk;
            float4 h4 = *(const float4*)&hs[k*68 + sbg*4];
            float wr = ws[k*5 + u_l];
            float wz = ws[(256 + k)*5 + u_l];
            float wn = ws[(512 + k)*5 + u_l];
            ar.x += wr*h4.x; ar.y += wr*h4.y; ar.z += wr*h4.z; ar.w += wr*h4.w;
            az.x += wz*h4.x; az.y += wz*h4.y; az.z += wz*h4.z; az.w += wz*h4.w;
            an.x += wn*h4.x; an.y += wn*h4.y; an.z += wn*h4.z; an.w += wn*h4.w;
        }
        float* rp = &red[(ks*64 + pair)*12];
        rp[0] = ar.x; rp[1] = ar.y; rp[2]  = ar.z; rp[3]  = ar.w;
        rp[4] = az.x; rp[5] = az.y; rp[6]  = az.z; rp[7]  = az.w;
        rp[8] = an.x; rp[9] = an.y; rp[10] = an.z; rp[11] = an.w;
        __syncthreads();
        {
            int q = ks;
            float sr = 0.f, sz = 0.f, sn = 0.f;
            #pragma unroll
            for (int kp = 0; kp < 4; kp++){
                const float* r2 = &red[(kp*64 + pair)*12];
                sr += r2[q]; sz += r2[4 + q]; sn += r2[8 + q];
            }
            float r = 1.f/(1.f + expf(-(x0 + sr + br)));
            float z = 1.f/(1.f + expf(-(x1 + sz + bz)));
            float n = tanhf(x2 + r*(sn + bn));
            float hv = (1.f - z)*n + z*hs[u*68 + sb];
            __stcg(&hn[u*64 + sb], hv);
            Y[(size_t)(sb*TT + tt)*HH2 + dir*HH + u] = hv;
        }
        __threadfence();
        __syncthreads();
        if (tid == 0){
            atomicAdd(&g_bar[dir], 1u);
            unsigned target = barbase + 64u*(unsigned)(t + 1);
            while (*(volatile unsigned*)&g_bar[dir] < target){}
        }
        __syncthreads();
    }
}

// ---------------- mma.sync pairwise highway scores (cp.async + ldsm4 B) ----------------
#define ASTR 1040
#define AHI_OFF 0
#define ALO_OFF (64*ASTR)
#define WT0_OFF (2*64*ASTR)
#define WT1_OFF (WT0_OFF + 4*64*144)
#define BIAS_OFF (WT1_OFF + 4*64*144)
#define SRED_OFF (BIAS_OFF + 192*4)
#define SMEM_SC  (SRED_OFF + 128*4)

__global__ void __launch_bounds__(256) k_scores_mma(const float* __restrict__ emb,
        const float* __restrict__ bnp, const float* __restrict__ bgp,
        const float* __restrict__ lwp){
    extern __shared__ char smc[];
    float* bias = (float*)(smc + BIAS_OFF);
    float* sred = (float*)(smc + SRED_OFF);
    const unsigned sbase = smem_u32(smc);
    int tid = threadIdx.x, w = tid >> 5, l = tid & 31;
    int b = blockIdx.y;
    int i0 = (blockIdx.x >> 3)*8, j0 = (blockIdx.x & 7)*8;
    int mw = w >> 1, nw = w & 1;

    {
        #pragma unroll
        for (int it = 0; it < 8; it++){
            int u = tid + it*256;
            int t4 = u >> 9, rem = u & 511, row = rem >> 3, c8 = rem & 7;
            cpasync16(sbase + WT0_OFF + (unsigned)(t4*9216 + row*144 + c8*16),
                      &g_WS[((size_t)t4*512 + row)*512 + c8*8]);
        }
        CP_COMMIT();
    }

    {
        int pb = tid >> 2, q = tid & 3;
        int itok = i0 + (pb >> 3), fi = itok >> 5, ti = itok & 31;
        int jtok = j0 + (pb & 7), fj = (jtok >> 5) + 2, tj = jtok & 31;
        const float* lr = &emb[(size_t)((fi*BSZ + b)*TT + ti)*HH2 + q*128];
        const float* rr = &emb[(size_t)((fj*BSZ + b)*TT + tj)*HH2 + q*128];
        char* ahi = smc + AHI_OFF + pb*ASTR + q*256;
        char* alo = smc + ALO_OFF + pb*ASTR + q*256;
        #pragma unroll
        for (int kk = 0; kk < 128; kk += 4){
            float4 lv = *(const float4*)&lr[kk];
            float4 rv = *(const float4*)&rr[kk];
            float d0 = fabsf(lv.x - rv.x), d1 = fabsf(lv.y - rv.y);
            float d2 = fabsf(lv.z - rv.z), d3 = fabsf(lv.w - rv.w);
            __nv_bfloat16 h0 = __float2bfloat16(d0), h1 = __float2bfloat16(d1);
            __nv_bfloat16 h2 = __float2bfloat16(d2), h3 = __float2bfloat16(d3);
            __nv_bfloat16 e0 = __float2bfloat16(d0 - __bfloat162float(h0));
            __nv_bfloat16 e1 = __float2bfloat16(d1 - __bfloat162float(h1));
            __nv_bfloat16 e2 = __float2bfloat16(d2 - __bfloat162float(h2));
            __nv_bfloat16 e3 = __float2bfloat16(d3 - __bfloat162float(h3));
            unsigned hp0 = ((unsigned)*(unsigned short*)&h0) | (((unsigned)*(unsigned short*)&h1) << 16);
            unsigned hp1 = ((unsigned)*(unsigned short*)&h2) | (((unsigned)*(unsigned short*)&h3) << 16);
            unsigned lp0 = ((unsigned)*(unsigned short*)&e0) | (((unsigned)*(unsigned short*)&e1) << 16);
            unsigned lp1 = ((unsigned)*(unsigned short*)&e2) | (((unsigned)*(unsigned short*)&e3) << 16);
            *(unsigned*)(ahi + kk*2) = hp0; *(unsigned*)(ahi + kk*2 + 4) = hp1;
            *(unsigned*)(alo + kk*2) = lp0; *(unsigned*)(alo + kk*2 + 4) = lp1;
        }
    }

    float sl[2] = {0.f, 0.f};

    for (int nc = 0; nc < 8; nc++){
        __syncthreads();
        float acc[8][4];
        #pragma unroll
        for (int nt=0;nt<8;nt++){acc[nt][0]=0.f;acc[nt][1]=0.f;acc[nt][2]=0.f;acc[nt][3]=0.f;}
        if (tid < 192){
            int t3 = tid >> 6, g = tid & 63;
            const float* src = (t3==0) ? bnp : (t3==1) ? bgp : lwp;
            bias[t3*64 + g] = src[nc*64 + g];
        }
        for (int kc = 0; kc < 8; kc++){
            int it = nc*8 + kc;
            unsigned wbuf = (it & 1) ? WT1_OFF : WT0_OFF;
            CP_WAIT0();
            __syncthreads();
            if (it + 1 < 64){
                int nit = it + 1;
                int nnc = nit >> 3, nkc = nit & 7;
                unsigned obuf = (nit & 1) ? WT1_OFF : WT0_OFF;
                #pragma unroll
                for (int itr = 0; itr < 8; itr++){
                    int u = tid + itr*256;
                    int t4 = u >> 9, rem = u & 511, row = rem >> 3, c8 = rem & 7;
                    cpasync16(sbase + obuf + (unsigned)(t4*9216 + row*144 + c8*16),
                              &g_WS[((size_t)t4*512 + nnc*64 + row)*512 + nkc*64 + c8*8]);
                }
                CP_COMMIT();
            }
            #pragma unroll
            for (int ks = 0; ks < 4; ks++){
                unsigned ah[4], al[4];
                unsigned arow = 16*mw + (l & 15);
                unsigned aoff = AHI_OFF + arow*ASTR + (unsigned)((kc*64 + ks*16 + (l>>4)*8)*2);
                ldsm4(ah, sbase + aoff);
                ldsm4(al, sbase + aoff + (ALO_OFF - AHI_OFF));
                unsigned q = (unsigned)(l >> 3), nt_off = q >> 1, khalf = q & 1;
                #pragma unroll
                for (int np = 0; np < 4; np++){
                    int ntb = np*2;
                    int thi = (ntb < 4) ? 0 : 2;
                    unsigned grow = nw*32 + (unsigned)(((ntb + nt_off) & 3)*8) + (l & 7);
                    unsigned boff = wbuf + thi*9216 + grow*144 + (unsigned)((ks*16 + khalf*8)*2);
                    unsigned bh[4], bl[4];
                    ldsm4(bh, sbase + boff);
                    ldsm4(bl, sbase + boff + 9216);
                    mma_bf16(acc[ntb],   ah, bh);
                    mma_bf16(acc[ntb],   al, bh);
                    mma_bf16(acc[ntb],   ah, bl);
                    mma_bf16(acc[ntb+1], ah, bh+2);
                    mma_bf16(acc[ntb+1], al, bh+2);
                    mma_bf16(acc[ntb+1], ah, bl+2);
                }
            }
        }
        #pragma unroll
        for (int nt = 0; nt < 4; nt++)
        #pragma unroll
        for (int rh = 0; rh < 2; rh++)
        #pragma unroll
        for (int cc = 0; cc < 2; cc++){
            float an = acc[nt][rh*2 + cc];
            float ag = acc[nt+4][rh*2 + cc];
            int kgl = nw*32 + nt*8 + (l & 3)*2 + cc;
            int kg = nc*64 + kgl;
            int r = 16*mw + 8*rh + (l >> 2);
            const unsigned short* dh = (const unsigned short*)(smc + AHI_OFF + r*ASTR + kg*2);
            const unsigned short* dl = (const unsigned short*)(smc + ALO_OFF + r*ASTR + kg*2);
            float d = __bfloat162float(*(const __nv_bfloat16*)dh)
                    + __bfloat162float(*(const __nv_bfloat16*)dl);
            float nn = fmaxf(an + bias[kgl], 0.f);
            float gv = 1.f/(1.f + __expf(-(ag + bias[64 + kgl])));
            sl[rh] += bias[128 + kgl]*(nn*gv + (1.f - gv)*d);
        }
    }
    #pragma unroll
    for (int rh = 0; rh < 2; rh++){
        float s = sl[rh];
        s += __shfl_xor_sync(0xffffffffu, s, 1);
        s += __shfl_xor_sync(0xffffffffu, s, 2);
        if ((l & 3) == 0){
            int r = 16*mw + 8*rh + (l >> 2);
            sred[r*2 + nw] = s;
        }
    }
    __syncthreads();
    if (tid < 64){
        float s = sred[tid*2] + sred[tid*2 + 1];
        int il = tid >> 3, jl = tid & 7;
        g_SP[(b*NTOK + i0 + il)*NTOK + j0 + jl] = s;
    }
}

// masked softmax; z = 0: rows (mask MTR -> WL); z = 1: cols (mask MTL -> WR)
__global__ void k_soft(const float* __restrict__ lintb){
    int b = blockIdx.y, r = blockIdx.x, j = threadIdx.x;
    int tr = blockIdx.z;
    const float* mask = tr ? g_MTL : g_MTR;
    float* Wout = tr ? g_WR : g_WL;
    float v = lintb[0] + (tr ? g_SP[(b*NTOK + j)*NTOK + r]
                             : g_SP[(b*NTOK + r)*NTOK + j]);
    v += (mask[b*NTOK + j] > 0.5f) ? 0.f : -1e10f;
    __shared__ float red[2];
    float m = v;
    #pragma unroll
    for (int off = 16; off; off >>= 1) m = fmaxf(m, __shfl_xor_sync(0xffffffffu, m, off));
    if ((j & 31) == 0) red[j >> 5] = m;
    __syncthreads();
    m = fmaxf(red[0], red[1]);
    __syncthreads();
    float e = expf(v - m), s = e;
    #pragma unroll
    for (int off = 16; off; off >>= 1) s += __shfl_xor_sync(0xffffffffu, s, off);
    if ((j & 31) == 0) red[j >> 5] = s;
    __syncthreads();
    Wout[(b*NTOK + r)*NTOK + j] = e / (red[0] + red[1]);
}

__global__ void __launch_bounds__(256) k_cmp(const float* __restrict__ emb){
    int b = blockIdx.y, r = blockIdx.x, tid = threadIdx.x;
    int rside = blockIdx.z;
    const float* W = rside ? g_WR : g_WL;
    float* OUT = rside ? g_RC : g_LC;
    __shared__ float w[64];
    __shared__ float a[512];
    if (tid < 64) w[tid] = W[(b*NTOK + r)*NTOK + tid];
    int f_own = (r >> 5) + (rside ? 2 : 0), t_own = r & 31;
    for (int k = tid; k < 512; k += 256)
        a[k] = emb[(size_t)((f_own*BSZ + b)*TT + t_own)*HH2 + k];
    __syncthreads();
    int k0 = tid, k1 = tid + 256;
    float acc0 = 0.f, acc1 = 0.f;
    for (int o = 0; o < 64; o++){
        int f_o = (o >> 5) + (rside ? 0 : 2), t_o = o & 31;
        const float* row = emb + (size_t)((f_o*BSZ + b)*TT + t_o)*HH2;
        float wv = w[o];
        acc0 += wv*fabsf(a[k0] - row[k0]);
        acc1 += wv*fabsf(a[k1] - row[k1]);
    }
    OUT[(size_t)(b*NTOK + r)*HH2 + k0] = acc0;
    OUT[(size_t)(b*NTOK + r)*HH2 + k1] = acc1;
}

// fused attribute attention: dot + masked softmax; grid (4 sf, 16 b), 256 threads
__global__ void __launch_bounds__(256) k_att(const float* __restrict__ emb,
        const float* __restrict__ attrL, const float* __restrict__ attrR){
    int sf = blockIdx.x, b = blockIdx.y;
    int tid = threadIdx.x, wrp = tid >> 5, lane = tid & 31;
    __shared__ float sc[32];
    const float* av = (sf < 2 ? attrL + sf*HH2 : attrR + (sf-2)*HH2);
    #pragma unroll
    for (int tb = 0; tb < 4; tb++){
        int t = wrp*4 + tb;
        const float* row = emb + (size_t)((sf*BSZ + b)*TT + t)*HH2;
        float s = 0.f;
        for (int k = lane; k < HH2; k += 32) s += row[k]*av[k];
        #pragma unroll
        for (int off = 16; off; off >>= 1) s += __shfl_xor_sync(0xffffffffu, s, off);
        if (lane == 0) sc[t] = s;
    }
    __syncthreads();
    if (tid < 32){
        int t = tid;
        float mk = (sf < 2) ? g_MTL[b*NTOK + sf*32 + t] : g_MTR[b*NTOK + (sf-2)*32 + t];
        float v = sc[t] + (mk > 0.5f ? 0.f : -1e10f);
        float m = v;
        #pragma unroll
        for (int off = 16; off; off >>= 1) m = fmaxf(m, __shfl_xor_sync(0xffffffffu, m, off));
        float e = expf(v - m), s = e;
        #pragma unroll
        for (int off = 16; off; off >>= 1) s += __shfl_xor_sync(0xffffffffu, s, off);
        g_ATTW[(sf*BSZ + b)*TT + t] = e / s;
    }
}

__global__ void __launch_bounds__(256) k_rep(const float* __restrict__ empty_attr){
    int sf = blockIdx.x, b = blockIdx.y, tid = threadIdx.x;
    const float* MT = (sf < 2) ? g_MTL + b*NTOK + sf*32 : g_MTR + b*NTOK + (sf-2)*32;
    float am = 0.f;
    for (int t = 0; t < 32; t++) am = fmaxf(am, MT[t]);
    const float* cmp = (sf < 2) ? g_LC : g_RC;
    int tok0 = (sf & 1)*32;
    for (int k = tid; k < HH2; k += 256){
        float acc = 0.f;
        for (int t = 0; t < 32; t++)
            acc += cmp[(size_t)(b*NTOK + tok0 + t)*HH2 + k]*g_ATTW[(sf*BSZ + b)*TT + t];
        g_CAT[b*DEDIM + sf*HH2 + k] = (am > 0.5f) ? acc : empty_attr[k];
    }
}

__global__ void __launch_bounds__(256) k_hwe(const float* __restrict__ Wn,
        const float* __restrict__ bn, const float* __restrict__ Wg,
        const float* __restrict__ bg){
    int n = blockIdx.x*8 + (threadIdx.x >> 5), lane = threadIdx.x & 31;
    int b = blockIdx.y;
    const float* c = g_CAT + b*DEDIM;
    float sn = 0.f, sg = 0.f;
    for (int k = lane; k < DEDIM; k += 32){
        float cv = c[k];
        sn += Wn[(size_t)n*DEDIM + k]*cv;
        sg += Wg[(size_t)n*DEDIM + k]*cv;
    }
    #pragma unroll
    for (int off = 16; off; off >>= 1){
        sn += __shfl_xor_sync(0xffffffffu, sn, off);
        sg += __shfl_xor_sync(0xffffffffu, sg, off);
    }
    if (lane == 0){
        float nn = fmaxf(sn + bn[n], 0.f);
        float gv = 1.f/(1.f + expf(-(sg + bg[n])));
        g_HW[b*DEDIM + n] = nn*gv + (1.f - gv)*c[n];
    }
}

__global__ void __launch_bounds__(256) k_logits(const float* __restrict__ lW,
        const float* __restrict__ lb, float* __restrict__ out){
    int b = blockIdx.x, tid = threadIdx.x;
    const float* h = g_HW + b*DEDIM;
    float a0 = 0.f, a1 = 0.f;
    for (int k = tid; k < DEDIM; k += 256){
        float hv = h[k];
        a0 += hv*lW[k];
        a1 += hv*lW[DEDIM + k];
    }
    #pragma unroll
    for (int off = 16; off; off >>= 1){
        a0 += __shfl_xor_sync(0xffffffffu, a0, off);
        a1 += __shfl_xor_sync(0xffffffffu, a1, off);
    }
    __shared__ float r0[8], r1[8];
    if ((tid & 31) == 0){ r0[tid >> 5] = a0; r1[tid >> 5] = a1; }
    __syncthreads();
    if (tid == 0){
        float s0 = 0.f, s1 = 0.f;
        for (int w = 0; w < 8; w++){ s0 += r0[w]; s1 += r1[w]; }
        s0 += lb[0]; s1 += lb[1];
        float m = fmaxf(s0, s1);
        float lse = m + logf(expf(s0 - m) + expf(s1 - m));
        out[b*2 + 0] = s0 - lse;
        out[b*2 + 1] = s1 - lse;
    }
}

extern "C" void kernel_launch(void* const* d_in, const int* in_sizes, int n_in,
                              void* d_out, int out_size) {
    const float* lf0 = (const float*)d_in[0];
    const float* lf1 = (const float*)d_in[1];
    const float* rf0 = (const float*)d_in[2];
    const float* rf1 = (const float*)d_in[3];
    const float* Wih0 = (const float*)d_in[4];
    const float* Whh0 = (const float*)d_in[5];
    const float* bih0 = (const float*)d_in[6];
    const float* bhh0 = (const float*)d_in[7];
    const float* Wih12 = (const float*)d_in[8];
    const float* Whh12 = (const float*)d_in[9];
    const float* bih12 = (const float*)d_in[10];
    const float* bhh12 = (const float*)d_in[11];
    const float* hwt_Wn = (const float*)d_in[12];
    const float* hwt_bn = (const float*)d_in[13];
    const float* hwt_Wg = (const float*)d_in[14];
    const float* hwt_bg = (const float*)d_in[15];
    const float* lint_W = (const float*)d_in[16];
    const float* lint_b = (const float*)d_in[17];
    const float* attrL = (const float*)d_in[18];
    const float* attrR = (const float*)d_in[19];
    const float* empty_attr = (const float*)d_in[20];
    const float* hwe_Wn = (const float*)d_in[21];
    const float* hwe_bn = (const float*)d_in[22];
    const float* hwe_Wg = (const float*)d_in[23];
    const float* hwe_bg = (const float*)d_in[24];
    const float* line_W = (const float*)d_in[25];
    const float* line_b = (const float*)d_in[26];
    float* out = (float*)d_out;

    float *X0, *HA, *HB, *WHT;
    cudaGetSymbolAddress((void**)&X0, g_X0);
    cudaGetSymbolAddress((void**)&HA, g_HA);
    cudaGetSymbolAddress((void**)&HB, g_HB);
    cudaGetSymbolAddress((void**)&WHT, g_WHT);

    cudaFuncSetAttribute(k_scores_mma, cudaFuncAttributeMaxDynamicSharedMemorySize, SMEM_SC);
    cudaFuncSetAttribute(k_gru_seq, cudaFuncAttributeMaxDynamicSharedMemorySize, SMEM_GRU);
    cudaFuncSetAttribute(k_xi_mma, cudaFuncAttributeMaxDynamicSharedMemorySize, SMEM_XI);

    k_gather<<<1536, 256>>>(lf0, lf1, rf0, rf1);
    k_masks<<<256, 256>>>(lf0, lf1, rf0, rf1);
    k_wsplit<<<1024, 256>>>(hwt_Wn, hwt_Wg);
    k_wisplit<<<13824, 256>>>(Wih0, Wih12);
    k_wtrans<<<4608, 256>>>(Whh0, Whh12);

    for (int l = 0; l < 3; l++){
        const float* A = (l == 0) ? X0 : ((l == 1) ? HA : HB);
        int K = (l == 0) ? EDIM : HH2;
        const float* bih = (l == 0) ? bih0 : bih12 + (size_t)(l-1)*2*G3;
        const float* bhh = (l == 0) ? bhh0 : bhh12 + (size_t)(l-1)*2*G3;
        const float* WhT = WHT + (size_t)l*2*HH*G3;
        float* Y = (l == 1) ? HB : HA;
        k_asplit<<<(2048*K + 255)/256, 256>>>(A, K);
        k_xi_mma<<<dim3(24, 32), 256, SMEM_XI>>>(K, l, bih);
        k_gru_seq<<<dim3(64, 1, 2), 256, SMEM_GRU>>>(WhT, bhh, Y, l);
    }

    k_scores_mma<<<dim3(64, 16), 256, SMEM_SC>>>(HA, hwt_bn, hwt_bg, lint_W);
    k_soft<<<dim3(64, 16, 2), 64>>>(lint_b);
    k_cmp<<<dim3(64, 16, 2), 256>>>(HA);
    k_att<<<dim3(4, 16), 256>>>(HA, attrL, attrR);
    k_rep<<<dim3(4, 16), 256>>>(empty_attr);
    k_hwe<<<dim3(256, 16), 256>>>(hwe_Wn, hwe_bn, hwe_Wg, hwe_bg);
    k_logits<<<16, 256>>>(line_W, line_b, out);
}